// round 4
// baseline (speedup 1.0000x reference)
#include <cuda_runtime.h>
#include <cuda_bf16.h>

#define NN 100000
#define NE 1600000
#define FEATS 128
#define HID 64
#define NCLS 40
#define NEG 0.01f
#define NPART ((NN + 1023) / 1024)

// ---------------- scratch (device globals) -----------------------------------
__device__ float g_deg[NN];
__device__ float g_dis[NN];
__device__ float g_t[(size_t)NN * HID];
__device__ float g_t2[(size_t)NN * HID];
__device__ int   g_cnt[NN];
__device__ int   g_fill[NN];
__device__ int   g_rowptr[NN + 1];
__device__ int   g_part[NPART];
__device__ int2  g_csre[NE];      // .x = src, .y = norm bits
__device__ int   g_is64;

// ---------------- edge helpers ------------------------------------------------
__device__ __forceinline__ long long edge_node(const void* ei, long long idx) {
    if (g_is64) return ((const long long*)ei)[idx];
    return (long long)((const int*)ei)[idx];
}

// ---------------- init (+ dtype detection) ------------------------------------
__global__ void init_kernel(const void* ei) {
    int i = blockIdx.x * blockDim.x + threadIdx.x;
    if (i < NN) { g_deg[i] = 1.0f; g_cnt[i] = 0; g_fill[i] = 0; }
    if (blockIdx.x == 0 && threadIdx.x == 0) {
        const int* w = (const int*)ei;
        int zeros = 0;
        for (int j = 1; j < 64; j += 2) zeros += (w[j] == 0);
        g_is64 = (zeros == 32) ? 1 : 0;
    }
}

__global__ void deg_accum_kernel(const void* __restrict__ ei,
                                 const float* __restrict__ ew) {
    int e = blockIdx.x * blockDim.x + threadIdx.x;
    if (e < NE) {
        int d = (int)edge_node(ei, (long long)NE + e);
        atomicAdd(&g_deg[d], ew[e]);
        atomicAdd(&g_cnt[d], 1);
    }
}

// ---------------- scan over g_cnt -> g_rowptr (+ dis fused) -------------------
__global__ void scan1_kernel() {
    __shared__ int sh[256];
    int t = threadIdx.x;
    int nb = blockIdx.x * 1024;
    // fused dis for this block's 1024 nodes
    for (int i = nb + t; i < nb + 1024 && i < NN; i += 256) {
        float d = g_deg[i];
        g_dis[i] = (d > 0.f) ? rsqrtf(d) : 0.f;
    }
    int base = nb + t * 4;
    int s = 0;
#pragma unroll
    for (int j = 0; j < 4; j++) if (base + j < NN) s += g_cnt[base + j];
    sh[t] = s; __syncthreads();
#pragma unroll
    for (int o = 128; o > 0; o >>= 1) {
        if (t < o) sh[t] += sh[t + o];
        __syncthreads();
    }
    if (t == 0) g_part[blockIdx.x] = sh[0];
}

__global__ void scan2_kernel() {
    int run = 0;
    for (int i = 0; i < NPART; i++) { int v = g_part[i]; g_part[i] = run; run += v; }
}

__global__ void scan3_kernel() {
    __shared__ int sh[256];
    int t = threadIdx.x;
    int base = blockIdx.x * 1024 + t * 4;
    int v[4]; int s = 0;
#pragma unroll
    for (int j = 0; j < 4; j++) { v[j] = (base + j < NN) ? g_cnt[base + j] : 0; s += v[j]; }
    sh[t] = s; __syncthreads();
    for (int o = 1; o < 256; o <<= 1) {          // inclusive Hillis-Steele
        int x = (t >= o) ? sh[t - o] : 0;
        __syncthreads();
        sh[t] += x;
        __syncthreads();
    }
    int off = (t == 0) ? 0 : sh[t - 1];
    int b = g_part[blockIdx.x] + off;
    int run = 0;
#pragma unroll
    for (int j = 0; j < 4; j++) {
        if (base + j < NN) g_rowptr[base + j] = b + run;
        run += v[j];
    }
    if (blockIdx.x == 0 && t == 0) g_rowptr[NN] = NE;
}

// ---------------- CSR fill (norm computed inline, packed int2) ----------------
__global__ void fill_kernel(const void* __restrict__ ei,
                            const float* __restrict__ ew) {
    int e = blockIdx.x * blockDim.x + threadIdx.x;
    if (e < NE) {
        int s = (int)edge_node(ei, e);
        int d = (int)edge_node(ei, (long long)NE + e);
        float nrm = g_dis[s] * ew[e] * g_dis[d];
        int pos = g_rowptr[d] + atomicAdd(&g_fill[d], 1);
        g_csre[pos] = make_int2(s, __float_as_int(nrm));
    }
}

// ---------------- fused: x@W1 + b1 -> leaky -> @Wc1 -> g_t --------------------
__global__ void __launch_bounds__(256)
fused_linear(const float* __restrict__ x, const float* __restrict__ W1,
             const float* __restrict__ b1, const float* __restrict__ W2) {
    __shared__ float Ws[64 * HID];    // 16 KB, reused 3x
    __shared__ float Xs[16 * FEATS];  // 8 KB
    __shared__ float Hs[16 * HID];    // 4 KB
    int tid = threadIdx.x;
    long long row0 = (long long)blockIdx.x * 16;
    for (int i = tid; i < 16 * FEATS; i += 256) Xs[i] = x[row0 * FEATS + i];
    for (int i = tid; i < 64 * HID; i += 256) Ws[i] = W1[i];   // k = 0..63
    __syncthreads();

    int col = tid & 63, rg = tid >> 6;
    float acc[4] = {0.f, 0.f, 0.f, 0.f};
#pragma unroll 4
    for (int k = 0; k < 64; k++) {
        float w = Ws[k * HID + col];
#pragma unroll
        for (int j = 0; j < 4; j++) acc[j] += Xs[(rg + 4 * j) * FEATS + k] * w;
    }
    __syncthreads();
    for (int i = tid; i < 64 * HID; i += 256) Ws[i] = W1[64 * HID + i];  // k = 64..127
    __syncthreads();
#pragma unroll 4
    for (int k = 0; k < 64; k++) {
        float w = Ws[k * HID + col];
#pragma unroll
        for (int j = 0; j < 4; j++) acc[j] += Xs[(rg + 4 * j) * FEATS + 64 + k] * w;
    }
    float bb = b1[col];
#pragma unroll
    for (int j = 0; j < 4; j++) {
        float v = acc[j] + bb;
        Hs[(rg + 4 * j) * HID + col] = (v > 0.f) ? v : NEG * v;
    }
    __syncthreads();
    for (int i = tid; i < HID * HID; i += 256) Ws[i] = W2[i];
    __syncthreads();

    float acc2[4] = {0.f, 0.f, 0.f, 0.f};
#pragma unroll 4
    for (int k = 0; k < HID; k++) {
        float w = Ws[k * HID + col];
#pragma unroll
        for (int j = 0; j < 4; j++) acc2[j] += Hs[(rg + 4 * j) * HID + k] * w;
    }
#pragma unroll
    for (int j = 0; j < 4; j++)
        g_t[(row0 + rg + 4 * j) * HID + col] = acc2[j];
}

// ---------------- agg1: segreduce(g_t) -> +b -> leaky -> @Wc2 -> g_t2 --------
__global__ void __launch_bounds__(256)
agg1_kernel(const float* __restrict__ bc, const float* __restrict__ Wc2) {
    __shared__ float WsA[HID * 32];  // even cols (2*lane)
    __shared__ float WsB[HID * 32];  // odd cols (2*lane+1)
    __shared__ float bs[HID];
    int tid = threadIdx.x;
    for (int i = tid; i < HID * 32; i += 256) {
        int k = i >> 5, j = i & 31;
        WsA[i] = Wc2[k * HID + 2 * j];
        WsB[i] = Wc2[k * HID + 2 * j + 1];
    }
    if (tid < HID) bs[tid] = bc[tid];
    __syncthreads();

    int warp = (blockIdx.x * 256 + tid) >> 5;
    int lane = tid & 31;
    if (warp >= NN) return;
    int d = warp;

    float dd = g_dis[d];
    float sc = dd * dd;
    float2 acc = ((const float2*)(g_t + (size_t)d * HID))[lane];
    acc.x *= sc; acc.y *= sc;

    int e = g_rowptr[d], e1 = g_rowptr[d + 1];
    for (; e + 4 <= e1; e += 4) {
        int2 a0 = g_csre[e], a1 = g_csre[e + 1], a2 = g_csre[e + 2], a3 = g_csre[e + 3];
        float2 v0 = ((const float2*)(g_t + (size_t)a0.x * HID))[lane];
        float2 v1 = ((const float2*)(g_t + (size_t)a1.x * HID))[lane];
        float2 v2 = ((const float2*)(g_t + (size_t)a2.x * HID))[lane];
        float2 v3 = ((const float2*)(g_t + (size_t)a3.x * HID))[lane];
        acc.x += __int_as_float(a0.y) * v0.x; acc.y += __int_as_float(a0.y) * v0.y;
        acc.x += __int_as_float(a1.y) * v1.x; acc.y += __int_as_float(a1.y) * v1.y;
        acc.x += __int_as_float(a2.y) * v2.x; acc.y += __int_as_float(a2.y) * v2.y;
        acc.x += __int_as_float(a3.y) * v3.x; acc.y += __int_as_float(a3.y) * v3.y;
    }
    for (; e < e1; e++) {
        int2 a = g_csre[e];
        float2 v = ((const float2*)(g_t + (size_t)a.x * HID))[lane];
        acc.x += __int_as_float(a.y) * v.x;
        acc.y += __int_as_float(a.y) * v.y;
    }

    float x0 = acc.x + bs[2 * lane], x1 = acc.y + bs[2 * lane + 1];
    x0 = (x0 > 0.f) ? x0 : NEG * x0;
    x1 = (x1 > 0.f) ? x1 : NEG * x1;

    // t2 = h @ Wc2  (h col k lives on lane k>>1, comp k&1)
    float t0 = 0.f, t1 = 0.f;
#pragma unroll
    for (int k = 0; k < HID; k++) {
        float hk = __shfl_sync(0xffffffffu, (k & 1) ? x1 : x0, k >> 1);
        t0 += hk * WsA[k * 32 + lane];
        t1 += hk * WsB[k * 32 + lane];
    }
    ((float2*)(g_t2 + (size_t)d * HID))[lane] = make_float2(t0, t1);
}

// ---------------- agg2: segreduce(g_t2) -> +b -> leaky -> head+logsoftmax ----
__global__ void __launch_bounds__(256)
agg2_kernel(const float* __restrict__ bc, const float* __restrict__ Wo,
            const float* __restrict__ bo, float* __restrict__ out) {
    __shared__ float Ws[HID * NCLS];  // 10 KB
    __shared__ float bs[HID];
    __shared__ float bos[NCLS];
    int tid = threadIdx.x;
    for (int i = tid; i < HID * NCLS; i += 256) Ws[i] = Wo[i];
    if (tid < HID) bs[tid] = bc[tid];
    if (tid < NCLS) bos[tid] = bo[tid];
    __syncthreads();

    int warp = (blockIdx.x * 256 + tid) >> 5;
    int lane = tid & 31;
    if (warp >= NN) return;
    int d = warp;

    float dd = g_dis[d];
    float sc = dd * dd;
    float2 acc = ((const float2*)(g_t2 + (size_t)d * HID))[lane];
    acc.x *= sc; acc.y *= sc;

    int e = g_rowptr[d], e1 = g_rowptr[d + 1];
    for (; e + 4 <= e1; e += 4) {
        int2 a0 = g_csre[e], a1 = g_csre[e + 1], a2 = g_csre[e + 2], a3 = g_csre[e + 3];
        float2 v0 = ((const float2*)(g_t2 + (size_t)a0.x * HID))[lane];
        float2 v1 = ((const float2*)(g_t2 + (size_t)a1.x * HID))[lane];
        float2 v2 = ((const float2*)(g_t2 + (size_t)a2.x * HID))[lane];
        float2 v3 = ((const float2*)(g_t2 + (size_t)a3.x * HID))[lane];
        acc.x += __int_as_float(a0.y) * v0.x; acc.y += __int_as_float(a0.y) * v0.y;
        acc.x += __int_as_float(a1.y) * v1.x; acc.y += __int_as_float(a1.y) * v1.y;
        acc.x += __int_as_float(a2.y) * v2.x; acc.y += __int_as_float(a2.y) * v2.y;
        acc.x += __int_as_float(a3.y) * v3.x; acc.y += __int_as_float(a3.y) * v3.y;
    }
    for (; e < e1; e++) {
        int2 a = g_csre[e];
        float2 v = ((const float2*)(g_t2 + (size_t)a.x * HID))[lane];
        acc.x += __int_as_float(a.y) * v.x;
        acc.y += __int_as_float(a.y) * v.y;
    }

    float x0 = acc.x + bs[2 * lane], x1 = acc.y + bs[2 * lane + 1];
    x0 = (x0 > 0.f) ? x0 : NEG * x0;
    x1 = (x1 > 0.f) ? x1 : NEG * x1;

    // logits = h @ Wo + bo; classes: lane (a0), 32+lane for lane<8 (a1)
    float a0 = bos[lane];
    float a1 = (lane < 8) ? bos[32 + lane] : 0.f;
#pragma unroll
    for (int k = 0; k < HID; k++) {
        float hk = __shfl_sync(0xffffffffu, (k & 1) ? x1 : x0, k >> 1);
        a0 += hk * Ws[k * NCLS + lane];
        if (lane < 8) a1 += hk * Ws[k * NCLS + 32 + lane];
    }

    float m = (lane < 8) ? fmaxf(a0, a1) : a0;
#pragma unroll
    for (int o = 16; o > 0; o >>= 1)
        m = fmaxf(m, __shfl_xor_sync(0xffffffffu, m, o));

    float s = expf(a0 - m) + ((lane < 8) ? expf(a1 - m) : 0.f);
#pragma unroll
    for (int o = 16; o > 0; o >>= 1)
        s += __shfl_xor_sync(0xffffffffu, s, o);

    float lse = m + logf(s);
    out[(size_t)d * NCLS + lane] = a0 - lse;
    if (lane < 8) out[(size_t)d * NCLS + 32 + lane] = a1 - lse;
}

// ---------------- launch (kernel launches ONLY) ------------------------------
extern "C" void kernel_launch(void* const* d_in, const int* in_sizes, int n_in,
                              void* d_out, int out_size) {
    const float* x       = (const float*)d_in[0];
    const void*  ei      = d_in[1];
    const float* ew      = (const float*)d_in[2];
    const float* W_first = (const float*)d_in[3];
    const float* b_first = (const float*)d_in[4];
    const float* Wc1     = (const float*)d_in[5];
    const float* bc1     = (const float*)d_in[6];
    const float* Wc2     = (const float*)d_in[7];
    const float* bc2     = (const float*)d_in[8];
    const float* W_out   = (const float*)d_in[9];
    const float* b_out   = (const float*)d_in[10];
    float* out = (float*)d_out;

    const int T = 256;
    init_kernel<<<(NN + T - 1) / T, T>>>(ei);
    deg_accum_kernel<<<(NE + T - 1) / T, T>>>(ei, ew);
    scan1_kernel<<<NPART, 256>>>();
    scan2_kernel<<<1, 1>>>();
    scan3_kernel<<<NPART, 256>>>();
    fill_kernel<<<(NE + T - 1) / T, T>>>(ei, ew);

    fused_linear<<<NN / 16, T>>>(x, W_first, b_first, Wc1);
    agg1_kernel<<<(NN * 32 + T - 1) / T, T>>>(bc1, Wc2);
    agg2_kernel<<<(NN * 32 + T - 1) / T, T>>>(bc2, W_out, b_out, out);
}

// round 5
// speedup vs baseline: 1.0763x; 1.0763x over previous
#include <cuda_runtime.h>
#include <cuda_bf16.h>

#define NN 100000
#define NE 1600000
#define FEATS 128
#define HID 64
#define NCLS 40
#define NEG 0.01f
#define NPART ((NN + 1023) / 1024)

// ---------------- scratch (device globals) -----------------------------------
__device__ float g_deg[NN];
__device__ float g_dis[NN];
__device__ float g_h[(size_t)NN * HID];
__device__ float g_t[(size_t)NN * HID];
__device__ int   g_cnt[NN];
__device__ int   g_fill[NN];
__device__ int   g_rowptr[NN + 1];
__device__ int   g_part[NPART];
__device__ int2  g_csre[NE];      // .x = src, .y = norm bits
__device__ int   g_is64;

// ---------------- edge helpers ------------------------------------------------
__device__ __forceinline__ long long edge_node(const void* ei, long long idx) {
    if (g_is64) return ((const long long*)ei)[idx];
    return (long long)((const int*)ei)[idx];
}

// ---------------- init (+ dtype detection) ------------------------------------
__global__ void init_kernel(const void* ei) {
    int i = blockIdx.x * blockDim.x + threadIdx.x;
    if (i < NN) { g_deg[i] = 1.0f; g_cnt[i] = 0; g_fill[i] = 0; }
    if (blockIdx.x == 0 && threadIdx.x == 0) {
        const int* w = (const int*)ei;
        int zeros = 0;
        for (int j = 1; j < 64; j += 2) zeros += (w[j] == 0);
        g_is64 = (zeros == 32) ? 1 : 0;
    }
}

__global__ void deg_accum_kernel(const void* __restrict__ ei,
                                 const float* __restrict__ ew) {
    int e = blockIdx.x * blockDim.x + threadIdx.x;
    if (e < NE) {
        int d = (int)edge_node(ei, (long long)NE + e);
        atomicAdd(&g_deg[d], ew[e]);
        atomicAdd(&g_cnt[d], 1);
    }
}

// ---------------- GEMM: [NN,128] @ [128,64] + b, leaky -> g_h ----------------
__global__ void __launch_bounds__(256)
gemm128_bias_lrelu(const float* __restrict__ A, const float* __restrict__ W,
                   const float* __restrict__ b) {
    __shared__ float Ws[FEATS * HID];   // 32 KB
    __shared__ float Xs[16 * FEATS];    // 8 KB
    int tid = threadIdx.x;
    for (int i = tid; i < FEATS * HID; i += 256) Ws[i] = W[i];
    long long row0 = (long long)blockIdx.x * 16;
    for (int i = tid; i < 16 * FEATS; i += 256) Xs[i] = A[row0 * FEATS + i];
    __syncthreads();

    int col = tid & 63, rg = tid >> 6;
    float acc[4] = {0.f, 0.f, 0.f, 0.f};
#pragma unroll 4
    for (int k = 0; k < FEATS; k++) {
        float w = Ws[k * HID + col];
#pragma unroll
        for (int j = 0; j < 4; j++) acc[j] += Xs[(rg + 4 * j) * FEATS + k] * w;
    }
    float bb = b[col];
#pragma unroll
    for (int j = 0; j < 4; j++) {
        float v = acc[j] + bb;
        g_h[(row0 + rg + 4 * j) * HID + col] = (v > 0.f) ? v : NEG * v;
    }
}

// ---------------- GEMM: g_h[NN,64] @ W[64,64] -> g_t -------------------------
__global__ void __launch_bounds__(256)
gemm64(const float* __restrict__ W) {
    __shared__ float Ws[HID * HID];   // 16 KB
    __shared__ float Xs[32 * HID];    // 8 KB
    int tid = threadIdx.x;
    for (int i = tid; i < HID * HID; i += 256) Ws[i] = W[i];
    long long row0 = (long long)blockIdx.x * 32;
    for (int i = tid; i < 32 * HID; i += 256) Xs[i] = g_h[row0 * HID + i];
    __syncthreads();

    int col = tid & 63, rg = tid >> 6;
    float acc[8] = {0.f, 0.f, 0.f, 0.f, 0.f, 0.f, 0.f, 0.f};
#pragma unroll 4
    for (int k = 0; k < HID; k++) {
        float w = Ws[k * HID + col];
#pragma unroll
        for (int j = 0; j < 8; j++) acc[j] += Xs[(rg + 4 * j) * HID + k] * w;
    }
#pragma unroll
    for (int j = 0; j < 8; j++)
        g_t[(row0 + rg + 4 * j) * HID + col] = acc[j];
}

// ---------------- scan over g_cnt -> g_rowptr (+ dis fused) -------------------
__global__ void scan1_kernel() {
    __shared__ int sh[256];
    int t = threadIdx.x;
    int nb = blockIdx.x * 1024;
    for (int i = nb + t; i < nb + 1024 && i < NN; i += 256) {
        float d = g_deg[i];
        g_dis[i] = (d > 0.f) ? rsqrtf(d) : 0.f;
    }
    int base = nb + t * 4;
    int s = 0;
#pragma unroll
    for (int j = 0; j < 4; j++) if (base + j < NN) s += g_cnt[base + j];
    sh[t] = s; __syncthreads();
#pragma unroll
    for (int o = 128; o > 0; o >>= 1) {
        if (t < o) sh[t] += sh[t + o];
        __syncthreads();
    }
    if (t == 0) g_part[blockIdx.x] = sh[0];
}

// parallel exclusive scan over NPART partials, single 128-thread block
__global__ void scan2_kernel() {
    __shared__ int sh[128];
    int t = threadIdx.x;
    int v = (t < NPART) ? g_part[t] : 0;
    sh[t] = v; __syncthreads();
    for (int o = 1; o < 128; o <<= 1) {
        int x = (t >= o) ? sh[t - o] : 0;
        __syncthreads();
        sh[t] += x;
        __syncthreads();
    }
    if (t < NPART) g_part[t] = sh[t] - v;   // exclusive
}

__global__ void scan3_kernel() {
    __shared__ int sh[256];
    int t = threadIdx.x;
    int base = blockIdx.x * 1024 + t * 4;
    int v[4]; int s = 0;
#pragma unroll
    for (int j = 0; j < 4; j++) { v[j] = (base + j < NN) ? g_cnt[base + j] : 0; s += v[j]; }
    sh[t] = s; __syncthreads();
    for (int o = 1; o < 256; o <<= 1) {
        int x = (t >= o) ? sh[t - o] : 0;
        __syncthreads();
        sh[t] += x;
        __syncthreads();
    }
    int off = (t == 0) ? 0 : sh[t - 1];
    int b = g_part[blockIdx.x] + off;
    int run = 0;
#pragma unroll
    for (int j = 0; j < 4; j++) {
        if (base + j < NN) g_rowptr[base + j] = b + run;
        run += v[j];
    }
    if (blockIdx.x == 0 && t == 0) g_rowptr[NN] = NE;
}

// ---------------- CSR fill (norm computed inline, packed int2) ----------------
__global__ void fill_kernel(const void* __restrict__ ei,
                            const float* __restrict__ ew) {
    int e = blockIdx.x * blockDim.x + threadIdx.x;
    if (e < NE) {
        int s = (int)edge_node(ei, e);
        int d = (int)edge_node(ei, (long long)NE + e);
        float nrm = g_dis[s] * ew[e] * g_dis[d];
        int pos = g_rowptr[d] + atomicAdd(&g_fill[d], 1);
        g_csre[pos] = make_int2(s, __float_as_int(nrm));
    }
}

// ---------------- agg: warp per dst, fused self+bias+leaky, MLP4 -------------
__global__ void __launch_bounds__(256)
agg_kernel(const float* __restrict__ b) {
    int warp = (blockIdx.x * 256 + threadIdx.x) >> 5;
    int lane = threadIdx.x & 31;
    if (warp >= NN) return;
    int d = warp;

    float dd = g_dis[d];
    float sc = dd * dd;
    float2 acc = ((const float2*)(g_t + (size_t)d * HID))[lane];
    acc.x *= sc; acc.y *= sc;

    int e = g_rowptr[d], e1 = g_rowptr[d + 1];
    for (; e + 4 <= e1; e += 4) {
        int2 a0 = g_csre[e], a1 = g_csre[e + 1], a2 = g_csre[e + 2], a3 = g_csre[e + 3];
        float2 v0 = ((const float2*)(g_t + (size_t)a0.x * HID))[lane];
        float2 v1 = ((const float2*)(g_t + (size_t)a1.x * HID))[lane];
        float2 v2 = ((const float2*)(g_t + (size_t)a2.x * HID))[lane];
        float2 v3 = ((const float2*)(g_t + (size_t)a3.x * HID))[lane];
        acc.x += __int_as_float(a0.y) * v0.x; acc.y += __int_as_float(a0.y) * v0.y;
        acc.x += __int_as_float(a1.y) * v1.x; acc.y += __int_as_float(a1.y) * v1.y;
        acc.x += __int_as_float(a2.y) * v2.x; acc.y += __int_as_float(a2.y) * v2.y;
        acc.x += __int_as_float(a3.y) * v3.x; acc.y += __int_as_float(a3.y) * v3.y;
    }
    for (; e < e1; e++) {
        int2 a = g_csre[e];
        float2 v = ((const float2*)(g_t + (size_t)a.x * HID))[lane];
        acc.x += __int_as_float(a.y) * v.x;
        acc.y += __int_as_float(a.y) * v.y;
    }

    float x0 = acc.x + b[2 * lane], x1 = acc.y + b[2 * lane + 1];
    g_h[(size_t)d * HID + 2 * lane]     = (x0 > 0.f) ? x0 : NEG * x0;
    g_h[(size_t)d * HID + 2 * lane + 1] = (x1 > 0.f) ? x1 : NEG * x1;
}

// ---------------- output: g_h[NN,64]@[64,40] + b, log_softmax ----------------
__global__ void __launch_bounds__(256)
out_kernel(const float* __restrict__ W, const float* __restrict__ b,
           float* __restrict__ out) {
    __shared__ float Ws[HID * NCLS];
    __shared__ float bs[NCLS];
    int tid = threadIdx.x;
    for (int i = tid; i < HID * NCLS; i += 256) Ws[i] = W[i];
    if (tid < NCLS) bs[tid] = b[tid];
    __syncthreads();

    int warp = tid >> 5, lane = tid & 31;
    long long node = (long long)blockIdx.x * 8 + warp;
    if (node >= NN) return;

    float hv0 = g_h[node * HID + lane];
    float hv1 = g_h[node * HID + 32 + lane];

    float a0 = bs[lane];
    float a1 = (lane < 8) ? bs[32 + lane] : 0.f;
#pragma unroll 8
    for (int k = 0; k < HID; k++) {
        float hk = __shfl_sync(0xffffffffu, (k < 32) ? hv0 : hv1, k & 31);
        a0 += hk * Ws[k * NCLS + lane];
        if (lane < 8) a1 += hk * Ws[k * NCLS + 32 + lane];
    }

    float m = (lane < 8) ? fmaxf(a0, a1) : a0;
#pragma unroll
    for (int o = 16; o > 0; o >>= 1)
        m = fmaxf(m, __shfl_xor_sync(0xffffffffu, m, o));

    float s = expf(a0 - m) + ((lane < 8) ? expf(a1 - m) : 0.f);
#pragma unroll
    for (int o = 16; o > 0; o >>= 1)
        s += __shfl_xor_sync(0xffffffffu, s, o);

    float lse = m + logf(s);
    out[node * NCLS + lane] = a0 - lse;
    if (lane < 8) out[node * NCLS + 32 + lane] = a1 - lse;
}

// ---------------- launch (kernel launches ONLY) ------------------------------
extern "C" void kernel_launch(void* const* d_in, const int* in_sizes, int n_in,
                              void* d_out, int out_size) {
    const float* x       = (const float*)d_in[0];
    const void*  ei      = d_in[1];
    const float* ew      = (const float*)d_in[2];
    const float* W_first = (const float*)d_in[3];
    const float* b_first = (const float*)d_in[4];
    const float* Wc1     = (const float*)d_in[5];
    const float* bc1     = (const float*)d_in[6];
    const float* Wc2     = (const float*)d_in[7];
    const float* bc2     = (const float*)d_in[8];
    const float* W_out   = (const float*)d_in[9];
    const float* b_out   = (const float*)d_in[10];
    float* out = (float*)d_out;

    const int T = 256;
    // order chosen so launch #4 (ncu capture slot) = gemm64
    init_kernel<<<(NN + T - 1) / T, T>>>(ei);                 // 1
    deg_accum_kernel<<<(NE + T - 1) / T, T>>>(ei, ew);        // 2
    gemm128_bias_lrelu<<<NN / 16, T>>>(x, W_first, b_first);  // 3 (indep of CSR)
    gemm64<<<NN / 32, T>>>(Wc1);                              // 4 <- profiled
    scan1_kernel<<<NPART, 256>>>();                           // 5
    scan2_kernel<<<1, 128>>>();                               // 6
    scan3_kernel<<<NPART, 256>>>();                           // 7
    fill_kernel<<<(NE + T - 1) / T, T>>>(ei, ew);             // 8

    agg_kernel<<<(NN * 32 + T - 1) / T, T>>>(bc1);            // 9  : g_t -> g_h
    gemm64<<<NN / 32, T>>>(Wc2);                              // 10 : g_h -> g_t
    agg_kernel<<<(NN * 32 + T - 1) / T, T>>>(bc2);            // 11 : g_t -> g_h
    out_kernel<<<(NN + 7) / 8, T>>>(W_out, b_out, out);       // 12
}

// round 7
// speedup vs baseline: 1.1336x; 1.0532x over previous
#include <cuda_runtime.h>
#include <cuda_bf16.h>

#define NN 100000
#define NE 1600000
#define FEATS 128
#define HID 64
#define NCLS 40
#define NEG 0.01f
#define NPART ((NN + 1023) / 1024)

// ---------------- scratch (device globals) -----------------------------------
__device__ float g_deg[NN];
__device__ float g_dis[NN];
__device__ float g_h[(size_t)NN * HID];
__device__ float g_t[(size_t)NN * HID];
__device__ int   g_cnt[NN];
__device__ int   g_fill[NN];
__device__ int   g_rowptr[NN + 1];
__device__ int   g_part[NPART];
__device__ int2  g_csre[NE];      // .x = src, .y = norm bits
__device__ int   g_is64;

// ---------------- edge helpers ------------------------------------------------
__device__ __forceinline__ long long edge_node(const void* ei, long long idx) {
    if (g_is64) return ((const long long*)ei)[idx];
    return (long long)((const int*)ei)[idx];
}

// ---------------- init (+ dtype detection) ------------------------------------
__global__ void init_kernel(const void* ei) {
    int i = blockIdx.x * blockDim.x + threadIdx.x;
    if (i < NN) { g_deg[i] = 1.0f; g_cnt[i] = 0; g_fill[i] = 0; }
    if (blockIdx.x == 0 && threadIdx.x == 0) {
        const int* w = (const int*)ei;
        int zeros = 0;
        for (int j = 1; j < 64; j += 2) zeros += (w[j] == 0);
        g_is64 = (zeros == 32) ? 1 : 0;
    }
}

__global__ void deg_accum_kernel(const void* __restrict__ ei,
                                 const float* __restrict__ ew) {
    int e = blockIdx.x * blockDim.x + threadIdx.x;
    if (e < NE) {
        int d = (int)edge_node(ei, (long long)NE + e);
        atomicAdd(&g_deg[d], ew[e]);
        atomicAdd(&g_cnt[d], 1);
    }
}

// ---------------- GEMM: x[NN,128] @ W[128,64] + b, leaky -> g_h --------------
// register-tiled: 2 rows x 4 cols per thread; 3 LDS per 8 FMA
__global__ void __launch_bounds__(256)
gemm128_bias_lrelu(const float* __restrict__ x, const float* __restrict__ W,
                   const float* __restrict__ b) {
    __shared__ float Ws[64 * HID];          // 16 KB, half of W per phase
    __shared__ float Xs[32][FEATS + 1];     // 16.5 KB padded
    int tid = threadIdx.x;
    long long row0 = (long long)blockIdx.x * 32;

    // load X tile (32 x 128) via float4
    for (int i = tid; i < 32 * (FEATS / 4); i += 256) {
        int r = i >> 5, c4 = i & 31;
        float4 v = ((const float4*)x)[(row0 + r) * (FEATS / 4) + c4];
        Xs[r][c4 * 4 + 0] = v.x; Xs[r][c4 * 4 + 1] = v.y;
        Xs[r][c4 * 4 + 2] = v.z; Xs[r][c4 * 4 + 3] = v.w;
    }
    for (int i = tid; i < 64 * HID; i += 256) Ws[i] = W[i];   // k = 0..63
    __syncthreads();

    int cg = tid & 15;            // 16 col-groups of 4
    int rp = tid >> 4;            // 16 row-pairs
    int r0 = rp * 2, r1 = r0 + 1;
    float4 acc0 = {0.f,0.f,0.f,0.f}, acc1 = {0.f,0.f,0.f,0.f};

#pragma unroll 4
    for (int k = 0; k < 64; k++) {
        float4 w = *(const float4*)&Ws[k * HID + cg * 4];
        float xa = Xs[r0][k], xb = Xs[r1][k];
        acc0.x += xa * w.x; acc0.y += xa * w.y; acc0.z += xa * w.z; acc0.w += xa * w.w;
        acc1.x += xb * w.x; acc1.y += xb * w.y; acc1.z += xb * w.z; acc1.w += xb * w.w;
    }
    __syncthreads();
    for (int i = tid; i < 64 * HID; i += 256) Ws[i] = W[64 * HID + i];  // k = 64..127
    __syncthreads();
#pragma unroll 4
    for (int k = 0; k < 64; k++) {
        float4 w = *(const float4*)&Ws[k * HID + cg * 4];
        float xa = Xs[r0][64 + k], xb = Xs[r1][64 + k];
        acc0.x += xa * w.x; acc0.y += xa * w.y; acc0.z += xa * w.z; acc0.w += xa * w.w;
        acc1.x += xb * w.x; acc1.y += xb * w.y; acc1.z += xb * w.z; acc1.w += xb * w.w;
    }

    float4 bb = *(const float4*)&b[cg * 4];
    float4 o0, o1;
    o0.x = acc0.x + bb.x; o0.y = acc0.y + bb.y; o0.z = acc0.z + bb.z; o0.w = acc0.w + bb.w;
    o1.x = acc1.x + bb.x; o1.y = acc1.y + bb.y; o1.z = acc1.z + bb.z; o1.w = acc1.w + bb.w;
    o0.x = (o0.x > 0.f) ? o0.x : NEG * o0.x;  o0.y = (o0.y > 0.f) ? o0.y : NEG * o0.y;
    o0.z = (o0.z > 0.f) ? o0.z : NEG * o0.z;  o0.w = (o0.w > 0.f) ? o0.w : NEG * o0.w;
    o1.x = (o1.x > 0.f) ? o1.x : NEG * o1.x;  o1.y = (o1.y > 0.f) ? o1.y : NEG * o1.y;
    o1.z = (o1.z > 0.f) ? o1.z : NEG * o1.z;  o1.w = (o1.w > 0.f) ? o1.w : NEG * o1.w;
    ((float4*)g_h)[(row0 + r0) * (HID / 4) + cg] = o0;
    ((float4*)g_h)[(row0 + r1) * (HID / 4) + cg] = o1;
}

// ---------------- GEMM: g_h[NN,64] @ W[64,64] -> g_t -------------------------
// register-tiled: 2 rows x 4 cols per thread; 3 LDS per 8 FMA
__global__ void __launch_bounds__(256)
gemm64(const float* __restrict__ W) {
    __shared__ float Ws[HID * HID];      // 16 KB
    __shared__ float Xs[32][HID + 1];    // 8.3 KB padded
    int tid = threadIdx.x;
    long long row0 = (long long)blockIdx.x * 32;

    for (int i = tid; i < HID * HID; i += 256) Ws[i] = W[i];
    for (int i = tid; i < 32 * (HID / 4); i += 256) {
        int r = i >> 4, c4 = i & 15;
        float4 v = ((const float4*)g_h)[(row0 + r) * (HID / 4) + c4];
        Xs[r][c4 * 4 + 0] = v.x; Xs[r][c4 * 4 + 1] = v.y;
        Xs[r][c4 * 4 + 2] = v.z; Xs[r][c4 * 4 + 3] = v.w;
    }
    __syncthreads();

    int cg = tid & 15;
    int rp = tid >> 4;
    int r0 = rp * 2, r1 = r0 + 1;
    float4 acc0 = {0.f,0.f,0.f,0.f}, acc1 = {0.f,0.f,0.f,0.f};

#pragma unroll 4
    for (int k = 0; k < HID; k++) {
        float4 w = *(const float4*)&Ws[k * HID + cg * 4];
        float xa = Xs[r0][k], xb = Xs[r1][k];
        acc0.x += xa * w.x; acc0.y += xa * w.y; acc0.z += xa * w.z; acc0.w += xa * w.w;
        acc1.x += xb * w.x; acc1.y += xb * w.y; acc1.z += xb * w.z; acc1.w += xb * w.w;
    }
    ((float4*)g_t)[(row0 + r0) * (HID / 4) + cg] = acc0;
    ((float4*)g_t)[(row0 + r1) * (HID / 4) + cg] = acc1;
}

// ---------------- scan over g_cnt -> g_rowptr (+ dis fused) -------------------
__global__ void scan1_kernel() {
    __shared__ int sh[256];
    int t = threadIdx.x;
    int nb = blockIdx.x * 1024;
    for (int i = nb + t; i < nb + 1024 && i < NN; i += 256) {
        float d = g_deg[i];
        g_dis[i] = (d > 0.f) ? rsqrtf(d) : 0.f;
    }
    int base = nb + t * 4;
    int s = 0;
#pragma unroll
    for (int j = 0; j < 4; j++) if (base + j < NN) s += g_cnt[base + j];
    sh[t] = s; __syncthreads();
#pragma unroll
    for (int o = 128; o > 0; o >>= 1) {
        if (t < o) sh[t] += sh[t + o];
        __syncthreads();
    }
    if (t == 0) g_part[blockIdx.x] = sh[0];
}

__global__ void scan2_kernel() {
    __shared__ int sh[128];
    int t = threadIdx.x;
    int v = (t < NPART) ? g_part[t] : 0;
    sh[t] = v; __syncthreads();
    for (int o = 1; o < 128; o <<= 1) {
        int x = (t >= o) ? sh[t - o] : 0;
        __syncthreads();
        sh[t] += x;
        __syncthreads();
    }
    if (t < NPART) g_part[t] = sh[t] - v;   // exclusive
}

__global__ void scan3_kernel() {
    __shared__ int sh[256];
    int t = threadIdx.x;
    int base = blockIdx.x * 1024 + t * 4;
    int v[4]; int s = 0;
#pragma unroll
    for (int j = 0; j < 4; j++) { v[j] = (base + j < NN) ? g_cnt[base + j] : 0; s += v[j]; }
    sh[t] = s; __syncthreads();
    for (int o = 1; o < 256; o <<= 1) {
        int x = (t >= o) ? sh[t - o] : 0;
        __syncthreads();
        sh[t] += x;
        __syncthreads();
    }
    int off = (t == 0) ? 0 : sh[t - 1];
    int b = g_part[blockIdx.x] + off;
    int run = 0;
#pragma unroll
    for (int j = 0; j < 4; j++) {
        if (base + j < NN) g_rowptr[base + j] = b + run;
        run += v[j];
    }
    if (blockIdx.x == 0 && t == 0) g_rowptr[NN] = NE;
}

// ---------------- CSR fill (norm computed inline, packed int2) ----------------
__global__ void fill_kernel(const void* __restrict__ ei,
                            const float* __restrict__ ew) {
    int e = blockIdx.x * blockDim.x + threadIdx.x;
    if (e < NE) {
        int s = (int)edge_node(ei, e);
        int d = (int)edge_node(ei, (long long)NE + e);
        float nrm = g_dis[s] * ew[e] * g_dis[d];
        int pos = g_rowptr[d] + atomicAdd(&g_fill[d], 1);
        g_csre[pos] = make_int2(s, __float_as_int(nrm));
    }
}

// ---------------- agg: warp per dst, fused self+bias+leaky, MLP4 -------------
__global__ void __launch_bounds__(256)
agg_kernel(const float* __restrict__ b) {
    int warp = (blockIdx.x * 256 + threadIdx.x) >> 5;
    int lane = threadIdx.x & 31;
    if (warp >= NN) return;
    int d = warp;

    float dd = g_dis[d];
    float sc = dd * dd;
    float2 acc = ((const float2*)(g_t + (size_t)d * HID))[lane];
    acc.x *= sc; acc.y *= sc;

    int e = g_rowptr[d], e1 = g_rowptr[d + 1];
    for (; e + 4 <= e1; e += 4) {
        int2 a0 = g_csre[e], a1 = g_csre[e + 1], a2 = g_csre[e + 2], a3 = g_csre[e + 3];
        float2 v0 = ((const float2*)(g_t + (size_t)a0.x * HID))[lane];
        float2 v1 = ((const float2*)(g_t + (size_t)a1.x * HID))[lane];
        float2 v2 = ((const float2*)(g_t + (size_t)a2.x * HID))[lane];
        float2 v3 = ((const float2*)(g_t + (size_t)a3.x * HID))[lane];
        acc.x += __int_as_float(a0.y) * v0.x; acc.y += __int_as_float(a0.y) * v0.y;
        acc.x += __int_as_float(a1.y) * v1.x; acc.y += __int_as_float(a1.y) * v1.y;
        acc.x += __int_as_float(a2.y) * v2.x; acc.y += __int_as_float(a2.y) * v2.y;
        acc.x += __int_as_float(a3.y) * v3.x; acc.y += __int_as_float(a3.y) * v3.y;
    }
    for (; e < e1; e++) {
        int2 a = g_csre[e];
        float2 v = ((const float2*)(g_t + (size_t)a.x * HID))[lane];
        acc.x += __int_as_float(a.y) * v.x;
        acc.y += __int_as_float(a.y) * v.y;
    }

    float x0 = acc.x + b[2 * lane], x1 = acc.y + b[2 * lane + 1];
    g_h[(size_t)d * HID + 2 * lane]     = (x0 > 0.f) ? x0 : NEG * x0;
    g_h[(size_t)d * HID + 2 * lane + 1] = (x1 > 0.f) ? x1 : NEG * x1;
}

// ---------------- output: g_h[NN,64]@[64,40] + b, log_softmax ----------------
__global__ void __launch_bounds__(256)
out_kernel(const float* __restrict__ W, const float* __restrict__ b,
           float* __restrict__ out) {
    __shared__ float Ws[HID * NCLS];
    __shared__ float bs[NCLS];
    int tid = threadIdx.x;
    for (int i = tid; i < HID * NCLS; i += 256) Ws[i] = W[i];
    if (tid < NCLS) bs[tid] = b[tid];
    __syncthreads();

    int warp = tid >> 5, lane = tid & 31;
    long long node = (long long)blockIdx.x * 8 + warp;
    if (node >= NN) return;

    float hv0 = g_h[node * HID + lane];
    float hv1 = g_h[node * HID + 32 + lane];

    float a0 = bs[lane];
    float a1 = (lane < 8) ? bs[32 + lane] : 0.f;
#pragma unroll 8
    for (int k = 0; k < HID; k++) {
        float hk = __shfl_sync(0xffffffffu, (k < 32) ? hv0 : hv1, k & 31);
        a0 += hk * Ws[k * NCLS + lane];
        if (lane < 8) a1 += hk * Ws[k * NCLS + 32 + lane];
    }

    float m = (lane < 8) ? fmaxf(a0, a1) : a0;
#pragma unroll
    for (int o = 16; o > 0; o >>= 1)
        m = fmaxf(m, __shfl_xor_sync(0xffffffffu, m, o));

    float s = expf(a0 - m) + ((lane < 8) ? expf(a1 - m) : 0.f);
#pragma unroll
    for (int o = 16; o > 0; o >>= 1)
        s += __shfl_xor_sync(0xffffffffu, s, o);

    float lse = m + logf(s);
    out[node * NCLS + lane] = a0 - lse;
    if (lane < 8) out[node * NCLS + 32 + lane] = a1 - lse;
}

// ---------------- launch (kernel launches ONLY) ------------------------------
extern "C" void kernel_launch(void* const* d_in, const int* in_sizes, int n_in,
                              void* d_out, int out_size) {
    const float* x       = (const float*)d_in[0];
    const void*  ei      = d_in[1];
    const float* ew      = (const float*)d_in[2];
    const float* W_first = (const float*)d_in[3];
    const float* b_first = (const float*)d_in[4];
    const float* Wc1     = (const float*)d_in[5];
    const float* bc1     = (const float*)d_in[6];
    const float* Wc2     = (const float*)d_in[7];
    const float* bc2     = (const float*)d_in[8];
    const float* W_out   = (const float*)d_in[9];
    const float* b_out   = (const float*)d_in[10];
    float* out = (float*)d_out;

    const int T = 256;
    // slot 4 (ncu capture) = new gemm64 to verify the LDS fix
    init_kernel<<<(NN + T - 1) / T, T>>>(ei);                 // 1
    deg_accum_kernel<<<(NE + T - 1) / T, T>>>(ei, ew);        // 2
    gemm128_bias_lrelu<<<NN / 32, T>>>(x, W_first, b_first);  // 3
    gemm64<<<NN / 32, T>>>(Wc1);                              // 4 <- profiled
    scan1_kernel<<<NPART, 256>>>();                           // 5
    scan2_kernel<<<1, 128>>>();                               // 6
    scan3_kernel<<<NPART, 256>>>();                           // 7
    fill_kernel<<<(NE + T - 1) / T, T>>>(ei, ew);             // 8

    agg_kernel<<<(NN * 32 + T - 1) / T, T>>>(bc1);            // 9  : g_t -> g_h
    gemm64<<<NN / 32, T>>>(Wc2);                              // 10 : g_h -> g_t
    agg_kernel<<<(NN * 32 + T - 1) / T, T>>>(bc2);            // 11 : g_t -> g_h
    out_kernel<<<(NN + 7) / 8, T>>>(W_out, b_out, out);       // 12
}

// round 9
// speedup vs baseline: 1.3761x; 1.2140x over previous
#include <cuda_runtime.h>
#include <cuda_bf16.h>

#define NN 100000
#define NE 1600000
#define FEATS 128
#define HID 64
#define NCLS 40
#define NEG 0.01f
#define NPART ((NN + 1023) / 1024)
#define NB64 ((NN + 63) / 64)

// ---------------- scratch (device globals) -----------------------------------
__device__ float g_deg[NN];
__device__ float g_dis[NN];
__device__ float g_h[(size_t)NN * HID];
__device__ float g_t[(size_t)NN * HID];
__device__ int   g_cnt[NN];
__device__ int   g_fill[NN];
__device__ int   g_rowptr[NN + 1];
__device__ int   g_part[NPART];
__device__ int2  g_csre[NE];      // .x = src, .y = norm bits
__device__ int   g_is64;

// ---------------- edge helpers ------------------------------------------------
__device__ __forceinline__ long long edge_node(const void* ei, long long idx) {
    if (g_is64) return ((const long long*)ei)[idx];
    return (long long)((const int*)ei)[idx];
}

// ---------------- init (+ dtype detection) ------------------------------------
__global__ void init_kernel(const void* ei) {
    int i = blockIdx.x * blockDim.x + threadIdx.x;
    if (i < NN) { g_deg[i] = 1.0f; g_cnt[i] = 0; g_fill[i] = 0; }
    if (blockIdx.x == 0 && threadIdx.x == 0) {
        const int* w = (const int*)ei;
        int zeros = 0;
        for (int j = 1; j < 64; j += 2) zeros += (w[j] == 0);
        g_is64 = (zeros == 32) ? 1 : 0;
    }
}

__global__ void deg_accum_kernel(const void* __restrict__ ei,
                                 const float* __restrict__ ew) {
    int e = blockIdx.x * blockDim.x + threadIdx.x;
    if (e < NE) {
        int d = (int)edge_node(ei, (long long)NE + e);
        atomicAdd(&g_deg[d], ew[e]);
        atomicAdd(&g_cnt[d], 1);
    }
}

// ---------------- fused first chain: x@W1 + b1 -> leaky -> @Wc1 -> g_t -------
// 64x64 block tile, 4 rows x 4 cols per thread
__global__ void __launch_bounds__(256)
fused_first(const float* __restrict__ x, const float* __restrict__ W1,
            const float* __restrict__ b1, const float* __restrict__ Wc1) {
    __shared__ float Ws[64 * HID];       // 16 KB
    __shared__ float Xs[64][HID + 1];    // 16.6 KB (X halves, then H)
    int tid = threadIdx.x;
    long long row0 = (long long)blockIdx.x * 64;

    int cg = tid & 15;          // col group (4 cols)
    int rg = tid >> 4;          // row group (4 rows)
    float acc[4][4];
#pragma unroll
    for (int j = 0; j < 4; j++)
#pragma unroll
        for (int c = 0; c < 4; c++) acc[j][c] = 0.f;

#pragma unroll
    for (int ph = 0; ph < 2; ph++) {
        // load X half: 64 rows x 64 cols (clamped rows)
        for (int i = tid; i < 64 * 16; i += 256) {
            int r = i >> 4, c4 = i & 15;
            long long rr = row0 + r; if (rr >= NN) rr = NN - 1;
            float4 v = ((const float4*)x)[rr * (FEATS / 4) + ph * 16 + c4];
            Xs[r][c4 * 4 + 0] = v.x; Xs[r][c4 * 4 + 1] = v.y;
            Xs[r][c4 * 4 + 2] = v.z; Xs[r][c4 * 4 + 3] = v.w;
        }
        for (int i = tid; i < 64 * HID; i += 256) Ws[i] = W1[ph * 64 * HID + i];
        __syncthreads();

#pragma unroll 2
        for (int k = 0; k < 64; k++) {
            float4 w = *(const float4*)&Ws[k * HID + cg * 4];
            float xr[4];
#pragma unroll
            for (int j = 0; j < 4; j++) xr[j] = Xs[rg * 4 + j][k];
#pragma unroll
            for (int j = 0; j < 4; j++) {
                acc[j][0] += xr[j] * w.x; acc[j][1] += xr[j] * w.y;
                acc[j][2] += xr[j] * w.z; acc[j][3] += xr[j] * w.w;
            }
        }
        __syncthreads();
    }

    // bias + leaky -> H into Xs
    float4 bb = *(const float4*)&b1[cg * 4];
#pragma unroll
    for (int j = 0; j < 4; j++) {
        float v0 = acc[j][0] + bb.x, v1 = acc[j][1] + bb.y;
        float v2 = acc[j][2] + bb.z, v3 = acc[j][3] + bb.w;
        Xs[rg * 4 + j][cg * 4 + 0] = (v0 > 0.f) ? v0 : NEG * v0;
        Xs[rg * 4 + j][cg * 4 + 1] = (v1 > 0.f) ? v1 : NEG * v1;
        Xs[rg * 4 + j][cg * 4 + 2] = (v2 > 0.f) ? v2 : NEG * v2;
        Xs[rg * 4 + j][cg * 4 + 3] = (v3 > 0.f) ? v3 : NEG * v3;
    }
    for (int i = tid; i < HID * HID; i += 256) Ws[i] = Wc1[i];
    __syncthreads();

    // second GEMM: H @ Wc1
#pragma unroll
    for (int j = 0; j < 4; j++)
#pragma unroll
        for (int c = 0; c < 4; c++) acc[j][c] = 0.f;

#pragma unroll 2
    for (int k = 0; k < HID; k++) {
        float4 w = *(const float4*)&Ws[k * HID + cg * 4];
        float xr[4];
#pragma unroll
        for (int j = 0; j < 4; j++) xr[j] = Xs[rg * 4 + j][k];
#pragma unroll
        for (int j = 0; j < 4; j++) {
            acc[j][0] += xr[j] * w.x; acc[j][1] += xr[j] * w.y;
            acc[j][2] += xr[j] * w.z; acc[j][3] += xr[j] * w.w;
        }
    }
#pragma unroll
    for (int j = 0; j < 4; j++) {
        long long row = row0 + rg * 4 + j;
        if (row < NN) {
            float4 o = {acc[j][0], acc[j][1], acc[j][2], acc[j][3]};
            ((float4*)g_t)[row * (HID / 4) + cg] = o;
        }
    }
}

// ---------------- GEMM: g_h[NN,64] @ W[64,64] -> g_t, 64x64 tile, 4x4 -------
__global__ void __launch_bounds__(256)
gemm64(const float* __restrict__ W) {
    __shared__ float Ws[HID * HID];      // 16 KB
    __shared__ float Xs[64][HID + 1];    // 16.6 KB
    int tid = threadIdx.x;
    long long row0 = (long long)blockIdx.x * 64;

    for (int i = tid; i < HID * HID; i += 256) Ws[i] = W[i];
    for (int i = tid; i < 64 * 16; i += 256) {
        int r = i >> 4, c4 = i & 15;
        long long rr = row0 + r; if (rr >= NN) rr = NN - 1;
        float4 v = ((const float4*)g_h)[rr * (HID / 4) + c4];
        Xs[r][c4 * 4 + 0] = v.x; Xs[r][c4 * 4 + 1] = v.y;
        Xs[r][c4 * 4 + 2] = v.z; Xs[r][c4 * 4 + 3] = v.w;
    }
    __syncthreads();

    int cg = tid & 15;
    int rg = tid >> 4;
    float acc[4][4];
#pragma unroll
    for (int j = 0; j < 4; j++)
#pragma unroll
        for (int c = 0; c < 4; c++) acc[j][c] = 0.f;

#pragma unroll 2
    for (int k = 0; k < HID; k++) {
        float4 w = *(const float4*)&Ws[k * HID + cg * 4];
        float xr[4];
#pragma unroll
        for (int j = 0; j < 4; j++) xr[j] = Xs[rg * 4 + j][k];
#pragma unroll
        for (int j = 0; j < 4; j++) {
            acc[j][0] += xr[j] * w.x; acc[j][1] += xr[j] * w.y;
            acc[j][2] += xr[j] * w.z; acc[j][3] += xr[j] * w.w;
        }
    }
#pragma unroll
    for (int j = 0; j < 4; j++) {
        long long row = row0 + rg * 4 + j;
        if (row < NN) {
            float4 o = {acc[j][0], acc[j][1], acc[j][2], acc[j][3]};
            ((float4*)g_t)[row * (HID / 4) + cg] = o;
        }
    }
}

// ---------------- scan over g_cnt -> g_rowptr (+ dis fused) -------------------
__global__ void scan1_kernel() {
    __shared__ int sh[256];
    int t = threadIdx.x;
    int nb = blockIdx.x * 1024;
    for (int i = nb + t; i < nb + 1024 && i < NN; i += 256) {
        float d = g_deg[i];
        g_dis[i] = (d > 0.f) ? rsqrtf(d) : 0.f;
    }
    int base = nb + t * 4;
    int s = 0;
#pragma unroll
    for (int j = 0; j < 4; j++) if (base + j < NN) s += g_cnt[base + j];
    sh[t] = s; __syncthreads();
#pragma unroll
    for (int o = 128; o > 0; o >>= 1) {
        if (t < o) sh[t] += sh[t + o];
        __syncthreads();
    }
    if (t == 0) g_part[blockIdx.x] = sh[0];
}

__global__ void scan2_kernel() {
    __shared__ int sh[128];
    int t = threadIdx.x;
    int v = (t < NPART) ? g_part[t] : 0;
    sh[t] = v; __syncthreads();
    for (int o = 1; o < 128; o <<= 1) {
        int x = (t >= o) ? sh[t - o] : 0;
        __syncthreads();
        sh[t] += x;
        __syncthreads();
    }
    if (t < NPART) g_part[t] = sh[t] - v;   // exclusive
}

__global__ void scan3_kernel() {
    __shared__ int sh[256];
    int t = threadIdx.x;
    int base = blockIdx.x * 1024 + t * 4;
    int v[4]; int s = 0;
#pragma unroll
    for (int j = 0; j < 4; j++) { v[j] = (base + j < NN) ? g_cnt[base + j] : 0; s += v[j]; }
    sh[t] = s; __syncthreads();
    for (int o = 1; o < 256; o <<= 1) {
        int x = (t >= o) ? sh[t - o] : 0;
        __syncthreads();
        sh[t] += x;
        __syncthreads();
    }
    int off = (t == 0) ? 0 : sh[t - 1];
    int b = g_part[blockIdx.x] + off;
    int run = 0;
#pragma unroll
    for (int j = 0; j < 4; j++) {
        if (base + j < NN) g_rowptr[base + j] = b + run;
        run += v[j];
    }
    if (blockIdx.x == 0 && t == 0) g_rowptr[NN] = NE;
}

// ---------------- CSR fill (norm computed inline, packed int2) ----------------
__global__ void fill_kernel(const void* __restrict__ ei,
                            const float* __restrict__ ew) {
    int e = blockIdx.x * blockDim.x + threadIdx.x;
    if (e < NE) {
        int s = (int)edge_node(ei, e);
        int d = (int)edge_node(ei, (long long)NE + e);
        float nrm = g_dis[s] * ew[e] * g_dis[d];
        int pos = g_rowptr[d] + atomicAdd(&g_fill[d], 1);
        g_csre[pos] = make_int2(s, __float_as_int(nrm));
    }
}

// ---------------- agg: warp per dst, fused self+bias+leaky, MLP4 -------------
__global__ void __launch_bounds__(256)
agg_kernel(const float* __restrict__ b) {
    int warp = (blockIdx.x * 256 + threadIdx.x) >> 5;
    int lane = threadIdx.x & 31;
    if (warp >= NN) return;
    int d = warp;

    float dd = g_dis[d];
    float sc = dd * dd;
    float2 acc = ((const float2*)(g_t + (size_t)d * HID))[lane];
    acc.x *= sc; acc.y *= sc;

    int e = g_rowptr[d], e1 = g_rowptr[d + 1];
    for (; e + 4 <= e1; e += 4) {
        int2 a0 = g_csre[e], a1 = g_csre[e + 1], a2 = g_csre[e + 2], a3 = g_csre[e + 3];
        float2 v0 = ((const float2*)(g_t + (size_t)a0.x * HID))[lane];
        float2 v1 = ((const float2*)(g_t + (size_t)a1.x * HID))[lane];
        float2 v2 = ((const float2*)(g_t + (size_t)a2.x * HID))[lane];
        float2 v3 = ((const float2*)(g_t + (size_t)a3.x * HID))[lane];
        acc.x += __int_as_float(a0.y) * v0.x; acc.y += __int_as_float(a0.y) * v0.y;
        acc.x += __int_as_float(a1.y) * v1.x; acc.y += __int_as_float(a1.y) * v1.y;
        acc.x += __int_as_float(a2.y) * v2.x; acc.y += __int_as_float(a2.y) * v2.y;
        acc.x += __int_as_float(a3.y) * v3.x; acc.y += __int_as_float(a3.y) * v3.y;
    }
    for (; e < e1; e++) {
        int2 a = g_csre[e];
        float2 v = ((const float2*)(g_t + (size_t)a.x * HID))[lane];
        acc.x += __int_as_float(a.y) * v.x;
        acc.y += __int_as_float(a.y) * v.y;
    }

    float x0 = acc.x + b[2 * lane], x1 = acc.y + b[2 * lane + 1];
    g_h[(size_t)d * HID + 2 * lane]     = (x0 > 0.f) ? x0 : NEG * x0;
    g_h[(size_t)d * HID + 2 * lane + 1] = (x1 > 0.f) ? x1 : NEG * x1;
}

// ---------------- output: g_h[NN,64]@[64,40] + b, log_softmax ----------------
__global__ void __launch_bounds__(256)
out_kernel(const float* __restrict__ W, const float* __restrict__ b,
           float* __restrict__ out) {
    __shared__ float Ws[HID * NCLS];
    __shared__ float bs[NCLS];
    int tid = threadIdx.x;
    for (int i = tid; i < HID * NCLS; i += 256) Ws[i] = W[i];
    if (tid < NCLS) bs[tid] = b[tid];
    __syncthreads();

    int warp = tid >> 5, lane = tid & 31;
    long long node = (long long)blockIdx.x * 8 + warp;
    if (node >= NN) return;

    float hv0 = g_h[node * HID + lane];
    float hv1 = g_h[node * HID + 32 + lane];

    float a0 = bs[lane];
    float a1 = (lane < 8) ? bs[32 + lane] : 0.f;
#pragma unroll 8
    for (int k = 0; k < HID; k++) {
        float hk = __shfl_sync(0xffffffffu, (k < 32) ? hv0 : hv1, k & 31);
        a0 += hk * Ws[k * NCLS + lane];
        if (lane < 8) a1 += hk * Ws[k * NCLS + 32 + lane];
    }

    float m = (lane < 8) ? fmaxf(a0, a1) : a0;
#pragma unroll
    for (int o = 16; o > 0; o >>= 1)
        m = fmaxf(m, __shfl_xor_sync(0xffffffffu, m, o));

    float s = expf(a0 - m) + ((lane < 8) ? expf(a1 - m) : 0.f);
#pragma unroll
    for (int o = 16; o > 0; o >>= 1)
        s += __shfl_xor_sync(0xffffffffu, s, o);

    float lse = m + logf(s);
    out[node * NCLS + lane] = a0 - lse;
    if (lane < 8) out[node * NCLS + 32 + lane] = a1 - lse;
}

// ---------------- launch (kernel launches ONLY) ------------------------------
extern "C" void kernel_launch(void* const* d_in, const int* in_sizes, int n_in,
                              void* d_out, int out_size) {
    const float* x       = (const float*)d_in[0];
    const void*  ei      = d_in[1];
    const float* ew      = (const float*)d_in[2];
    const float* W_first = (const float*)d_in[3];
    const float* b_first = (const float*)d_in[4];
    const float* Wc1     = (const float*)d_in[5];
    const float* bc1     = (const float*)d_in[6];
    const float* Wc2     = (const float*)d_in[7];
    const float* bc2     = (const float*)d_in[8];
    const float* W_out   = (const float*)d_in[9];
    const float* b_out   = (const float*)d_in[10];
    float* out = (float*)d_out;

    const int T = 256;
    // slot 4 (empirical ncu capture) = fused_first
    init_kernel<<<(NN + T - 1) / T, T>>>(ei);                    // 1
    deg_accum_kernel<<<(NE + T - 1) / T, T>>>(ei, ew);           // 2
    scan1_kernel<<<NPART, 256>>>();                              // 3
    fused_first<<<NB64, T>>>(x, W_first, b_first, Wc1);          // 4 <- profiled
    scan2_kernel<<<1, 128>>>();                                  // 5
    scan3_kernel<<<NPART, 256>>>();                              // 6
    fill_kernel<<<(NE + T - 1) / T, T>>>(ei, ew);                // 7

    agg_kernel<<<(NN * 32 + T - 1) / T, T>>>(bc1);               // 8  : g_t -> g_h
    gemm64<<<NB64, T>>>(Wc2);                                    // 9  : g_h -> g_t
    agg_kernel<<<(NN * 32 + T - 1) / T, T>>>(bc2);               // 10 : g_t -> g_h
    out_kernel<<<(NN + 7) / 8, T>>>(W_out, b_out, out);          // 11
}

// round 10
// speedup vs baseline: 1.3920x; 1.0115x over previous
#include <cuda_runtime.h>
#include <cuda_bf16.h>

#define NN 100000
#define NE 1600000
#define FEATS 128
#define HID 64
#define NCLS 40
#define NEG 0.01f
#define NPART ((NN + 1023) / 1024)
#define NB64 ((NN + 63) / 64)
#define XPAD 68   // 16B-aligned row stride for Xs

typedef unsigned long long ull;

// ---------------- f32x2 helpers ----------------------------------------------
__device__ __forceinline__ ull pack2(float lo, float hi) {
    ull r;
    asm("mov.b64 %0, {%1, %2};" : "=l"(r) : "f"(lo), "f"(hi));
    return r;
}
__device__ __forceinline__ void ffma2(ull& d, ull a, ull b) {
    asm("fma.rn.f32x2 %0, %1, %2, %3;" : "=l"(d) : "l"(a), "l"(b), "l"(d));
}
__device__ __forceinline__ float2 unpack2(ull v) {
    float2 f;
    asm("mov.b64 {%0, %1}, %2;" : "=f"(f.x), "=f"(f.y) : "l"(v));
    return f;
}

// ---------------- scratch (device globals) -----------------------------------
__device__ float g_deg[NN];
__device__ float g_dis[NN];
__device__ float g_h[(size_t)NN * HID];
__device__ float g_t[(size_t)NN * HID];
__device__ int   g_cnt[NN];
__device__ int   g_fill[NN];
__device__ int   g_rowptr[NN + 1];
__device__ int   g_part[NPART];
__device__ int2  g_csre[NE];      // .x = src, .y = norm bits
__device__ int   g_is64;

// ---------------- edge helpers ------------------------------------------------
__device__ __forceinline__ long long edge_node(const void* ei, long long idx) {
    if (g_is64) return ((const long long*)ei)[idx];
    return (long long)((const int*)ei)[idx];
}

// ---------------- init (+ dtype detection) ------------------------------------
__global__ void init_kernel(const void* ei) {
    int i = blockIdx.x * blockDim.x + threadIdx.x;
    if (i < NN) { g_deg[i] = 1.0f; g_cnt[i] = 0; g_fill[i] = 0; }
    if (blockIdx.x == 0 && threadIdx.x == 0) {
        const int* w = (const int*)ei;
        int zeros = 0;
        for (int j = 1; j < 64; j += 2) zeros += (w[j] == 0);
        g_is64 = (zeros == 32) ? 1 : 0;
    }
}

__global__ void deg_accum_kernel(const void* __restrict__ ei,
                                 const float* __restrict__ ew) {
    int e = blockIdx.x * blockDim.x + threadIdx.x;
    if (e < NE) {
        int d = (int)edge_node(ei, (long long)NE + e);
        atomicAdd(&g_deg[d], ew[e]);
        atomicAdd(&g_cnt[d], 1);
    }
}

// ---------------- core 64x64 f32x2 GEMM step over smem tiles -----------------
// acc[j][p] += Xs[rg*4+j][k] * Ws[k][cg*4 + 2p .. 2p+1], k = 0..63
__device__ __forceinline__ void mma_tile_64(const float (*Xs)[XPAD],
                                            const float* Ws,
                                            int rg, int cg, ull acc[4][2]) {
#pragma unroll 4
    for (int k4 = 0; k4 < 16; k4++) {
        float4 xj[4];
#pragma unroll
        for (int j = 0; j < 4; j++)
            xj[j] = *(const float4*)&Xs[rg * 4 + j][k4 * 4];
#pragma unroll
        for (int kk = 0; kk < 4; kk++) {
            ulonglong2 wv = *(const ulonglong2*)&Ws[(k4 * 4 + kk) * HID + cg * 4];
            float xc[4] = {
                kk == 0 ? xj[0].x : kk == 1 ? xj[0].y : kk == 2 ? xj[0].z : xj[0].w,
                kk == 0 ? xj[1].x : kk == 1 ? xj[1].y : kk == 2 ? xj[1].z : xj[1].w,
                kk == 0 ? xj[2].x : kk == 1 ? xj[2].y : kk == 2 ? xj[2].z : xj[2].w,
                kk == 0 ? xj[3].x : kk == 1 ? xj[3].y : kk == 2 ? xj[3].z : xj[3].w };
#pragma unroll
            for (int j = 0; j < 4; j++) {
                ull xx = pack2(xc[j], xc[j]);
                ffma2(acc[j][0], xx, wv.x);
                ffma2(acc[j][1], xx, wv.y);
            }
        }
    }
}

// ---------------- fused first chain: x@W1 + b1 -> leaky -> @Wc1 -> g_t -------
__global__ void __launch_bounds__(256)
fused_first(const float* __restrict__ x, const float* __restrict__ W1,
            const float* __restrict__ b1, const float* __restrict__ Wc1) {
    __shared__ float Ws[64 * HID];       // 16 KB
    __shared__ float Xs[64][XPAD];       // 17.4 KB
    int tid = threadIdx.x;
    long long row0 = (long long)blockIdx.x * 64;

    int cg = tid & 15;          // col group (4 cols)
    int rg = tid >> 4;          // row group (4 rows)
    ull acc[4][2];
    ull z = pack2(0.f, 0.f);
#pragma unroll
    for (int j = 0; j < 4; j++) { acc[j][0] = z; acc[j][1] = z; }

#pragma unroll
    for (int ph = 0; ph < 2; ph++) {
        for (int i = tid; i < 64 * 16; i += 256) {
            int r = i >> 4, c4 = i & 15;
            long long rr = row0 + r; if (rr >= NN) rr = NN - 1;
            float4 v = ((const float4*)x)[rr * (FEATS / 4) + ph * 16 + c4];
            *(float4*)&Xs[r][c4 * 4] = v;
        }
        for (int i = tid; i < 64 * HID; i += 256) Ws[i] = W1[ph * 64 * HID + i];
        __syncthreads();
        mma_tile_64(Xs, Ws, rg, cg, acc);
        __syncthreads();
    }

    // bias + leaky -> H back into Xs
    float4 bb = *(const float4*)&b1[cg * 4];
#pragma unroll
    for (int j = 0; j < 4; j++) {
        float2 p0 = unpack2(acc[j][0]);
        float2 p1 = unpack2(acc[j][1]);
        float v0 = p0.x + bb.x, v1 = p0.y + bb.y;
        float v2 = p1.x + bb.z, v3 = p1.y + bb.w;
        float4 h;
        h.x = (v0 > 0.f) ? v0 : NEG * v0;
        h.y = (v1 > 0.f) ? v1 : NEG * v1;
        h.z = (v2 > 0.f) ? v2 : NEG * v2;
        h.w = (v3 > 0.f) ? v3 : NEG * v3;
        *(float4*)&Xs[rg * 4 + j][cg * 4] = h;
    }
    for (int i = tid; i < HID * HID; i += 256) Ws[i] = Wc1[i];
    __syncthreads();

    // second GEMM: H @ Wc1
#pragma unroll
    for (int j = 0; j < 4; j++) { acc[j][0] = z; acc[j][1] = z; }
    mma_tile_64(Xs, Ws, rg, cg, acc);

#pragma unroll
    for (int j = 0; j < 4; j++) {
        long long row = row0 + rg * 4 + j;
        if (row < NN) {
            float2 p0 = unpack2(acc[j][0]);
            float2 p1 = unpack2(acc[j][1]);
            float4 o = {p0.x, p0.y, p1.x, p1.y};
            ((float4*)g_t)[row * (HID / 4) + cg] = o;
        }
    }
}

// ---------------- GEMM: g_h[NN,64] @ W[64,64] -> g_t -------------------------
__global__ void __launch_bounds__(256)
gemm64(const float* __restrict__ W) {
    __shared__ float Ws[HID * HID];      // 16 KB
    __shared__ float Xs[64][XPAD];       // 17.4 KB
    int tid = threadIdx.x;
    long long row0 = (long long)blockIdx.x * 64;

    for (int i = tid; i < HID * HID; i += 256) Ws[i] = W[i];
    for (int i = tid; i < 64 * 16; i += 256) {
        int r = i >> 4, c4 = i & 15;
        long long rr = row0 + r; if (rr >= NN) rr = NN - 1;
        float4 v = ((const float4*)g_h)[rr * (HID / 4) + c4];
        *(float4*)&Xs[r][c4 * 4] = v;
    }
    __syncthreads();

    int cg = tid & 15;
    int rg = tid >> 4;
    ull acc[4][2];
    ull z = pack2(0.f, 0.f);
#pragma unroll
    for (int j = 0; j < 4; j++) { acc[j][0] = z; acc[j][1] = z; }
    mma_tile_64(Xs, Ws, rg, cg, acc);

#pragma unroll
    for (int j = 0; j < 4; j++) {
        long long row = row0 + rg * 4 + j;
        if (row < NN) {
            float2 p0 = unpack2(acc[j][0]);
            float2 p1 = unpack2(acc[j][1]);
            float4 o = {p0.x, p0.y, p1.x, p1.y};
            ((float4*)g_t)[row * (HID / 4) + cg] = o;
        }
    }
}

// ---------------- scan over g_cnt -> g_rowptr (+ dis fused) -------------------
__global__ void scan1_kernel() {
    __shared__ int sh[256];
    int t = threadIdx.x;
    int nb = blockIdx.x * 1024;
    for (int i = nb + t; i < nb + 1024 && i < NN; i += 256) {
        float d = g_deg[i];
        g_dis[i] = (d > 0.f) ? rsqrtf(d) : 0.f;
    }
    int base = nb + t * 4;
    int s = 0;
#pragma unroll
    for (int j = 0; j < 4; j++) if (base + j < NN) s += g_cnt[base + j];
    sh[t] = s; __syncthreads();
#pragma unroll
    for (int o = 128; o > 0; o >>= 1) {
        if (t < o) sh[t] += sh[t + o];
        __syncthreads();
    }
    if (t == 0) g_part[blockIdx.x] = sh[0];
}

__global__ void scan2_kernel() {
    __shared__ int sh[128];
    int t = threadIdx.x;
    int v = (t < NPART) ? g_part[t] : 0;
    sh[t] = v; __syncthreads();
    for (int o = 1; o < 128; o <<= 1) {
        int x = (t >= o) ? sh[t - o] : 0;
        __syncthreads();
        sh[t] += x;
        __syncthreads();
    }
    if (t < NPART) g_part[t] = sh[t] - v;   // exclusive
}

__global__ void scan3_kernel() {
    __shared__ int sh[256];
    int t = threadIdx.x;
    int base = blockIdx.x * 1024 + t * 4;
    int v[4]; int s = 0;
#pragma unroll
    for (int j = 0; j < 4; j++) { v[j] = (base + j < NN) ? g_cnt[base + j] : 0; s += v[j]; }
    sh[t] = s; __syncthreads();
    for (int o = 1; o < 256; o <<= 1) {
        int x = (t >= o) ? sh[t - o] : 0;
        __syncthreads();
        sh[t] += x;
        __syncthreads();
    }
    int off = (t == 0) ? 0 : sh[t - 1];
    int b = g_part[blockIdx.x] + off;
    int run = 0;
#pragma unroll
    for (int j = 0; j < 4; j++) {
        if (base + j < NN) g_rowptr[base + j] = b + run;
        run += v[j];
    }
    if (blockIdx.x == 0 && t == 0) g_rowptr[NN] = NE;
}

// ---------------- CSR fill (norm computed inline, packed int2) ----------------
__global__ void fill_kernel(const void* __restrict__ ei,
                            const float* __restrict__ ew) {
    int e = blockIdx.x * blockDim.x + threadIdx.x;
    if (e < NE) {
        int s = (int)edge_node(ei, e);
        int d = (int)edge_node(ei, (long long)NE + e);
        float nrm = g_dis[s] * ew[e] * g_dis[d];
        int pos = g_rowptr[d] + atomicAdd(&g_fill[d], 1);
        g_csre[pos] = make_int2(s, __float_as_int(nrm));
    }
}

// ---------------- agg: warp per dst, fused self+bias+leaky, MLP4 -------------
__global__ void __launch_bounds__(256)
agg_kernel(const float* __restrict__ b) {
    int warp = (blockIdx.x * 256 + threadIdx.x) >> 5;
    int lane = threadIdx.x & 31;
    if (warp >= NN) return;
    int d = warp;

    float dd = g_dis[d];
    float sc = dd * dd;
    float2 acc = ((const float2*)(g_t + (size_t)d * HID))[lane];
    acc.x *= sc; acc.y *= sc;

    int e = g_rowptr[d], e1 = g_rowptr[d + 1];
    for (; e + 4 <= e1; e += 4) {
        int2 a0 = g_csre[e], a1 = g_csre[e + 1], a2 = g_csre[e + 2], a3 = g_csre[e + 3];
        float2 v0 = ((const float2*)(g_t + (size_t)a0.x * HID))[lane];
        float2 v1 = ((const float2*)(g_t + (size_t)a1.x * HID))[lane];
        float2 v2 = ((const float2*)(g_t + (size_t)a2.x * HID))[lane];
        float2 v3 = ((const float2*)(g_t + (size_t)a3.x * HID))[lane];
        acc.x += __int_as_float(a0.y) * v0.x; acc.y += __int_as_float(a0.y) * v0.y;
        acc.x += __int_as_float(a1.y) * v1.x; acc.y += __int_as_float(a1.y) * v1.y;
        acc.x += __int_as_float(a2.y) * v2.x; acc.y += __int_as_float(a2.y) * v2.y;
        acc.x += __int_as_float(a3.y) * v3.x; acc.y += __int_as_float(a3.y) * v3.y;
    }
    for (; e < e1; e++) {
        int2 a = g_csre[e];
        float2 v = ((const float2*)(g_t + (size_t)a.x * HID))[lane];
        acc.x += __int_as_float(a.y) * v.x;
        acc.y += __int_as_float(a.y) * v.y;
    }

    float x0 = acc.x + b[2 * lane], x1 = acc.y + b[2 * lane + 1];
    g_h[(size_t)d * HID + 2 * lane]     = (x0 > 0.f) ? x0 : NEG * x0;
    g_h[(size_t)d * HID + 2 * lane + 1] = (x1 > 0.f) ? x1 : NEG * x1;
}

// ---------------- output: g_h[NN,64]@[64,40] + b, log_softmax ----------------
__global__ void __launch_bounds__(256)
out_kernel(const float* __restrict__ W, const float* __restrict__ b,
           float* __restrict__ out) {
    __shared__ float Ws[HID * NCLS];
    __shared__ float bs[NCLS];
    int tid = threadIdx.x;
    for (int i = tid; i < HID * NCLS; i += 256) Ws[i] = W[i];
    if (tid < NCLS) bs[tid] = b[tid];
    __syncthreads();

    int warp = tid >> 5, lane = tid & 31;
    long long node = (long long)blockIdx.x * 8 + warp;
    if (node >= NN) return;

    float hv0 = g_h[node * HID + lane];
    float hv1 = g_h[node * HID + 32 + lane];

    float a0 = bs[lane];
    float a1 = (lane < 8) ? bs[32 + lane] : 0.f;
#pragma unroll 8
    for (int k = 0; k < HID; k++) {
        float hk = __shfl_sync(0xffffffffu, (k < 32) ? hv0 : hv1, k & 31);
        a0 += hk * Ws[k * NCLS + lane];
        if (lane < 8) a1 += hk * Ws[k * NCLS + 32 + lane];
    }

    float m = (lane < 8) ? fmaxf(a0, a1) : a0;
#pragma unroll
    for (int o = 16; o > 0; o >>= 1)
        m = fmaxf(m, __shfl_xor_sync(0xffffffffu, m, o));

    float s = expf(a0 - m) + ((lane < 8) ? expf(a1 - m) : 0.f);
#pragma unroll
    for (int o = 16; o > 0; o >>= 1)
        s += __shfl_xor_sync(0xffffffffu, s, o);

    float lse = m + logf(s);
    out[node * NCLS + lane] = a0 - lse;
    if (lane < 8) out[node * NCLS + 32 + lane] = a1 - lse;
}

// ---------------- launch (kernel launches ONLY) ------------------------------
extern "C" void kernel_launch(void* const* d_in, const int* in_sizes, int n_in,
                              void* d_out, int out_size) {
    const float* x       = (const float*)d_in[0];
    const void*  ei      = d_in[1];
    const float* ew      = (const float*)d_in[2];
    const float* W_first = (const float*)d_in[3];
    const float* b_first = (const float*)d_in[4];
    const float* Wc1     = (const float*)d_in[5];
    const float* bc1     = (const float*)d_in[6];
    const float* Wc2     = (const float*)d_in[7];
    const float* bc2     = (const float*)d_in[8];
    const float* W_out   = (const float*)d_in[9];
    const float* b_out   = (const float*)d_in[10];
    float* out = (float*)d_out;

    const int T = 256;
    // slot 4 (empirical ncu capture) = fused_first to verify f32x2 win
    init_kernel<<<(NN + T - 1) / T, T>>>(ei);                    // 1
    deg_accum_kernel<<<(NE + T - 1) / T, T>>>(ei, ew);           // 2
    scan1_kernel<<<NPART, 256>>>();                              // 3
    fused_first<<<NB64, T>>>(x, W_first, b_first, Wc1);          // 4 <- profiled
    scan2_kernel<<<1, 128>>>();                                  // 5
    scan3_kernel<<<NPART, 256>>>();                              // 6
    fill_kernel<<<(NE + T - 1) / T, T>>>(ei, ew);                // 7

    agg_kernel<<<(NN * 32 + T - 1) / T, T>>>(bc1);               // 8  : g_t -> g_h
    gemm64<<<NB64, T>>>(Wc2);                                    // 9  : g_h -> g_t
    agg_kernel<<<(NN * 32 + T - 1) / T, T>>>(bc2);               // 10 : g_t -> g_h
    out_kernel<<<(NN + 7) / 8, T>>>(W_out, b_out, out);          // 11
}

// round 11
// speedup vs baseline: 1.4000x; 1.0058x over previous
#include <cuda_runtime.h>
#include <cuda_bf16.h>
#include <cuda_fp16.h>

#define NN 100000
#define NE 1600000
#define FEATS 128
#define HID 64
#define NCLS 40
#define NEG 0.01f
#define NPART ((NN + 1023) / 1024)
#define NB64 ((NN + 63) / 64)
#define XPAD 68   // 16B-aligned row stride for Xs

typedef unsigned long long ull;

// ---------------- f32x2 helpers ----------------------------------------------
__device__ __forceinline__ ull pack2(float lo, float hi) {
    ull r;
    asm("mov.b64 %0, {%1, %2};" : "=l"(r) : "f"(lo), "f"(hi));
    return r;
}
__device__ __forceinline__ void ffma2(ull& d, ull a, ull b) {
    asm("fma.rn.f32x2 %0, %1, %2, %3;" : "=l"(d) : "l"(a), "l"(b), "l"(d));
}
__device__ __forceinline__ float2 unpack2(ull v) {
    float2 f;
    asm("mov.b64 {%0, %1}, %2;" : "=f"(f.x), "=f"(f.y) : "l"(v));
    return f;
}

// ---------------- scratch (device globals) -----------------------------------
__device__ float  g_deg[NN];
__device__ float  g_dis[NN];
__device__ float  g_h[(size_t)NN * HID];
__device__ __half g_t16[(size_t)NN * HID];   // fp16 messages for aggregation
__device__ int    g_cnt[NN];
__device__ int    g_fill[NN];
__device__ int    g_rowptr[NN + 1];
__device__ int    g_part[NPART];
__device__ int2   g_csre[NE];     // .x = src, .y = norm bits
__device__ int    g_is64;

// ---------------- edge helpers ------------------------------------------------
__device__ __forceinline__ long long edge_node(const void* ei, long long idx) {
    if (g_is64) return ((const long long*)ei)[idx];
    return (long long)((const int*)ei)[idx];
}

// ---------------- init (+ dtype detection) ------------------------------------
__global__ void init_kernel(const void* ei) {
    int i = blockIdx.x * blockDim.x + threadIdx.x;
    if (i < NN) { g_deg[i] = 1.0f; g_cnt[i] = 0; g_fill[i] = 0; }
    if (blockIdx.x == 0 && threadIdx.x == 0) {
        const int* w = (const int*)ei;
        int zeros = 0;
        for (int j = 1; j < 64; j += 2) zeros += (w[j] == 0);
        g_is64 = (zeros == 32) ? 1 : 0;
    }
}

__global__ void deg_accum_kernel(const void* __restrict__ ei,
                                 const float* __restrict__ ew) {
    int e = blockIdx.x * blockDim.x + threadIdx.x;
    if (e < NE) {
        int d = (int)edge_node(ei, (long long)NE + e);
        atomicAdd(&g_deg[d], ew[e]);
        atomicAdd(&g_cnt[d], 1);
    }
}

// ---------------- fp16 epilogue store ----------------------------------------
__device__ __forceinline__ void store_t16(long long row, int cg, float4 o) {
    __half2 h0 = __floats2half2_rn(o.x, o.y);
    __half2 h1 = __floats2half2_rn(o.z, o.w);
    uint2 u;
    u.x = *(unsigned int*)&h0;
    u.y = *(unsigned int*)&h1;
    ((uint2*)g_t16)[row * 16 + cg] = u;   // 8 bytes = 4 halves at col cg*4
}

// ---------------- core 64x64 f32x2 GEMM step over smem tiles -----------------
__device__ __forceinline__ void mma_tile_64(const float (*Xs)[XPAD],
                                            const float* Ws,
                                            int rg, int cg, ull acc[4][2]) {
#pragma unroll 4
    for (int k4 = 0; k4 < 16; k4++) {
        float4 xj[4];
#pragma unroll
        for (int j = 0; j < 4; j++)
            xj[j] = *(const float4*)&Xs[rg * 4 + j][k4 * 4];
#pragma unroll
        for (int kk = 0; kk < 4; kk++) {
            ulonglong2 wv = *(const ulonglong2*)&Ws[(k4 * 4 + kk) * HID + cg * 4];
            float xc[4] = {
                kk == 0 ? xj[0].x : kk == 1 ? xj[0].y : kk == 2 ? xj[0].z : xj[0].w,
                kk == 0 ? xj[1].x : kk == 1 ? xj[1].y : kk == 2 ? xj[1].z : xj[1].w,
                kk == 0 ? xj[2].x : kk == 1 ? xj[2].y : kk == 2 ? xj[2].z : xj[2].w,
                kk == 0 ? xj[3].x : kk == 1 ? xj[3].y : kk == 2 ? xj[3].z : xj[3].w };
#pragma unroll
            for (int j = 0; j < 4; j++) {
                ull xx = pack2(xc[j], xc[j]);
                ffma2(acc[j][0], xx, wv.x);
                ffma2(acc[j][1], xx, wv.y);
            }
        }
    }
}

// ---------------- fused first chain: x@W1 + b1 -> leaky -> @Wc1 -> g_t16 -----
__global__ void __launch_bounds__(256)
fused_first(const float* __restrict__ x, const float* __restrict__ W1,
            const float* __restrict__ b1, const float* __restrict__ Wc1) {
    __shared__ float Ws[64 * HID];       // 16 KB
    __shared__ float Xs[64][XPAD];       // 17.4 KB
    int tid = threadIdx.x;
    long long row0 = (long long)blockIdx.x * 64;

    int cg = tid & 15;
    int rg = tid >> 4;
    ull acc[4][2];
    ull z = pack2(0.f, 0.f);
#pragma unroll
    for (int j = 0; j < 4; j++) { acc[j][0] = z; acc[j][1] = z; }

#pragma unroll
    for (int ph = 0; ph < 2; ph++) {
        for (int i = tid; i < 64 * 16; i += 256) {
            int r = i >> 4, c4 = i & 15;
            long long rr = row0 + r; if (rr >= NN) rr = NN - 1;
            float4 v = ((const float4*)x)[rr * (FEATS / 4) + ph * 16 + c4];
            *(float4*)&Xs[r][c4 * 4] = v;
        }
        for (int i = tid; i < 64 * HID; i += 256) Ws[i] = W1[ph * 64 * HID + i];
        __syncthreads();
        mma_tile_64(Xs, Ws, rg, cg, acc);
        __syncthreads();
    }

    // bias + leaky -> H back into Xs
    float4 bb = *(const float4*)&b1[cg * 4];
#pragma unroll
    for (int j = 0; j < 4; j++) {
        float2 p0 = unpack2(acc[j][0]);
        float2 p1 = unpack2(acc[j][1]);
        float v0 = p0.x + bb.x, v1 = p0.y + bb.y;
        float v2 = p1.x + bb.z, v3 = p1.y + bb.w;
        float4 h;
        h.x = (v0 > 0.f) ? v0 : NEG * v0;
        h.y = (v1 > 0.f) ? v1 : NEG * v1;
        h.z = (v2 > 0.f) ? v2 : NEG * v2;
        h.w = (v3 > 0.f) ? v3 : NEG * v3;
        *(float4*)&Xs[rg * 4 + j][cg * 4] = h;
    }
    for (int i = tid; i < HID * HID; i += 256) Ws[i] = Wc1[i];
    __syncthreads();

    // second GEMM: H @ Wc1
#pragma unroll
    for (int j = 0; j < 4; j++) { acc[j][0] = z; acc[j][1] = z; }
    mma_tile_64(Xs, Ws, rg, cg, acc);

#pragma unroll
    for (int j = 0; j < 4; j++) {
        long long row = row0 + rg * 4 + j;
        if (row < NN) {
            float2 p0 = unpack2(acc[j][0]);
            float2 p1 = unpack2(acc[j][1]);
            float4 o = {p0.x, p0.y, p1.x, p1.y};
            store_t16(row, cg, o);
        }
    }
}

// ---------------- GEMM: g_h[NN,64] @ W[64,64] -> g_t16 -----------------------
__global__ void __launch_bounds__(256)
gemm64(const float* __restrict__ W) {
    __shared__ float Ws[HID * HID];      // 16 KB
    __shared__ float Xs[64][XPAD];       // 17.4 KB
    int tid = threadIdx.x;
    long long row0 = (long long)blockIdx.x * 64;

    for (int i = tid; i < HID * HID; i += 256) Ws[i] = W[i];
    for (int i = tid; i < 64 * 16; i += 256) {
        int r = i >> 4, c4 = i & 15;
        long long rr = row0 + r; if (rr >= NN) rr = NN - 1;
        float4 v = ((const float4*)g_h)[rr * (HID / 4) + c4];
        *(float4*)&Xs[r][c4 * 4] = v;
    }
    __syncthreads();

    int cg = tid & 15;
    int rg = tid >> 4;
    ull acc[4][2];
    ull z = pack2(0.f, 0.f);
#pragma unroll
    for (int j = 0; j < 4; j++) { acc[j][0] = z; acc[j][1] = z; }
    mma_tile_64(Xs, Ws, rg, cg, acc);

#pragma unroll
    for (int j = 0; j < 4; j++) {
        long long row = row0 + rg * 4 + j;
        if (row < NN) {
            float2 p0 = unpack2(acc[j][0]);
            float2 p1 = unpack2(acc[j][1]);
            float4 o = {p0.x, p0.y, p1.x, p1.y};
            store_t16(row, cg, o);
        }
    }
}

// ---------------- scan over g_cnt -> g_rowptr (+ dis fused) -------------------
__global__ void scan1_kernel() {
    __shared__ int sh[256];
    int t = threadIdx.x;
    int nb = blockIdx.x * 1024;
    for (int i = nb + t; i < nb + 1024 && i < NN; i += 256) {
        float d = g_deg[i];
        g_dis[i] = (d > 0.f) ? rsqrtf(d) : 0.f;
    }
    int base = nb + t * 4;
    int s = 0;
#pragma unroll
    for (int j = 0; j < 4; j++) if (base + j < NN) s += g_cnt[base + j];
    sh[t] = s; __syncthreads();
#pragma unroll
    for (int o = 128; o > 0; o >>= 1) {
        if (t < o) sh[t] += sh[t + o];
        __syncthreads();
    }
    if (t == 0) g_part[blockIdx.x] = sh[0];
}

__global__ void scan2_kernel() {
    __shared__ int sh[128];
    int t = threadIdx.x;
    int v = (t < NPART) ? g_part[t] : 0;
    sh[t] = v; __syncthreads();
    for (int o = 1; o < 128; o <<= 1) {
        int x = (t >= o) ? sh[t - o] : 0;
        __syncthreads();
        sh[t] += x;
        __syncthreads();
    }
    if (t < NPART) g_part[t] = sh[t] - v;   // exclusive
}

__global__ void scan3_kernel() {
    __shared__ int sh[256];
    int t = threadIdx.x;
    int base = blockIdx.x * 1024 + t * 4;
    int v[4]; int s = 0;
#pragma unroll
    for (int j = 0; j < 4; j++) { v[j] = (base + j < NN) ? g_cnt[base + j] : 0; s += v[j]; }
    sh[t] = s; __syncthreads();
    for (int o = 1; o < 256; o <<= 1) {
        int x = (t >= o) ? sh[t - o] : 0;
        __syncthreads();
        sh[t] += x;
        __syncthreads();
    }
    int off = (t == 0) ? 0 : sh[t - 1];
    int b = g_part[blockIdx.x] + off;
    int run = 0;
#pragma unroll
    for (int j = 0; j < 4; j++) {
        if (base + j < NN) g_rowptr[base + j] = b + run;
        run += v[j];
    }
    if (blockIdx.x == 0 && t == 0) g_rowptr[NN] = NE;
}

// ---------------- CSR fill (norm computed inline, packed int2) ----------------
__global__ void fill_kernel(const void* __restrict__ ei,
                            const float* __restrict__ ew) {
    int e = blockIdx.x * blockDim.x + threadIdx.x;
    if (e < NE) {
        int s = (int)edge_node(ei, e);
        int d = (int)edge_node(ei, (long long)NE + e);
        float nrm = g_dis[s] * ew[e] * g_dis[d];
        int pos = g_rowptr[d] + atomicAdd(&g_fill[d], 1);
        g_csre[pos] = make_int2(s, __float_as_int(nrm));
    }
}

// ---------------- agg: warp per dst, fp16 gathers, fused self+bias+leaky -----
__global__ void __launch_bounds__(256)
agg_kernel(const float* __restrict__ b) {
    const unsigned int* t16 = (const unsigned int*)g_t16;  // 1 uint = 2 halves
    int warp = (blockIdx.x * 256 + threadIdx.x) >> 5;
    int lane = threadIdx.x & 31;
    if (warp >= NN) return;
    int d = warp;

    float dd = g_dis[d];
    float sc = dd * dd;
    unsigned int su = t16[(size_t)d * 32 + lane];
    float2 sv = __half22float2(*(__half2*)&su);
    float ax = sc * sv.x, ay = sc * sv.y;

    int e = g_rowptr[d], e1 = g_rowptr[d + 1];
    for (; e + 8 <= e1; e += 8) {
        int2 a[8]; unsigned int u[8];
#pragma unroll
        for (int q = 0; q < 8; q++) a[q] = g_csre[e + q];
#pragma unroll
        for (int q = 0; q < 8; q++) u[q] = t16[(size_t)a[q].x * 32 + lane];
#pragma unroll
        for (int q = 0; q < 8; q++) {
            float2 v = __half22float2(*(__half2*)&u[q]);
            float n = __int_as_float(a[q].y);
            ax += n * v.x; ay += n * v.y;
        }
    }
    for (; e < e1; e++) {
        int2 a = g_csre[e];
        unsigned int u = t16[(size_t)a.x * 32 + lane];
        float2 v = __half22float2(*(__half2*)&u);
        float n = __int_as_float(a.y);
        ax += n * v.x; ay += n * v.y;
    }

    float x0 = ax + b[2 * lane], x1 = ay + b[2 * lane + 1];
    g_h[(size_t)d * HID + 2 * lane]     = (x0 > 0.f) ? x0 : NEG * x0;
    g_h[(size_t)d * HID + 2 * lane + 1] = (x1 > 0.f) ? x1 : NEG * x1;
}

// ---------------- output: g_h[NN,64]@[64,40] + b, log_softmax ----------------
__global__ void __launch_bounds__(256)
out_kernel(const float* __restrict__ W, const float* __restrict__ b,
           float* __restrict__ out) {
    __shared__ float Ws[HID * NCLS];
    __shared__ float bs[NCLS];
    int tid = threadIdx.x;
    for (int i = tid; i < HID * NCLS; i += 256) Ws[i] = W[i];
    if (tid < NCLS) bs[tid] = b[tid];
    __syncthreads();

    int warp = tid >> 5, lane = tid & 31;
    long long node = (long long)blockIdx.x * 8 + warp;
    if (node >= NN) return;

    float hv0 = g_h[node * HID + lane];
    float hv1 = g_h[node * HID + 32 + lane];

    float a0 = bs[lane];
    float a1 = (lane < 8) ? bs[32 + lane] : 0.f;
#pragma unroll 8
    for (int k = 0; k < HID; k++) {
        float hk = __shfl_sync(0xffffffffu, (k < 32) ? hv0 : hv1, k & 31);
        a0 += hk * Ws[k * NCLS + lane];
        if (lane < 8) a1 += hk * Ws[k * NCLS + 32 + lane];
    }

    float m = (lane < 8) ? fmaxf(a0, a1) : a0;
#pragma unroll
    for (int o = 16; o > 0; o >>= 1)
        m = fmaxf(m, __shfl_xor_sync(0xffffffffu, m, o));

    float s = expf(a0 - m) + ((lane < 8) ? expf(a1 - m) : 0.f);
#pragma unroll
    for (int o = 16; o > 0; o >>= 1)
        s += __shfl_xor_sync(0xffffffffu, s, o);

    float lse = m + logf(s);
    out[node * NCLS + lane] = a0 - lse;
    if (lane < 8) out[node * NCLS + 32 + lane] = a1 - lse;
}

// ---------------- launch (kernel launches ONLY) ------------------------------
extern "C" void kernel_launch(void* const* d_in, const int* in_sizes, int n_in,
                              void* d_out, int out_size) {
    const float* x       = (const float*)d_in[0];
    const void*  ei      = d_in[1];
    const float* ew      = (const float*)d_in[2];
    const float* W_first = (const float*)d_in[3];
    const float* b_first = (const float*)d_in[4];
    const float* Wc1     = (const float*)d_in[5];
    const float* bc1     = (const float*)d_in[6];
    const float* Wc2     = (const float*)d_in[7];
    const float* bc2     = (const float*)d_in[8];
    const float* W_out   = (const float*)d_in[9];
    const float* b_out   = (const float*)d_in[10];
    float* out = (float*)d_out;

    const int T = 256;
    init_kernel<<<(NN + T - 1) / T, T>>>(ei);                    // 1
    deg_accum_kernel<<<(NE + T - 1) / T, T>>>(ei, ew);           // 2
    scan1_kernel<<<NPART, 256>>>();                              // 3
    fused_first<<<NB64, T>>>(x, W_first, b_first, Wc1);          // 4 <- profiled
    scan2_kernel<<<1, 128>>>();                                  // 5
    scan3_kernel<<<NPART, 256>>>();                              // 6
    fill_kernel<<<(NE + T - 1) / T, T>>>(ei, ew);                // 7

    agg_kernel<<<(NN * 32 + T - 1) / T, T>>>(bc1);               // 8  : g_t16 -> g_h
    gemm64<<<NB64, T>>>(Wc2);                                    // 9  : g_h -> g_t16
    agg_kernel<<<(NN * 32 + T - 1) / T, T>>>(bc2);               // 10 : g_t16 -> g_h
    out_kernel<<<(NN + 7) / 8, T>>>(W_out, b_out, out);          // 11
}

// round 13
// speedup vs baseline: 1.4169x; 1.0121x over previous
#include <cuda_runtime.h>
#include <cuda_bf16.h>
#include <cuda_fp16.h>

#define NN 100000
#define NE 1600000
#define FEATS 128
#define HID 64
#define NCLS 40
#define NEG 0.01f
#define NPART ((NN + 1023) / 1024)
#define NB128 ((NN + 127) / 128)
#define XP32 36   // fp32 Xs row stride (32 cols + pad, 16B-aligned)
#define HP16 68   // fp16 Hs row stride (64 cols + pad, 8B-aligned)

typedef unsigned long long ull;

// ---------------- f32x2 helpers ----------------------------------------------
__device__ __forceinline__ ull pack2(float lo, float hi) {
    ull r;
    asm("mov.b64 %0, {%1, %2};" : "=l"(r) : "f"(lo), "f"(hi));
    return r;
}
__device__ __forceinline__ void ffma2(ull& d, ull a, ull b) {
    asm("fma.rn.f32x2 %0, %1, %2, %3;" : "=l"(d) : "l"(a), "l"(b), "l"(d));
}
__device__ __forceinline__ float2 unpack2(ull v) {
    float2 f;
    asm("mov.b64 {%0, %1}, %2;" : "=f"(f.x), "=f"(f.y) : "l"(v));
    return f;
}

// ---------------- scratch (device globals) -----------------------------------
__device__ float  g_deg[NN];
__device__ float  g_dis[NN];
__device__ float  g_h[(size_t)NN * HID];
__device__ __half g_t16[(size_t)NN * HID];   // fp16 messages for aggregation
__device__ int    g_cnt[NN];
__device__ int    g_fill[NN];
__device__ int    g_rowptr[NN + 1];
__device__ int    g_part[NPART];
__device__ int2   g_csre[NE];     // .x = src, .y = norm bits
__device__ int    g_is64;

// ---------------- edge helpers ------------------------------------------------
__device__ __forceinline__ long long edge_node(const void* ei, long long idx) {
    if (g_is64) return ((const long long*)ei)[idx];
    return (long long)((const int*)ei)[idx];
}

// ---------------- init (+ dtype detection) ------------------------------------
__global__ void init_kernel(const void* ei) {
    int i = blockIdx.x * blockDim.x + threadIdx.x;
    if (i < NN) { g_deg[i] = 1.0f; g_cnt[i] = 0; g_fill[i] = 0; }
    if (blockIdx.x == 0 && threadIdx.x == 0) {
        const int* w = (const int*)ei;
        int zeros = 0;
        for (int j = 1; j < 64; j += 2) zeros += (w[j] == 0);
        g_is64 = (zeros == 32) ? 1 : 0;
    }
}

__global__ void deg_accum_kernel(const void* __restrict__ ei,
                                 const float* __restrict__ ew) {
    int e = blockIdx.x * blockDim.x + threadIdx.x;
    if (e < NE) {
        int d = (int)edge_node(ei, (long long)NE + e);
        atomicAdd(&g_deg[d], ew[e]);
        atomicAdd(&g_cnt[d], 1);
    }
}

// ---------------- fp16 epilogue store ----------------------------------------
__device__ __forceinline__ void store_t16(long long row, int cg, float4 o) {
    __half2 h0 = __floats2half2_rn(o.x, o.y);
    __half2 h1 = __floats2half2_rn(o.z, o.w);
    uint2 u;
    u.x = *(unsigned int*)&h0;
    u.y = *(unsigned int*)&h1;
    ((uint2*)g_t16)[row * 16 + cg] = u;
}

// ---------------- 128x64 k32 f32x2 GEMM step: fp32 X -------------------------
__device__ __forceinline__ void mma32_f32(const float (*Xs)[XP32],
                                          const float* Ws,
                                          int rg, int cg, ull acc[8][2]) {
#pragma unroll
    for (int k4 = 0; k4 < 8; k4++) {
        float4 xj[8];
#pragma unroll
        for (int j = 0; j < 8; j++)
            xj[j] = *(const float4*)&Xs[rg * 8 + j][k4 * 4];
#pragma unroll
        for (int kk = 0; kk < 4; kk++) {
            ulonglong2 wv = *(const ulonglong2*)&Ws[(k4 * 4 + kk) * HID + cg * 4];
#pragma unroll
            for (int j = 0; j < 8; j++) {
                float xc = (kk == 0) ? xj[j].x : (kk == 1) ? xj[j].y
                         : (kk == 2) ? xj[j].z : xj[j].w;
                ull xx = pack2(xc, xc);
                ffma2(acc[j][0], xx, wv.x);
                ffma2(acc[j][1], xx, wv.y);
            }
        }
    }
}

// ---------------- 128x64 k32 f32x2 GEMM step: fp16 H, column base cb ---------
__device__ __forceinline__ void mma32_f16(const __half (*Hs)[HP16], int cb,
                                          const float* Ws,
                                          int rg, int cg, ull acc[8][2]) {
#pragma unroll
    for (int k4 = 0; k4 < 8; k4++) {
        float4 xj[8];
#pragma unroll
        for (int j = 0; j < 8; j++) {
            uint2 hv = *(const uint2*)&Hs[rg * 8 + j][cb + k4 * 4];
            float2 a = __half22float2(*(__half2*)&hv.x);
            float2 b = __half22float2(*(__half2*)&hv.y);
            xj[j] = make_float4(a.x, a.y, b.x, b.y);
        }
#pragma unroll
        for (int kk = 0; kk < 4; kk++) {
            ulonglong2 wv = *(const ulonglong2*)&Ws[(k4 * 4 + kk) * HID + cg * 4];
#pragma unroll
            for (int j = 0; j < 8; j++) {
                float xc = (kk == 0) ? xj[j].x : (kk == 1) ? xj[j].y
                         : (kk == 2) ? xj[j].z : xj[j].w;
                ull xx = pack2(xc, xc);
                ffma2(acc[j][0], xx, wv.x);
                ffma2(acc[j][1], xx, wv.y);
            }
        }
    }
}

// ---------------- fused first chain: x@W1 + b1 -> leaky -> @Wc1 -> g_t16 -----
__global__ void __launch_bounds__(256)
fused_first(const float* __restrict__ x, const float* __restrict__ W1,
            const float* __restrict__ b1, const float* __restrict__ Wc1) {
    __shared__ float  Ws[32 * HID];       // 8 KB (one k-phase of W)
    __shared__ float  Xs[128][XP32];      // 18 KB (one 32-col slice of X)
    __shared__ __half Hs[128][HP16];      // 17 KB (full H tile, fp16)
    int tid = threadIdx.x;
    long long row0 = (long long)blockIdx.x * 128;

    int cg = tid & 15;     // 16 col groups x 4
    int rg = tid >> 4;     // 16 row groups x 8
    ull acc[8][2];
    ull z = pack2(0.f, 0.f);
#pragma unroll
    for (int j = 0; j < 8; j++) { acc[j][0] = z; acc[j][1] = z; }

    // GEMM 1: x @ W1, k phased by 32
#pragma unroll
    for (int kp = 0; kp < 4; kp++) {
        for (int i = tid; i < 128 * 8; i += 256) {
            int r = i >> 3, c4 = i & 7;
            long long rr = row0 + r; if (rr >= NN) rr = NN - 1;
            float4 v = ((const float4*)x)[rr * (FEATS / 4) + kp * 8 + c4];
            *(float4*)&Xs[r][c4 * 4] = v;
        }
        for (int i = tid; i < 32 * HID; i += 256) Ws[i] = W1[kp * 32 * HID + i];
        __syncthreads();
        mma32_f32(Xs, Ws, rg, cg, acc);
        __syncthreads();
    }

    // bias + leaky -> Hs (fp16)
    float4 bb = *(const float4*)&b1[cg * 4];
#pragma unroll
    for (int j = 0; j < 8; j++) {
        float2 p0 = unpack2(acc[j][0]);
        float2 p1 = unpack2(acc[j][1]);
        float v0 = p0.x + bb.x, v1 = p0.y + bb.y;
        float v2 = p1.x + bb.z, v3 = p1.y + bb.w;
        v0 = (v0 > 0.f) ? v0 : NEG * v0;
        v1 = (v1 > 0.f) ? v1 : NEG * v1;
        v2 = (v2 > 0.f) ? v2 : NEG * v2;
        v3 = (v3 > 0.f) ? v3 : NEG * v3;
        __half2 h0 = __floats2half2_rn(v0, v1);
        __half2 h1 = __floats2half2_rn(v2, v3);
        uint2 u; u.x = *(unsigned int*)&h0; u.y = *(unsigned int*)&h1;
        *(uint2*)&Hs[rg * 8 + j][cg * 4] = u;
    }

    // GEMM 2: H @ Wc1, k phased by 32
#pragma unroll
    for (int j = 0; j < 8; j++) { acc[j][0] = z; acc[j][1] = z; }
#pragma unroll
    for (int kp = 0; kp < 2; kp++) {
        __syncthreads();
        for (int i = tid; i < 32 * HID; i += 256) Ws[i] = Wc1[kp * 32 * HID + i];
        __syncthreads();
        mma32_f16(Hs, kp * 32, Ws, rg, cg, acc);
    }

#pragma unroll
    for (int j = 0; j < 8; j++) {
        long long row = row0 + rg * 8 + j;
        if (row < NN) {
            float2 p0 = unpack2(acc[j][0]);
            float2 p1 = unpack2(acc[j][1]);
            store_t16(row, cg, make_float4(p0.x, p0.y, p1.x, p1.y));
        }
    }
}

// ---------------- GEMM: g_h[NN,64] @ W[64,64] -> g_t16, 128x64 tile ----------
__global__ void __launch_bounds__(256)
gemm64(const float* __restrict__ W) {
    __shared__ float Ws[32 * HID];       // 8 KB
    __shared__ float Xs[128][XP32];      // 18 KB
    int tid = threadIdx.x;
    long long row0 = (long long)blockIdx.x * 128;

    int cg = tid & 15;
    int rg = tid >> 4;
    ull acc[8][2];
    ull z = pack2(0.f, 0.f);
#pragma unroll
    for (int j = 0; j < 8; j++) { acc[j][0] = z; acc[j][1] = z; }

#pragma unroll
    for (int kp = 0; kp < 2; kp++) {
        for (int i = tid; i < 128 * 8; i += 256) {
            int r = i >> 3, c4 = i & 7;
            long long rr = row0 + r; if (rr >= NN) rr = NN - 1;
            float4 v = ((const float4*)g_h)[rr * (HID / 4) + kp * 8 + c4];
            *(float4*)&Xs[r][c4 * 4] = v;
        }
        for (int i = tid; i < 32 * HID; i += 256) Ws[i] = W[kp * 32 * HID + i];
        __syncthreads();
        mma32_f32(Xs, Ws, rg, cg, acc);
        __syncthreads();
    }

#pragma unroll
    for (int j = 0; j < 8; j++) {
        long long row = row0 + rg * 8 + j;
        if (row < NN) {
            float2 p0 = unpack2(acc[j][0]);
            float2 p1 = unpack2(acc[j][1]);
            store_t16(row, cg, make_float4(p0.x, p0.y, p1.x, p1.y));
        }
    }
}

// ---------------- scan: block sums (+ dis fused) ------------------------------
__global__ void scan1_kernel() {
    __shared__ int sh[256];
    int t = threadIdx.x;
    int nb = blockIdx.x * 1024;
    for (int i = nb + t; i < nb + 1024 && i < NN; i += 256) {
        float d = g_deg[i];
        g_dis[i] = (d > 0.f) ? rsqrtf(d) : 0.f;
    }
    int base = nb + t * 4;
    int s = 0;
#pragma unroll
    for (int j = 0; j < 4; j++) if (base + j < NN) s += g_cnt[base + j];
    sh[t] = s; __syncthreads();
#pragma unroll
    for (int o = 128; o > 0; o >>= 1) {
        if (t < o) sh[t] += sh[t + o];
        __syncthreads();
    }
    if (t == 0) g_part[blockIdx.x] = sh[0];
}

// scan3: each block computes its own partial base (scan2 folded in)
__global__ void scan3_kernel() {
    __shared__ int parts[128];
    __shared__ int sh[256];
    int t = threadIdx.x;
    int pv = (t < 128) ? ((t < NPART) ? g_part[t] : 0) : 0;
    if (t < 128) parts[t] = pv;
    __syncthreads();
    for (int o = 1; o < 128; o <<= 1) {
        int x = (t >= o && t < 128) ? parts[t - o] : 0;
        __syncthreads();
        if (t < 128) parts[t] += x;
        __syncthreads();
    }
    int blk_base = (blockIdx.x == 0) ? 0 : parts[blockIdx.x - 1];

    int base = blockIdx.x * 1024 + t * 4;
    int v[4]; int s = 0;
#pragma unroll
    for (int j = 0; j < 4; j++) { v[j] = (base + j < NN) ? g_cnt[base + j] : 0; s += v[j]; }
    sh[t] = s; __syncthreads();
    for (int o = 1; o < 256; o <<= 1) {
        int x = (t >= o) ? sh[t - o] : 0;
        __syncthreads();
        sh[t] += x;
        __syncthreads();
    }
    int off = (t == 0) ? 0 : sh[t - 1];
    int b = blk_base + off;
    int run = 0;
#pragma unroll
    for (int j = 0; j < 4; j++) {
        if (base + j < NN) g_rowptr[base + j] = b + run;
        run += v[j];
    }
    if (blockIdx.x == 0 && t == 0) g_rowptr[NN] = NE;
}

// ---------------- CSR fill (norm computed inline, packed int2) ----------------
__global__ void fill_kernel(const void* __restrict__ ei,
                            const float* __restrict__ ew) {
    int e = blockIdx.x * blockDim.x + threadIdx.x;
    if (e < NE) {
        int s = (int)edge_node(ei, e);
        int d = (int)edge_node(ei, (long long)NE + e);
        float nrm = g_dis[s] * ew[e] * g_dis[d];
        int pos = g_rowptr[d] + atomicAdd(&g_fill[d], 1);
        g_csre[pos] = make_int2(s, __float_as_int(nrm));
    }
}

// ---------------- agg: warp per dst, fp16 gathers, fused self+bias+leaky -----
__global__ void __launch_bounds__(256)
agg_kernel(const float* __restrict__ b) {
    const unsigned int* t16 = (const unsigned int*)g_t16;
    int warp = (blockIdx.x * 256 + threadIdx.x) >> 5;
    int lane = threadIdx.x & 31;
    if (warp >= NN) return;
    int d = warp;

    float dd = g_dis[d];
    float sc = dd * dd;
    unsigned int su = t16[(size_t)d * 32 + lane];
    float2 sv = __half22float2(*(__half2*)&su);
    float ax = sc * sv.x, ay = sc * sv.y;

    int e = g_rowptr[d], e1 = g_rowptr[d + 1];
    for (; e + 8 <= e1; e += 8) {
        int2 a[8]; unsigned int u[8];
#pragma unroll
        for (int q = 0; q < 8; q++) a[q] = g_csre[e + q];
#pragma unroll
        for (int q = 0; q < 8; q++) u[q] = t16[(size_t)a[q].x * 32 + lane];
#pragma unroll
        for (int q = 0; q < 8; q++) {
            float2 v = __half22float2(*(__half2*)&u[q]);
            float n = __int_as_float(a[q].y);
            ax += n * v.x; ay += n * v.y;
        }
    }
    for (; e < e1; e++) {
        int2 a = g_csre[e];
        unsigned int u = t16[(size_t)a.x * 32 + lane];
        float2 v = __half22float2(*(__half2*)&u);
        float n = __int_as_float(a.y);
        ax += n * v.x; ay += n * v.y;
    }

    float x0 = ax + b[2 * lane], x1 = ay + b[2 * lane + 1];
    g_h[(size_t)d * HID + 2 * lane]     = (x0 > 0.f) ? x0 : NEG * x0;
    g_h[(size_t)d * HID + 2 * lane + 1] = (x1 > 0.f) ? x1 : NEG * x1;
}

// ---------------- output: g_h[NN,64]@[64,40] + b, log_softmax ----------------
__global__ void __launch_bounds__(256)
out_kernel(const float* __restrict__ W, const float* __restrict__ b,
           float* __restrict__ out) {
    __shared__ float Ws[HID * NCLS];
    __shared__ float bs[NCLS];
    int tid = threadIdx.x;
    for (int i = tid; i < HID * NCLS; i += 256) Ws[i] = W[i];
    if (tid < NCLS) bs[tid] = b[tid];
    __syncthreads();

    int warp = tid >> 5, lane = tid & 31;
    long long node = (long long)blockIdx.x * 8 + warp;
    if (node >= NN) return;

    float hv0 = g_h[node * HID + lane];
    float hv1 = g_h[node * HID + 32 + lane];

    float a0 = bs[lane];
    float a1 = (lane < 8) ? bs[32 + lane] : 0.f;
#pragma unroll 8
    for (int k = 0; k < HID; k++) {
        float hk = __shfl_sync(0xffffffffu, (k < 32) ? hv0 : hv1, k & 31);
        a0 += hk * Ws[k * NCLS + lane];
        if (lane < 8) a1 += hk * Ws[k * NCLS + 32 + lane];
    }

    float m = (lane < 8) ? fmaxf(a0, a1) : a0;
#pragma unroll
    for (int o = 16; o > 0; o >>= 1)
        m = fmaxf(m, __shfl_xor_sync(0xffffffffu, m, o));

    float s = expf(a0 - m) + ((lane < 8) ? expf(a1 - m) : 0.f);
#pragma unroll
    for (int o = 16; o > 0; o >>= 1)
        s += __shfl_xor_sync(0xffffffffu, s, o);

    float lse = m + logf(s);
    out[node * NCLS + lane] = a0 - lse;
    if (lane < 8) out[node * NCLS + 32 + lane] = a1 - lse;
}

// ---------------- launch (kernel launches ONLY) ------------------------------
extern "C" void kernel_launch(void* const* d_in, const int* in_sizes, int n_in,
                              void* d_out, int out_size) {
    const float* x       = (const float*)d_in[0];
    const void*  ei      = d_in[1];
    const float* ew      = (const float*)d_in[2];
    const float* W_first = (const float*)d_in[3];
    const float* b_first = (const float*)d_in[4];
    const float* Wc1     = (const float*)d_in[5];
    const float* bc1     = (const float*)d_in[6];
    const float* Wc2     = (const float*)d_in[7];
    const float* bc2     = (const float*)d_in[8];
    const float* W_out   = (const float*)d_in[9];
    const float* b_out   = (const float*)d_in[10];
    float* out = (float*)d_out;

    const int T = 256;
    init_kernel<<<(NN + T - 1) / T, T>>>(ei);                    // 1
    deg_accum_kernel<<<(NE + T - 1) / T, T>>>(ei, ew);           // 2
    scan1_kernel<<<NPART, 256>>>();                              // 3
    fused_first<<<NB128, T>>>(x, W_first, b_first, Wc1);         // 4 <- profiled
    scan3_kernel<<<NPART, 256>>>();                              // 5
    fill_kernel<<<(NE + T - 1) / T, T>>>(ei, ew);                // 6

    agg_kernel<<<(NN * 32 + T - 1) / T, T>>>(bc1);               // 7  : g_t16 -> g_h
    gemm64<<<NB128, T>>>(Wc2);                                   // 8  : g_h -> g_t16
    agg_kernel<<<(NN * 32 + T - 1) / T, T>>>(bc2);               // 9  : g_t16 -> g_h
    out_kernel<<<(NN + 7) / 8, T>>>(W_out, b_out, out);          // 10
}

// round 14
// speedup vs baseline: 1.6194x; 1.1429x over previous
#include <cuda_runtime.h>
#include <cuda_bf16.h>
#include <cuda_fp16.h>

#define NN 100000
#define NE 1600000
#define FEATS 128
#define HID 64
#define NCLS 40
#define NEG 0.01f
#define NPART ((NN + 1023) / 1024)
#define NB128 ((NN + 127) / 128)
#define HS 72    // fp16 smem row stride (64 + 8 pad) -> conflict-free ldmatrix

// ---------------- scratch (device globals) -----------------------------------
__device__ float  g_deg[NN];
__device__ float  g_dis[NN];
__device__ float  g_h[(size_t)NN * HID];
__device__ __half g_t16[(size_t)NN * HID];   // fp16 messages for aggregation
__device__ int    g_cnt[NN];
__device__ int    g_fill[NN];
__device__ int    g_rowptr[NN + 1];
__device__ int    g_part[NPART];
__device__ int2   g_csre[NE];     // .x = src, .y = norm bits
__device__ int    g_is64;

// ---------------- mma helpers -------------------------------------------------
__device__ __forceinline__ unsigned s2u(const void* p) {
    return (unsigned)__cvta_generic_to_shared(p);
}
__device__ __forceinline__ void ldsm4(unsigned& a0, unsigned& a1,
                                      unsigned& a2, unsigned& a3, unsigned ad) {
    asm volatile("ldmatrix.sync.aligned.m8n8.x4.shared.b16 {%0,%1,%2,%3},[%4];"
                 : "=r"(a0), "=r"(a1), "=r"(a2), "=r"(a3) : "r"(ad));
}
__device__ __forceinline__ void ldsm2t(unsigned& b0, unsigned& b1, unsigned ad) {
    asm volatile("ldmatrix.sync.aligned.m8n8.x2.trans.shared.b16 {%0,%1},[%2];"
                 : "=r"(b0), "=r"(b1) : "r"(ad));
}
__device__ __forceinline__ void mma16816(float* d, unsigned a0, unsigned a1,
                                         unsigned a2, unsigned a3,
                                         unsigned b0, unsigned b1) {
    asm volatile(
        "mma.sync.aligned.m16n8k16.row.col.f32.f16.f16.f32 "
        "{%0,%1,%2,%3},{%4,%5,%6,%7},{%8,%9},{%0,%1,%2,%3};"
        : "+f"(d[0]), "+f"(d[1]), "+f"(d[2]), "+f"(d[3])
        : "r"(a0), "r"(a1), "r"(a2), "r"(a3), "r"(b0), "r"(b1));
}

// ---------------- edge helpers ------------------------------------------------
__device__ __forceinline__ long long edge_node(const void* ei, long long idx) {
    if (g_is64) return ((const long long*)ei)[idx];
    return (long long)((const int*)ei)[idx];
}

// ---------------- init (+ dtype detection) ------------------------------------
__global__ void init_kernel(const void* ei) {
    int i = blockIdx.x * blockDim.x + threadIdx.x;
    if (i < NN) { g_deg[i] = 1.0f; g_cnt[i] = 0; g_fill[i] = 0; }
    if (blockIdx.x == 0 && threadIdx.x == 0) {
        const int* w = (const int*)ei;
        int zeros = 0;
        for (int j = 1; j < 64; j += 2) zeros += (w[j] == 0);
        g_is64 = (zeros == 32) ? 1 : 0;
    }
}

__global__ void deg_accum_kernel(const void* __restrict__ ei,
                                 const float* __restrict__ ew) {
    int e = blockIdx.x * blockDim.x + threadIdx.x;
    if (e < NE) {
        int d = (int)edge_node(ei, (long long)NE + e);
        atomicAdd(&g_deg[d], ew[e]);
        atomicAdd(&g_cnt[d], 1);
    }
}

// ---------------- warp-tile GEMM pieces ---------------------------------------
// A fragment: 16x16 at (warp row base wr, k base kb) from fp16 smem tile
__device__ __forceinline__ void load_a(const __half (*Xs)[HS], int wr, int kb,
                                       int lane, unsigned& a0, unsigned& a1,
                                       unsigned& a2, unsigned& a3) {
    int lr = lane & 7, sel = lane >> 3;
    int r = wr + lr + (sel & 1) * 8;
    int c = kb + (sel >> 1) * 8;
    ldsm4(a0, a1, a2, a3, s2u(&Xs[r][c]));
}
// B fragment: k16 x n8 at (k base kb, n base nb) from fp16 W smem [k][n]
__device__ __forceinline__ void load_b(const __half (*Wsh)[HS], int kb, int nb,
                                       int lane, unsigned& b0, unsigned& b1) {
    int kr = kb + (lane & 7) + ((lane >> 3) & 1) * 8;
    ldsm2t(b0, b1, s2u(&Wsh[kr][nb]));
}

// ---------------- fused first chain: x@W1 + b1 -> leaky -> @Wc1 -> g_t16 -----
__global__ void __launch_bounds__(256)
fused_first(const float* __restrict__ x, const float* __restrict__ W1,
            const float* __restrict__ b1, const float* __restrict__ Wc1) {
    __shared__ __half Xs[128][HS];    // 18.4 KB
    __shared__ __half Wsh[64][HS];    // 9.2 KB
    __shared__ float  bsh[HID];
    int tid = threadIdx.x, lane = tid & 31, w = tid >> 5;
    long long row0 = (long long)blockIdx.x * 128;
    if (tid < HID) bsh[tid] = b1[tid];

    float d[8][4];
#pragma unroll
    for (int nt = 0; nt < 8; nt++)
#pragma unroll
        for (int q = 0; q < 4; q++) d[nt][q] = 0.f;

    int wr = w * 16;

    // GEMM 1: x @ W1, K phased by 64
#pragma unroll
    for (int ph = 0; ph < 2; ph++) {
        for (int i = tid; i < 128 * 16; i += 256) {
            int r = i >> 4, c4 = i & 15;
            long long rr = row0 + r; if (rr >= NN) rr = NN - 1;
            float4 v = ((const float4*)x)[rr * (FEATS / 4) + ph * 16 + c4];
            __half2 h0 = __floats2half2_rn(v.x, v.y);
            __half2 h1 = __floats2half2_rn(v.z, v.w);
            uint2 u; u.x = *(unsigned*)&h0; u.y = *(unsigned*)&h1;
            *(uint2*)&Xs[r][c4 * 4] = u;
        }
        for (int i = tid; i < 64 * HID; i += 256) {
            int k = i >> 6, n = i & 63;
            Wsh[k][n] = __float2half(W1[(ph * 64 + k) * HID + n]);
        }
        __syncthreads();
#pragma unroll
        for (int ks = 0; ks < 4; ks++) {
            unsigned a0, a1, a2, a3;
            load_a(Xs, wr, ks * 16, lane, a0, a1, a2, a3);
#pragma unroll
            for (int nt = 0; nt < 8; nt++) {
                unsigned b0, b1r;
                load_b(Wsh, ks * 16, nt * 8, lane, b0, b1r);
                mma16816(d[nt], a0, a1, a2, a3, b0, b1r);
            }
        }
        __syncthreads();
    }

    // epilogue 1: bias + leaky, H (fp16) back into Xs
    int rA = wr + (lane >> 2);
#pragma unroll
    for (int nt = 0; nt < 8; nt++) {
        int c0 = nt * 8 + 2 * (lane & 3);
        float bx = bsh[c0], by = bsh[c0 + 1];
        float v0 = d[nt][0] + bx, v1 = d[nt][1] + by;
        float v2 = d[nt][2] + bx, v3 = d[nt][3] + by;
        v0 = (v0 > 0.f) ? v0 : NEG * v0;
        v1 = (v1 > 0.f) ? v1 : NEG * v1;
        v2 = (v2 > 0.f) ? v2 : NEG * v2;
        v3 = (v3 > 0.f) ? v3 : NEG * v3;
        *(__half2*)&Xs[rA][c0]     = __floats2half2_rn(v0, v1);
        *(__half2*)&Xs[rA + 8][c0] = __floats2half2_rn(v2, v3);
    }
    for (int i = tid; i < HID * HID; i += 256) {
        int k = i >> 6, n = i & 63;
        Wsh[k][n] = __float2half(Wc1[k * HID + n]);
    }
    __syncthreads();

    // GEMM 2: H @ Wc1 (K = 64)
#pragma unroll
    for (int nt = 0; nt < 8; nt++)
#pragma unroll
        for (int q = 0; q < 4; q++) d[nt][q] = 0.f;
#pragma unroll
    for (int ks = 0; ks < 4; ks++) {
        unsigned a0, a1, a2, a3;
        load_a(Xs, wr, ks * 16, lane, a0, a1, a2, a3);
#pragma unroll
        for (int nt = 0; nt < 8; nt++) {
            unsigned b0, b1r;
            load_b(Wsh, ks * 16, nt * 8, lane, b0, b1r);
            mma16816(d[nt], a0, a1, a2, a3, b0, b1r);
        }
    }

    long long r1 = row0 + rA, r2 = row0 + rA + 8;
#pragma unroll
    for (int nt = 0; nt < 8; nt++) {
        int c0 = nt * 8 + 2 * (lane & 3);
        if (r1 < NN) *(__half2*)&g_t16[r1 * HID + c0] = __floats2half2_rn(d[nt][0], d[nt][1]);
        if (r2 < NN) *(__half2*)&g_t16[r2 * HID + c0] = __floats2half2_rn(d[nt][2], d[nt][3]);
    }
}

// ---------------- GEMM: g_h[NN,64] @ W[64,64] -> g_t16 (HMMA) ----------------
__global__ void __launch_bounds__(256)
gemm64(const float* __restrict__ W) {
    __shared__ __half Xs[128][HS];
    __shared__ __half Wsh[64][HS];
    int tid = threadIdx.x, lane = tid & 31, w = tid >> 5;
    long long row0 = (long long)blockIdx.x * 128;

    for (int i = tid; i < 128 * 16; i += 256) {
        int r = i >> 4, c4 = i & 15;
        long long rr = row0 + r; if (rr >= NN) rr = NN - 1;
        float4 v = ((const float4*)g_h)[rr * (HID / 4) + c4];
        __half2 h0 = __floats2half2_rn(v.x, v.y);
        __half2 h1 = __floats2half2_rn(v.z, v.w);
        uint2 u; u.x = *(unsigned*)&h0; u.y = *(unsigned*)&h1;
        *(uint2*)&Xs[r][c4 * 4] = u;
    }
    for (int i = tid; i < HID * HID; i += 256) {
        int k = i >> 6, n = i & 63;
        Wsh[k][n] = __float2half(W[k * HID + n]);
    }
    __syncthreads();

    int wr = w * 16;
    float d[8][4];
#pragma unroll
    for (int nt = 0; nt < 8; nt++)
#pragma unroll
        for (int q = 0; q < 4; q++) d[nt][q] = 0.f;
#pragma unroll
    for (int ks = 0; ks < 4; ks++) {
        unsigned a0, a1, a2, a3;
        load_a(Xs, wr, ks * 16, lane, a0, a1, a2, a3);
#pragma unroll
        for (int nt = 0; nt < 8; nt++) {
            unsigned b0, b1r;
            load_b(Wsh, ks * 16, nt * 8, lane, b0, b1r);
            mma16816(d[nt], a0, a1, a2, a3, b0, b1r);
        }
    }

    int rA = wr + (lane >> 2);
    long long r1 = row0 + rA, r2 = row0 + rA + 8;
#pragma unroll
    for (int nt = 0; nt < 8; nt++) {
        int c0 = nt * 8 + 2 * (lane & 3);
        if (r1 < NN) *(__half2*)&g_t16[r1 * HID + c0] = __floats2half2_rn(d[nt][0], d[nt][1]);
        if (r2 < NN) *(__half2*)&g_t16[r2 * HID + c0] = __floats2half2_rn(d[nt][2], d[nt][3]);
    }
}

// ---------------- scan: block sums (+ dis fused) ------------------------------
__global__ void scan1_kernel() {
    __shared__ int sh[256];
    int t = threadIdx.x;
    int nb = blockIdx.x * 1024;
    for (int i = nb + t; i < nb + 1024 && i < NN; i += 256) {
        float d = g_deg[i];
        g_dis[i] = (d > 0.f) ? rsqrtf(d) : 0.f;
    }
    int base = nb + t * 4;
    int s = 0;
#pragma unroll
    for (int j = 0; j < 4; j++) if (base + j < NN) s += g_cnt[base + j];
    sh[t] = s; __syncthreads();
#pragma unroll
    for (int o = 128; o > 0; o >>= 1) {
        if (t < o) sh[t] += sh[t + o];
        __syncthreads();
    }
    if (t == 0) g_part[blockIdx.x] = sh[0];
}

// scan3: each block computes its own partial base
__global__ void scan3_kernel() {
    __shared__ int parts[128];
    __shared__ int sh[256];
    int t = threadIdx.x;
    int pv = (t < 128) ? ((t < NPART) ? g_part[t] : 0) : 0;
    if (t < 128) parts[t] = pv;
    __syncthreads();
    for (int o = 1; o < 128; o <<= 1) {
        int x = (t >= o && t < 128) ? parts[t - o] : 0;
        __syncthreads();
        if (t < 128) parts[t] += x;
        __syncthreads();
    }
    int blk_base = (blockIdx.x == 0) ? 0 : parts[blockIdx.x - 1];

    int base = blockIdx.x * 1024 + t * 4;
    int v[4]; int s = 0;
#pragma unroll
    for (int j = 0; j < 4; j++) { v[j] = (base + j < NN) ? g_cnt[base + j] : 0; s += v[j]; }
    sh[t] = s; __syncthreads();
    for (int o = 1; o < 256; o <<= 1) {
        int x = (t >= o) ? sh[t - o] : 0;
        __syncthreads();
        sh[t] += x;
        __syncthreads();
    }
    int off = (t == 0) ? 0 : sh[t - 1];
    int b = blk_base + off;
    int run = 0;
#pragma unroll
    for (int j = 0; j < 4; j++) {
        if (base + j < NN) g_rowptr[base + j] = b + run;
        run += v[j];
    }
    if (blockIdx.x == 0 && t == 0) g_rowptr[NN] = NE;
}

// ---------------- CSR fill (norm computed inline, packed int2) ----------------
__global__ void fill_kernel(const void* __restrict__ ei,
                            const float* __restrict__ ew) {
    int e = blockIdx.x * blockDim.x + threadIdx.x;
    if (e < NE) {
        int s = (int)edge_node(ei, e);
        int d = (int)edge_node(ei, (long long)NE + e);
        float nrm = g_dis[s] * ew[e] * g_dis[d];
        int pos = g_rowptr[d] + atomicAdd(&g_fill[d], 1);
        g_csre[pos] = make_int2(s, __float_as_int(nrm));
    }
}

// ---------------- agg: warp per dst, fp16 gathers, fused self+bias+leaky -----
__global__ void __launch_bounds__(256)
agg_kernel(const float* __restrict__ b) {
    const unsigned int* t16 = (const unsigned int*)g_t16;
    int warp = (blockIdx.x * 256 + threadIdx.x) >> 5;
    int lane = threadIdx.x & 31;
    if (warp >= NN) return;
    int d = warp;

    float dd = g_dis[d];
    float sc = dd * dd;
    unsigned int su = t16[(size_t)d * 32 + lane];
    float2 sv = __half22float2(*(__half2*)&su);
    float ax = sc * sv.x, ay = sc * sv.y;

    int e = g_rowptr[d], e1 = g_rowptr[d + 1];
    for (; e + 8 <= e1; e += 8) {
        int2 a[8]; unsigned int u[8];
#pragma unroll
        for (int q = 0; q < 8; q++) a[q] = g_csre[e + q];
#pragma unroll
        for (int q = 0; q < 8; q++) u[q] = t16[(size_t)a[q].x * 32 + lane];
#pragma unroll
        for (int q = 0; q < 8; q++) {
            float2 v = __half22float2(*(__half2*)&u[q]);
            float n = __int_as_float(a[q].y);
            ax += n * v.x; ay += n * v.y;
        }
    }
    for (; e < e1; e++) {
        int2 a = g_csre[e];
        unsigned int u = t16[(size_t)a.x * 32 + lane];
        float2 v = __half22float2(*(__half2*)&u);
        float n = __int_as_float(a.y);
        ax += n * v.x; ay += n * v.y;
    }

    float x0 = ax + b[2 * lane], x1 = ay + b[2 * lane + 1];
    g_h[(size_t)d * HID + 2 * lane]     = (x0 > 0.f) ? x0 : NEG * x0;
    g_h[(size_t)d * HID + 2 * lane + 1] = (x1 > 0.f) ? x1 : NEG * x1;
}

// ---------------- output: g_h[NN,64]@[64,40] + b, log_softmax ----------------
__global__ void __launch_bounds__(256)
out_kernel(const float* __restrict__ W, const float* __restrict__ b,
           float* __restrict__ out) {
    __shared__ float Ws[HID * NCLS];
    __shared__ float bs[NCLS];
    int tid = threadIdx.x;
    for (int i = tid; i < HID * NCLS; i += 256) Ws[i] = W[i];
    if (tid < NCLS) bs[tid] = b[tid];
    __syncthreads();

    int warp = tid >> 5, lane = tid & 31;
    long long node = (long long)blockIdx.x * 8 + warp;
    if (node >= NN) return;

    float hv0 = g_h[node * HID + lane];
    float hv1 = g_h[node * HID + 32 + lane];

    float a0 = bs[lane];
    float a1 = (lane < 8) ? bs[32 + lane] : 0.f;
#pragma unroll 8
    for (int k = 0; k < HID; k++) {
        float hk = __shfl_sync(0xffffffffu, (k < 32) ? hv0 : hv1, k & 31);
        a0 += hk * Ws[k * NCLS + lane];
        if (lane < 8) a1 += hk * Ws[k * NCLS + 32 + lane];
    }

    float m = (lane < 8) ? fmaxf(a0, a1) : a0;
#pragma unroll
    for (int o = 16; o > 0; o >>= 1)
        m = fmaxf(m, __shfl_xor_sync(0xffffffffu, m, o));

    float s = expf(a0 - m) + ((lane < 8) ? expf(a1 - m) : 0.f);
#pragma unroll
    for (int o = 16; o > 0; o >>= 1)
        s += __shfl_xor_sync(0xffffffffu, s, o);

    float lse = m + logf(s);
    out[node * NCLS + lane] = a0 - lse;
    if (lane < 8) out[node * NCLS + 32 + lane] = a1 - lse;
}

// ---------------- launch (kernel launches ONLY) ------------------------------
extern "C" void kernel_launch(void* const* d_in, const int* in_sizes, int n_in,
                              void* d_out, int out_size) {
    const float* x       = (const float*)d_in[0];
    const void*  ei      = d_in[1];
    const float* ew      = (const float*)d_in[2];
    const float* W_first = (const float*)d_in[3];
    const float* b_first = (const float*)d_in[4];
    const float* Wc1     = (const float*)d_in[5];
    const float* bc1     = (const float*)d_in[6];
    const float* Wc2     = (const float*)d_in[7];
    const float* bc2     = (const float*)d_in[8];
    const float* W_out   = (const float*)d_in[9];
    const float* b_out   = (const float*)d_in[10];
    float* out = (float*)d_out;

    const int T = 256;
    init_kernel<<<(NN + T - 1) / T, T>>>(ei);                    // 1
    deg_accum_kernel<<<(NE + T - 1) / T, T>>>(ei, ew);           // 2
    scan1_kernel<<<NPART, 256>>>();                              // 3
    fused_first<<<NB128, T>>>(x, W_first, b_first, Wc1);         // 4 <- profiled
    scan3_kernel<<<NPART, 256>>>();                              // 5
    fill_kernel<<<(NE + T - 1) / T, T>>>(ei, ew);                // 6

    agg_kernel<<<(NN * 32 + T - 1) / T, T>>>(bc1);               // 7  : g_t16 -> g_h
    gemm64<<<NB128, T>>>(Wc2);                                   // 8  : g_h -> g_t16
    agg_kernel<<<(NN * 32 + T - 1) / T, T>>>(bc2);               // 9  : g_t16 -> g_h
    out_kernel<<<(NN + 7) / 8, T>>>(W_out, b_out, out);          // 10
}

// round 15
// speedup vs baseline: 1.7126x; 1.0576x over previous
#include <cuda_runtime.h>
#include <cuda_bf16.h>
#include <cuda_fp16.h>

#define NN 100000
#define NE 1600000
#define FEATS 128
#define HID 64
#define NCLS 40
#define NEG 0.01f
#define NPART ((NN + 1023) / 1024)
#define NB128 ((NN + 127) / 128)
#define HS 72     // fp16 W/H smem row stride
#define XS16 40   // fp16 X smem row stride (32 cols + pad)
#define DEG_ONE (1ull << 20)
#define CNT_ONE (1ull << 40)

typedef unsigned long long ull;

// ---------------- scratch (device globals) -----------------------------------
__device__ ull    g_dc[NN];                  // cnt in [40:64), deg*2^20 in [0:40)
__device__ float  g_dis[NN];
__device__ float  g_h[(size_t)NN * HID];
__device__ __half g_t16[(size_t)NN * HID];
__device__ int    g_rowptr[NN + 1];
__device__ int    g_part[NPART];
__device__ int2   g_csre[NE];                // .x = src, .y = norm bits
__device__ int    g_is64;

// ---------------- mma / async helpers -----------------------------------------
__device__ __forceinline__ unsigned s2u(const void* p) {
    return (unsigned)__cvta_generic_to_shared(p);
}
__device__ __forceinline__ void ldsm4(unsigned& a0, unsigned& a1,
                                      unsigned& a2, unsigned& a3, unsigned ad) {
    asm volatile("ldmatrix.sync.aligned.m8n8.x4.shared.b16 {%0,%1,%2,%3},[%4];"
                 : "=r"(a0), "=r"(a1), "=r"(a2), "=r"(a3) : "r"(ad));
}
__device__ __forceinline__ void ldsm2t(unsigned& b0, unsigned& b1, unsigned ad) {
    asm volatile("ldmatrix.sync.aligned.m8n8.x2.trans.shared.b16 {%0,%1},[%2];"
                 : "=r"(b0), "=r"(b1) : "r"(ad));
}
__device__ __forceinline__ void mma16816(float* d, unsigned a0, unsigned a1,
                                         unsigned a2, unsigned a3,
                                         unsigned b0, unsigned b1) {
    asm volatile(
        "mma.sync.aligned.m16n8k16.row.col.f32.f16.f16.f32 "
        "{%0,%1,%2,%3},{%4,%5,%6,%7},{%8,%9},{%0,%1,%2,%3};"
        : "+f"(d[0]), "+f"(d[1]), "+f"(d[2]), "+f"(d[3])
        : "r"(a0), "r"(a1), "r"(a2), "r"(a3), "r"(b0), "r"(b1));
}
__device__ __forceinline__ void cp_async16(void* smem, const void* gmem) {
    asm volatile("cp.async.cg.shared.global [%0], [%1], 16;"
                 :: "r"(s2u(smem)), "l"(gmem));
}
#define CP_COMMIT() asm volatile("cp.async.commit_group;")
#define CP_WAIT1()  asm volatile("cp.async.wait_group 1;")
#define CP_WAIT0()  asm volatile("cp.async.wait_group 0;")

// A fragment 16x16 from fp16 smem with row stride ldm
__device__ __forceinline__ void load_a_s(const __half* base, int ldm, int wr,
                                         int kb, int lane, unsigned& a0,
                                         unsigned& a1, unsigned& a2, unsigned& a3) {
    int lr = lane & 7, sel = lane >> 3;
    int r = wr + lr + (sel & 1) * 8;
    int c = kb + (sel >> 1) * 8;
    ldsm4(a0, a1, a2, a3, s2u(base + r * ldm + c));
}
// B fragment k16 x n8 from fp16 W smem [k][n] with row stride ldm
__device__ __forceinline__ void load_b_s(const __half* base, int ldm, int kb,
                                         int nb, int lane, unsigned& b0, unsigned& b1) {
    int kr = kb + (lane & 7) + ((lane >> 3) & 1) * 8;
    ldsm2t(b0, b1, s2u(base + kr * ldm + nb));
}

// ---------------- edge helpers ------------------------------------------------
__device__ __forceinline__ long long edge_node(const void* ei, long long idx) {
    if (g_is64) return ((const long long*)ei)[idx];
    return (long long)((const int*)ei)[idx];
}

// ---------------- init (+ dtype detection) ------------------------------------
__global__ void init_kernel(const void* ei) {
    int i = blockIdx.x * blockDim.x + threadIdx.x;
    if (i < NN) g_dc[i] = DEG_ONE;   // deg = 1.0 (self loop), cnt = 0
    if (blockIdx.x == 0 && threadIdx.x == 0) {
        const int* w = (const int*)ei;
        int zeros = 0;
        for (int j = 1; j < 64; j += 2) zeros += (w[j] == 0);
        g_is64 = (zeros == 32) ? 1 : 0;
    }
}

// one packed 64-bit atomic per edge: count + fixed-point weight sum
__global__ void deg_accum_kernel(const void* __restrict__ ei,
                                 const float* __restrict__ ew) {
    int e = blockIdx.x * blockDim.x + threadIdx.x;
    if (e < NE) {
        int d = (int)edge_node(ei, (long long)NE + e);
        ull inc = CNT_ONE + (ull)__float2uint_rn(ew[e] * 1048576.0f);
        atomicAdd(&g_dc[d], inc);
    }
}

// ---------------- fused first chain: x@W1 + b1 -> leaky -> @Wc1 -> g_t16 -----
// cp.async double-buffered staging; 4 k-phases of 32
__global__ void __launch_bounds__(256)
fused_first(const float* __restrict__ x, const float* __restrict__ W1,
            const float* __restrict__ b1, const float* __restrict__ Wc1) {
    __shared__ __align__(16) char pool[2 * 128 * 32 * 4];   // 32 KB staging / H tile
    __shared__ __half Xs[128][XS16];                        // 10 KB
    __shared__ __half Wsh[32][HS];                          // 4.6 KB
    __shared__ float  bsh[HID];
    float (*St)[128][32] = reinterpret_cast<float(*)[128][32]>(pool);
    __half (*Hs)[HS]     = reinterpret_cast<__half(*)[HS]>(pool);

    int tid = threadIdx.x, lane = tid & 31, w = tid >> 5;
    long long row0 = (long long)blockIdx.x * 128;
    if (tid < HID) bsh[tid] = b1[tid];
    int wr = w * 16;

    float d[8][4];
#pragma unroll
    for (int nt = 0; nt < 8; nt++)
#pragma unroll
        for (int q = 0; q < 4; q++) d[nt][q] = 0.f;

    // issue phase 0 stage
    {
        for (int i = tid; i < 128 * 8; i += 256) {
            int r = i >> 3, c4 = i & 7;
            long long rr = row0 + r; if (rr >= NN) rr = NN - 1;
            cp_async16(&St[0][r][c4 * 4], &((const float4*)x)[rr * 32 + c4]);
        }
        CP_COMMIT();
    }

#pragma unroll
    for (int p = 0; p < 4; p++) {
        if (p < 3) {
            for (int i = tid; i < 128 * 8; i += 256) {
                int r = i >> 3, c4 = i & 7;
                long long rr = row0 + r; if (rr >= NN) rr = NN - 1;
                cp_async16(&St[(p + 1) & 1][r][c4 * 4],
                           &((const float4*)x)[rr * 32 + (p + 1) * 8 + c4]);
            }
            CP_COMMIT();
            CP_WAIT1();
        } else {
            CP_WAIT0();
        }
        __syncthreads();
        // convert staged fp32 -> Xs fp16; load W slice
        for (int i = tid; i < 128 * 16; i += 256) {
            int r = i >> 4, c2 = i & 15;
            float2 v = *(const float2*)&St[p & 1][r][c2 * 2];
            *(__half2*)&Xs[r][c2 * 2] = __floats2half2_rn(v.x, v.y);
        }
        for (int i = tid; i < 32 * HID; i += 256) {
            int k = i >> 6, n = i & 63;
            Wsh[k][n] = __float2half(W1[(p * 32 + k) * HID + n]);
        }
        __syncthreads();
#pragma unroll
        for (int ks = 0; ks < 2; ks++) {
            unsigned a0, a1, a2, a3;
            load_a_s(&Xs[0][0], XS16, wr, ks * 16, lane, a0, a1, a2, a3);
#pragma unroll
            for (int nt = 0; nt < 8; nt++) {
                unsigned b0, b1r;
                load_b_s(&Wsh[0][0], HS, ks * 16, nt * 8, lane, b0, b1r);
                mma16816(d[nt], a0, a1, a2, a3, b0, b1r);
            }
        }
        __syncthreads();
    }

    // epilogue 1: bias + leaky -> Hs (fp16, aliases staging pool)
    int rA = wr + (lane >> 2);
#pragma unroll
    for (int nt = 0; nt < 8; nt++) {
        int c0 = nt * 8 + 2 * (lane & 3);
        float bx = bsh[c0], by = bsh[c0 + 1];
        float v0 = d[nt][0] + bx, v1 = d[nt][1] + by;
        float v2 = d[nt][2] + bx, v3 = d[nt][3] + by;
        v0 = (v0 > 0.f) ? v0 : NEG * v0;
        v1 = (v1 > 0.f) ? v1 : NEG * v1;
        v2 = (v2 > 0.f) ? v2 : NEG * v2;
        v3 = (v3 > 0.f) ? v3 : NEG * v3;
        *(__half2*)&Hs[rA][c0]     = __floats2half2_rn(v0, v1);
        *(__half2*)&Hs[rA + 8][c0] = __floats2half2_rn(v2, v3);
    }

    // GEMM 2: H @ Wc1, 2 k-phases of 32
#pragma unroll
    for (int nt = 0; nt < 8; nt++)
#pragma unroll
        for (int q = 0; q < 4; q++) d[nt][q] = 0.f;
#pragma unroll
    for (int kp = 0; kp < 2; kp++) {
        __syncthreads();
        for (int i = tid; i < 32 * HID; i += 256) {
            int k = i >> 6, n = i & 63;
            Wsh[k][n] = __float2half(Wc1[(kp * 32 + k) * HID + n]);
        }
        __syncthreads();
#pragma unroll
        for (int ks = 0; ks < 2; ks++) {
            unsigned a0, a1, a2, a3;
            load_a_s(&Hs[0][0], HS, wr, kp * 32 + ks * 16, lane, a0, a1, a2, a3);
#pragma unroll
            for (int nt = 0; nt < 8; nt++) {
                unsigned b0, b1r;
                load_b_s(&Wsh[0][0], HS, ks * 16, nt * 8, lane, b0, b1r);
                mma16816(d[nt], a0, a1, a2, a3, b0, b1r);
            }
        }
    }

    long long r1 = row0 + rA, r2 = row0 + rA + 8;
#pragma unroll
    for (int nt = 0; nt < 8; nt++) {
        int c0 = nt * 8 + 2 * (lane & 3);
        if (r1 < NN) *(__half2*)&g_t16[r1 * HID + c0] = __floats2half2_rn(d[nt][0], d[nt][1]);
        if (r2 < NN) *(__half2*)&g_t16[r2 * HID + c0] = __floats2half2_rn(d[nt][2], d[nt][3]);
    }
}

// ---------------- GEMM: g_h[NN,64] @ W[64,64] -> g_t16 (HMMA) ----------------
__global__ void __launch_bounds__(256)
gemm64(const float* __restrict__ W) {
    __shared__ __half Xs[128][HS];
    __shared__ __half Wsh[64][HS];
    int tid = threadIdx.x, lane = tid & 31, w = tid >> 5;
    long long row0 = (long long)blockIdx.x * 128;

    for (int i = tid; i < 128 * 16; i += 256) {
        int r = i >> 4, c4 = i & 15;
        long long rr = row0 + r; if (rr >= NN) rr = NN - 1;
        float4 v = ((const float4*)g_h)[rr * (HID / 4) + c4];
        __half2 h0 = __floats2half2_rn(v.x, v.y);
        __half2 h1 = __floats2half2_rn(v.z, v.w);
        uint2 u; u.x = *(unsigned*)&h0; u.y = *(unsigned*)&h1;
        *(uint2*)&Xs[r][c4 * 4] = u;
    }
    for (int i = tid; i < HID * HID; i += 256) {
        int k = i >> 6, n = i & 63;
        Wsh[k][n] = __float2half(W[k * HID + n]);
    }
    __syncthreads();

    int wr = w * 16;
    float d[8][4];
#pragma unroll
    for (int nt = 0; nt < 8; nt++)
#pragma unroll
        for (int q = 0; q < 4; q++) d[nt][q] = 0.f;
#pragma unroll
    for (int ks = 0; ks < 4; ks++) {
        unsigned a0, a1, a2, a3;
        load_a_s(&Xs[0][0], HS, wr, ks * 16, lane, a0, a1, a2, a3);
#pragma unroll
        for (int nt = 0; nt < 8; nt++) {
            unsigned b0, b1r;
            load_b_s(&Wsh[0][0], HS, ks * 16, nt * 8, lane, b0, b1r);
            mma16816(d[nt], a0, a1, a2, a3, b0, b1r);
        }
    }

    int rA = wr + (lane >> 2);
    long long r1 = row0 + rA, r2 = row0 + rA + 8;
#pragma unroll
    for (int nt = 0; nt < 8; nt++) {
        int c0 = nt * 8 + 2 * (lane & 3);
        if (r1 < NN) *(__half2*)&g_t16[r1 * HID + c0] = __floats2half2_rn(d[nt][0], d[nt][1]);
        if (r2 < NN) *(__half2*)&g_t16[r2 * HID + c0] = __floats2half2_rn(d[nt][2], d[nt][3]);
    }
}

// ---------------- scan: block sums (+ dis fused, packed read) -----------------
__global__ void scan1_kernel() {
    __shared__ int sh[256];
    int t = threadIdx.x;
    int nb = blockIdx.x * 1024;
    for (int i = nb + t; i < nb + 1024 && i < NN; i += 256) {
        ull v = g_dc[i];
        float deg = (float)(v & (CNT_ONE - 1)) * (1.0f / 1048576.0f);
        g_dis[i] = rsqrtf(deg);   // deg >= 1 always
    }
    int base = nb + t * 4;
    int s = 0;
#pragma unroll
    for (int j = 0; j < 4; j++)
        if (base + j < NN) s += (int)(g_dc[base + j] >> 40);
    sh[t] = s; __syncthreads();
#pragma unroll
    for (int o = 128; o > 0; o >>= 1) {
        if (t < o) sh[t] += sh[t + o];
        __syncthreads();
    }
    if (t == 0) g_part[blockIdx.x] = sh[0];
}

// scan3: each block computes its own partial base
__global__ void scan3_kernel() {
    __shared__ int parts[128];
    __shared__ int sh[256];
    int t = threadIdx.x;
    int pv = (t < 128) ? ((t < NPART) ? g_part[t] : 0) : 0;
    if (t < 128) parts[t] = pv;
    __syncthreads();
    for (int o = 1; o < 128; o <<= 1) {
        int x = (t >= o && t < 128) ? parts[t - o] : 0;
        __syncthreads();
        if (t < 128) parts[t] += x;
        __syncthreads();
    }
    int blk_base = (blockIdx.x == 0) ? 0 : parts[blockIdx.x - 1];

    int base = blockIdx.x * 1024 + t * 4;
    int v[4]; int s = 0;
#pragma unroll
    for (int j = 0; j < 4; j++) {
        v[j] = (base + j < NN) ? (int)(g_dc[base + j] >> 40) : 0;
        s += v[j];
    }
    sh[t] = s; __syncthreads();
    for (int o = 1; o < 256; o <<= 1) {
        int x = (t >= o) ? sh[t - o] : 0;
        __syncthreads();
        sh[t] += x;
        __syncthreads();
    }
    int off = (t == 0) ? 0 : sh[t - 1];
    int b = blk_base + off;
    int run = 0;
#pragma unroll
    for (int j = 0; j < 4; j++) {
        if (base + j < NN) g_rowptr[base + j] = b + run;
        run += v[j];
    }
    if (blockIdx.x == 0 && t == 0) g_rowptr[NN] = NE;
}

// ---------------- CSR fill: slot via countdown on packed count ----------------
__global__ void fill_kernel(const void* __restrict__ ei,
                            const float* __restrict__ ew) {
    int e = blockIdx.x * blockDim.x + threadIdx.x;
    if (e < NE) {
        int s = (int)edge_node(ei, e);
        int d = (int)edge_node(ei, (long long)NE + e);
        float nrm = g_dis[s] * ew[e] * g_dis[d];
        ull old = atomicAdd(&g_dc[d], (ull)(0ull - CNT_ONE));
        int idx = (int)(old >> 40) - 1;
        g_csre[g_rowptr[d] + idx] = make_int2(s, __float_as_int(nrm));
    }
}

// ---------------- agg: warp per dst, fp16 gathers, fused self+bias+leaky -----
__global__ void __launch_bounds__(256)
agg_kernel(const float* __restrict__ b) {
    const unsigned int* t16 = (const unsigned int*)g_t16;
    int warp = (blockIdx.x * 256 + threadIdx.x) >> 5;
    int lane = threadIdx.x & 31;
    if (warp >= NN) return;
    int d = warp;

    float dd = g_dis[d];
    float sc = dd * dd;
    unsigned int su = t16[(size_t)d * 32 + lane];
    float2 sv = __half22float2(*(__half2*)&su);
    float ax = sc * sv.x, ay = sc * sv.y;

    int e = g_rowptr[d], e1 = g_rowptr[d + 1];
    for (; e + 8 <= e1; e += 8) {
        int2 a[8]; unsigned int u[8];
#pragma unroll
        for (int q = 0; q < 8; q++) a[q] = g_csre[e + q];
#pragma unroll
        for (int q = 0; q < 8; q++) u[q] = t16[(size_t)a[q].x * 32 + lane];
#pragma unroll
        for (int q = 0; q < 8; q++) {
            float2 v = __half22float2(*(__half2*)&u[q]);
            float n = __int_as_float(a[q].y);
            ax += n * v.x; ay += n * v.y;
        }
    }
    for (; e < e1; e++) {
        int2 a = g_csre[e];
        unsigned int u = t16[(size_t)a.x * 32 + lane];
        float2 v = __half22float2(*(__half2*)&u);
        float n = __int_as_float(a.y);
        ax += n * v.x; ay += n * v.y;
    }

    float x0 = ax + b[2 * lane], x1 = ay + b[2 * lane + 1];
    g_h[(size_t)d * HID + 2 * lane]     = (x0 > 0.f) ? x0 : NEG * x0;
    g_h[(size_t)d * HID + 2 * lane + 1] = (x1 > 0.f) ? x1 : NEG * x1;
}

// ---------------- output: g_h[NN,64]@[64,40] + b, log_softmax ----------------
__global__ void __launch_bounds__(256)
out_kernel(const float* __restrict__ W, const float* __restrict__ b,
           float* __restrict__ out) {
    __shared__ float Ws[HID * NCLS];
    __shared__ float bs[NCLS];
    int tid = threadIdx.x;
    for (int i = tid; i < HID * NCLS; i += 256) Ws[i] = W[i];
    if (tid < NCLS) bs[tid] = b[tid];
    __syncthreads();

    int warp = tid >> 5, lane = tid & 31;
    long long node = (long long)blockIdx.x * 8 + warp;
    if (node >= NN) return;

    float hv0 = g_h[node * HID + lane];
    float hv1 = g_h[node * HID + 32 + lane];

    float a0 = bs[lane];
    float a1 = (lane < 8) ? bs[32 + lane] : 0.f;
#pragma unroll 8
    for (int k = 0; k < HID; k++) {
        float hk = __shfl_sync(0xffffffffu, (k < 32) ? hv0 : hv1, k & 31);
        a0 += hk * Ws[k * NCLS + lane];
        if (lane < 8) a1 += hk * Ws[k * NCLS + 32 + lane];
    }

    float m = (lane < 8) ? fmaxf(a0, a1) : a0;
#pragma unroll
    for (int o = 16; o > 0; o >>= 1)
        m = fmaxf(m, __shfl_xor_sync(0xffffffffu, m, o));

    float s = expf(a0 - m) + ((lane < 8) ? expf(a1 - m) : 0.f);
#pragma unroll
    for (int o = 16; o > 0; o >>= 1)
        s += __shfl_xor_sync(0xffffffffu, s, o);

    float lse = m + logf(s);
    out[node * NCLS + lane] = a0 - lse;
    if (lane < 8) out[node * NCLS + 32 + lane] = a1 - lse;
}

// ---------------- launch (kernel launches ONLY) ------------------------------
extern "C" void kernel_launch(void* const* d_in, const int* in_sizes, int n_in,
                              void* d_out, int out_size) {
    const float* x       = (const float*)d_in[0];
    const void*  ei      = d_in[1];
    const float* ew      = (const float*)d_in[2];
    const float* W_first = (const float*)d_in[3];
    const float* b_first = (const float*)d_in[4];
    const float* Wc1     = (const float*)d_in[5];
    const float* bc1     = (const float*)d_in[6];
    const float* Wc2     = (const float*)d_in[7];
    const float* bc2     = (const float*)d_in[8];
    const float* W_out   = (const float*)d_in[9];
    const float* b_out   = (const float*)d_in[10];
    float* out = (float*)d_out;

    const int T = 256;
    init_kernel<<<(NN + T - 1) / T, T>>>(ei);                    // 1
    deg_accum_kernel<<<(NE + T - 1) / T, T>>>(ei, ew);           // 2
    scan1_kernel<<<NPART, 256>>>();                              // 3
    fused_first<<<NB128, T>>>(x, W_first, b_first, Wc1);         // 4 <- profiled
    scan3_kernel<<<NPART, 256>>>();                              // 5
    fill_kernel<<<(NE + T - 1) / T, T>>>(ei, ew);                // 6

    agg_kernel<<<(NN * 32 + T - 1) / T, T>>>(bc1);               // 7  : g_t16 -> g_h
    gemm64<<<NB128, T>>>(Wc2);                                   // 8  : g_h -> g_t16
    agg_kernel<<<(NN * 32 + T - 1) / T, T>>>(bc2);               // 9  : g_t16 -> g_h
    out_kernel<<<(NN + 7) / 8, T>>>(W_out, b_out, out);          // 10
}

// round 16
// speedup vs baseline: 2.0176x; 1.1781x over previous
#include <cuda_runtime.h>
#include <cuda_bf16.h>
#include <cuda_fp16.h>

#define NN 100000
#define NE 1600000
#define FEATS 128
#define HID 64
#define NCLS 40
#define NEG 0.01f
#define NPART ((NN + 1023) / 1024)
#define NB128 ((NN + 127) / 128)
#define HS 72     // fp16 W/H smem row stride
#define XS16 40   // fp16 X smem row stride (32 cols + pad)
#define DEG_ONE (1ull << 20)
#define CNT_ONE (1ull << 40)

typedef unsigned long long ull;

// ---------------- scratch (device globals) -----------------------------------
__device__ ull    g_dc[NN];                  // cnt in [40:64), deg*2^20 in [0:40)
__device__ float  g_dis[NN];
__device__ __half g_t16[(size_t)NN * HID];   // layer-1 messages
__device__ __half g_t16b[(size_t)NN * HID];  // layer-2 messages
__device__ int    g_rowptr[NN + 1];
__device__ int    g_part[NPART];
__device__ int2   g_csre[NE];                // .x = src, .y = norm bits
__device__ int    g_is64;

// ---------------- mma / async helpers -----------------------------------------
__device__ __forceinline__ unsigned s2u(const void* p) {
    return (unsigned)__cvta_generic_to_shared(p);
}
__device__ __forceinline__ void ldsm4(unsigned& a0, unsigned& a1,
                                      unsigned& a2, unsigned& a3, unsigned ad) {
    asm volatile("ldmatrix.sync.aligned.m8n8.x4.shared.b16 {%0,%1,%2,%3},[%4];"
                 : "=r"(a0), "=r"(a1), "=r"(a2), "=r"(a3) : "r"(ad));
}
__device__ __forceinline__ void ldsm2t(unsigned& b0, unsigned& b1, unsigned ad) {
    asm volatile("ldmatrix.sync.aligned.m8n8.x2.trans.shared.b16 {%0,%1},[%2];"
                 : "=r"(b0), "=r"(b1) : "r"(ad));
}
__device__ __forceinline__ void mma16816(float* d, unsigned a0, unsigned a1,
                                         unsigned a2, unsigned a3,
                                         unsigned b0, unsigned b1) {
    asm volatile(
        "mma.sync.aligned.m16n8k16.row.col.f32.f16.f16.f32 "
        "{%0,%1,%2,%3},{%4,%5,%6,%7},{%8,%9},{%0,%1,%2,%3};"
        : "+f"(d[0]), "+f"(d[1]), "+f"(d[2]), "+f"(d[3])
        : "r"(a0), "r"(a1), "r"(a2), "r"(a3), "r"(b0), "r"(b1));
}
__device__ __forceinline__ void cp_async16(void* smem, const void* gmem) {
    asm volatile("cp.async.cg.shared.global [%0], [%1], 16;"
                 :: "r"(s2u(smem)), "l"(gmem));
}
#define CP_COMMIT() asm volatile("cp.async.commit_group;")
#define CP_WAIT1()  asm volatile("cp.async.wait_group 1;")
#define CP_WAIT0()  asm volatile("cp.async.wait_group 0;")

__device__ __forceinline__ void load_a_s(const __half* base, int ldm, int wr,
                                         int kb, int lane, unsigned& a0,
                                         unsigned& a1, unsigned& a2, unsigned& a3) {
    int lr = lane & 7, sel = lane >> 3;
    int r = wr + lr + (sel & 1) * 8;
    int c = kb + (sel >> 1) * 8;
    ldsm4(a0, a1, a2, a3, s2u(base + r * ldm + c));
}
__device__ __forceinline__ void load_b_s(const __half* base, int ldm, int kb,
                                         int nb, int lane, unsigned& b0, unsigned& b1) {
    int kr = kb + (lane & 7) + ((lane >> 3) & 1) * 8;
    ldsm2t(b0, b1, s2u(base + kr * ldm + nb));
}

// ---------------- edge helpers ------------------------------------------------
__device__ __forceinline__ long long edge_node(const void* ei, long long idx) {
    if (g_is64) return ((const long long*)ei)[idx];
    return (long long)((const int*)ei)[idx];
}

// ---------------- init (+ dtype detection) ------------------------------------
__global__ void init_kernel(const void* ei) {
    int i = blockIdx.x * blockDim.x + threadIdx.x;
    if (i < NN) g_dc[i] = DEG_ONE;   // deg = 1.0 (self loop), cnt = 0
    if (blockIdx.x == 0 && threadIdx.x == 0) {
        const int* w = (const int*)ei;
        int zeros = 0;
        for (int j = 1; j < 64; j += 2) zeros += (w[j] == 0);
        g_is64 = (zeros == 32) ? 1 : 0;
    }
}

__global__ void deg_accum_kernel(const void* __restrict__ ei,
                                 const float* __restrict__ ew) {
    int e = blockIdx.x * blockDim.x + threadIdx.x;
    if (e < NE) {
        int d = (int)edge_node(ei, (long long)NE + e);
        ull inc = CNT_ONE + (ull)__float2uint_rn(ew[e] * 1048576.0f);
        atomicAdd(&g_dc[d], inc);
    }
}

// ---------------- fused first chain: x@W1 + b1 -> leaky -> @Wc1 -> g_t16 -----
__global__ void __launch_bounds__(256)
fused_first(const float* __restrict__ x, const float* __restrict__ W1,
            const float* __restrict__ b1, const float* __restrict__ Wc1) {
    __shared__ __align__(16) char pool[2 * 128 * 32 * 4];   // 32 KB staging / H tile
    __shared__ __half Xs[128][XS16];                        // 10 KB
    __shared__ __half Wsh[32][HS];                          // 4.6 KB
    __shared__ float  bsh[HID];
    float (*St)[128][32] = reinterpret_cast<float(*)[128][32]>(pool);
    __half (*Hs)[HS]     = reinterpret_cast<__half(*)[HS]>(pool);

    int tid = threadIdx.x, lane = tid & 31, w = tid >> 5;
    long long row0 = (long long)blockIdx.x * 128;
    if (tid < HID) bsh[tid] = b1[tid];
    int wr = w * 16;

    float d[8][4];
#pragma unroll
    for (int nt = 0; nt < 8; nt++)
#pragma unroll
        for (int q = 0; q < 4; q++) d[nt][q] = 0.f;

    {
        for (int i = tid; i < 128 * 8; i += 256) {
            int r = i >> 3, c4 = i & 7;
            long long rr = row0 + r; if (rr >= NN) rr = NN - 1;
            cp_async16(&St[0][r][c4 * 4], &((const float4*)x)[rr * 32 + c4]);
        }
        CP_COMMIT();
    }

#pragma unroll
    for (int p = 0; p < 4; p++) {
        if (p < 3) {
            for (int i = tid; i < 128 * 8; i += 256) {
                int r = i >> 3, c4 = i & 7;
                long long rr = row0 + r; if (rr >= NN) rr = NN - 1;
                cp_async16(&St[(p + 1) & 1][r][c4 * 4],
                           &((const float4*)x)[rr * 32 + (p + 1) * 8 + c4]);
            }
            CP_COMMIT();
            CP_WAIT1();
        } else {
            CP_WAIT0();
        }
        __syncthreads();
        for (int i = tid; i < 128 * 16; i += 256) {
            int r = i >> 4, c2 = i & 15;
            float2 v = *(const float2*)&St[p & 1][r][c2 * 2];
            *(__half2*)&Xs[r][c2 * 2] = __floats2half2_rn(v.x, v.y);
        }
        for (int i = tid; i < 32 * HID; i += 256) {
            int k = i >> 6, n = i & 63;
            Wsh[k][n] = __float2half(W1[(p * 32 + k) * HID + n]);
        }
        __syncthreads();
#pragma unroll
        for (int ks = 0; ks < 2; ks++) {
            unsigned a0, a1, a2, a3;
            load_a_s(&Xs[0][0], XS16, wr, ks * 16, lane, a0, a1, a2, a3);
#pragma unroll
            for (int nt = 0; nt < 8; nt++) {
                unsigned b0, b1r;
                load_b_s(&Wsh[0][0], HS, ks * 16, nt * 8, lane, b0, b1r);
                mma16816(d[nt], a0, a1, a2, a3, b0, b1r);
            }
        }
        __syncthreads();
    }

    int rA = wr + (lane >> 2);
#pragma unroll
    for (int nt = 0; nt < 8; nt++) {
        int c0 = nt * 8 + 2 * (lane & 3);
        float bx = bsh[c0], by = bsh[c0 + 1];
        float v0 = d[nt][0] + bx, v1 = d[nt][1] + by;
        float v2 = d[nt][2] + bx, v3 = d[nt][3] + by;
        v0 = (v0 > 0.f) ? v0 : NEG * v0;
        v1 = (v1 > 0.f) ? v1 : NEG * v1;
        v2 = (v2 > 0.f) ? v2 : NEG * v2;
        v3 = (v3 > 0.f) ? v3 : NEG * v3;
        *(__half2*)&Hs[rA][c0]     = __floats2half2_rn(v0, v1);
        *(__half2*)&Hs[rA + 8][c0] = __floats2half2_rn(v2, v3);
    }

#pragma unroll
    for (int nt = 0; nt < 8; nt++)
#pragma unroll
        for (int q = 0; q < 4; q++) d[nt][q] = 0.f;
#pragma unroll
    for (int kp = 0; kp < 2; kp++) {
        __syncthreads();
        for (int i = tid; i < 32 * HID; i += 256) {
            int k = i >> 6, n = i & 63;
            Wsh[k][n] = __float2half(Wc1[(kp * 32 + k) * HID + n]);
        }
        __syncthreads();
#pragma unroll
        for (int ks = 0; ks < 2; ks++) {
            unsigned a0, a1, a2, a3;
            load_a_s(&Hs[0][0], HS, wr, kp * 32 + ks * 16, lane, a0, a1, a2, a3);
#pragma unroll
            for (int nt = 0; nt < 8; nt++) {
                unsigned b0, b1r;
                load_b_s(&Wsh[0][0], HS, ks * 16, nt * 8, lane, b0, b1r);
                mma16816(d[nt], a0, a1, a2, a3, b0, b1r);
            }
        }
    }

    long long r1 = row0 + rA, r2 = row0 + rA + 8;
#pragma unroll
    for (int nt = 0; nt < 8; nt++) {
        int c0 = nt * 8 + 2 * (lane & 3);
        if (r1 < NN) *(__half2*)&g_t16[r1 * HID + c0] = __floats2half2_rn(d[nt][0], d[nt][1]);
        if (r2 < NN) *(__half2*)&g_t16[r2 * HID + c0] = __floats2half2_rn(d[nt][2], d[nt][3]);
    }
}

// ---------------- scan: block sums (+ dis fused, packed read) -----------------
__global__ void scan1_kernel() {
    __shared__ int sh[256];
    int t = threadIdx.x;
    int nb = blockIdx.x * 1024;
    for (int i = nb + t; i < nb + 1024 && i < NN; i += 256) {
        ull v = g_dc[i];
        float deg = (float)(v & (CNT_ONE - 1)) * (1.0f / 1048576.0f);
        g_dis[i] = rsqrtf(deg);
    }
    int base = nb + t * 4;
    int s = 0;
#pragma unroll
    for (int j = 0; j < 4; j++)
        if (base + j < NN) s += (int)(g_dc[base + j] >> 40);
    sh[t] = s; __syncthreads();
#pragma unroll
    for (int o = 128; o > 0; o >>= 1) {
        if (t < o) sh[t] += sh[t + o];
        __syncthreads();
    }
    if (t == 0) g_part[blockIdx.x] = sh[0];
}

__global__ void scan3_kernel() {
    __shared__ int parts[128];
    __shared__ int sh[256];
    int t = threadIdx.x;
    int pv = (t < 128) ? ((t < NPART) ? g_part[t] : 0) : 0;
    if (t < 128) parts[t] = pv;
    __syncthreads();
    for (int o = 1; o < 128; o <<= 1) {
        int x = (t >= o && t < 128) ? parts[t - o] : 0;
        __syncthreads();
        if (t < 128) parts[t] += x;
        __syncthreads();
    }
    int blk_base = (blockIdx.x == 0) ? 0 : parts[blockIdx.x - 1];

    int base = blockIdx.x * 1024 + t * 4;
    int v[4]; int s = 0;
#pragma unroll
    for (int j = 0; j < 4; j++) {
        v[j] = (base + j < NN) ? (int)(g_dc[base + j] >> 40) : 0;
        s += v[j];
    }
    sh[t] = s; __syncthreads();
    for (int o = 1; o < 256; o <<= 1) {
        int x = (t >= o) ? sh[t - o] : 0;
        __syncthreads();
        sh[t] += x;
        __syncthreads();
    }
    int off = (t == 0) ? 0 : sh[t - 1];
    int b = blk_base + off;
    int run = 0;
#pragma unroll
    for (int j = 0; j < 4; j++) {
        if (base + j < NN) g_rowptr[base + j] = b + run;
        run += v[j];
    }
    if (blockIdx.x == 0 && t == 0) g_rowptr[NN] = NE;
}

// ---------------- CSR fill: slot via countdown on packed count ----------------
__global__ void fill_kernel(const void* __restrict__ ei,
                            const float* __restrict__ ew) {
    int e = blockIdx.x * blockDim.x + threadIdx.x;
    if (e < NE) {
        int s = (int)edge_node(ei, e);
        int d = (int)edge_node(ei, (long long)NE + e);
        float nrm = g_dis[s] * ew[e] * g_dis[d];
        ull old = atomicAdd(&g_dc[d], (ull)(0ull - CNT_ONE));
        int idx = (int)(old >> 40) - 1;
        g_csre[g_rowptr[d] + idx] = make_int2(s, __float_as_int(nrm));
    }
}

// ---------------- seg reduce for dst d: lane holds cols 2l, 2l+1 -------------
__device__ __forceinline__ float2 seg_reduce(const unsigned* __restrict__ t16,
                                             int d, int lane) {
    float dd = g_dis[d];
    float sc = dd * dd;
    unsigned su = t16[(size_t)d * 32 + lane];
    float2 sv = __half22float2(*(__half2*)&su);
    float ax = sc * sv.x, ay = sc * sv.y;

    int e = g_rowptr[d], e1 = g_rowptr[d + 1];
    for (; e + 8 <= e1; e += 8) {
        int2 a[8]; unsigned u[8];
#pragma unroll
        for (int q = 0; q < 8; q++) a[q] = g_csre[e + q];
#pragma unroll
        for (int q = 0; q < 8; q++) u[q] = t16[(size_t)a[q].x * 32 + lane];
#pragma unroll
        for (int q = 0; q < 8; q++) {
            float2 v = __half22float2(*(__half2*)&u[q]);
            float n = __int_as_float(a[q].y);
            ax += n * v.x; ay += n * v.y;
        }
    }
    for (; e < e1; e++) {
        int2 a = g_csre[e];
        unsigned u = t16[(size_t)a.x * 32 + lane];
        float2 v = __half22float2(*(__half2*)&u);
        float n = __int_as_float(a.y);
        ax += n * v.x; ay += n * v.y;
    }
    return make_float2(ax, ay);
}

// ---------------- agg_mm: segreduce(g_t16) + b -> leaky -> @Wc2 -> g_t16b ----
__global__ void __launch_bounds__(256)
agg_mm_kernel(const float* __restrict__ bc, const float* __restrict__ W2) {
    __shared__ __half Hs[128][HS];     // 18.4 KB
    __shared__ __half Wsh[64][HS];     // 9.2 KB
    __shared__ float  bs[HID];
    int tid = threadIdx.x, lane = tid & 31, w = tid >> 5;
    long long row0 = (long long)blockIdx.x * 128;

    if (tid < HID) bs[tid] = bc[tid];
    for (int i = tid; i < 64 * HID; i += 256) {
        int k = i >> 6, n = i & 63;
        Wsh[k][n] = __float2half(W2[k * HID + n]);
    }
    __syncthreads();

    const unsigned* t16 = (const unsigned*)g_t16;
    float b0v = bs[2 * lane], b1v = bs[2 * lane + 1];
#pragma unroll 1
    for (int i = 0; i < 16; i++) {
        int lr = w * 16 + i;
        long long d = row0 + lr;
        if (d < NN) {
            float2 a = seg_reduce(t16, (int)d, lane);
            float x0 = a.x + b0v, x1 = a.y + b1v;
            x0 = (x0 > 0.f) ? x0 : NEG * x0;
            x1 = (x1 > 0.f) ? x1 : NEG * x1;
            *(__half2*)&Hs[lr][2 * lane] = __floats2half2_rn(x0, x1);
        } else {
            *(__half2*)&Hs[lr][2 * lane] = __floats2half2_rn(0.f, 0.f);
        }
    }
    __syncthreads();

    int wr = w * 16;
    float d[8][4];
#pragma unroll
    for (int nt = 0; nt < 8; nt++)
#pragma unroll
        for (int q = 0; q < 4; q++) d[nt][q] = 0.f;
#pragma unroll
    for (int ks = 0; ks < 4; ks++) {
        unsigned a0, a1, a2, a3;
        load_a_s(&Hs[0][0], HS, wr, ks * 16, lane, a0, a1, a2, a3);
#pragma unroll
        for (int nt = 0; nt < 8; nt++) {
            unsigned b0, b1r;
            load_b_s(&Wsh[0][0], HS, ks * 16, nt * 8, lane, b0, b1r);
            mma16816(d[nt], a0, a1, a2, a3, b0, b1r);
        }
    }

    int rA = wr + (lane >> 2);
    long long r1 = row0 + rA, r2 = row0 + rA + 8;
#pragma unroll
    for (int nt = 0; nt < 8; nt++) {
        int c0 = nt * 8 + 2 * (lane & 3);
        if (r1 < NN) *(__half2*)&g_t16b[r1 * HID + c0] = __floats2half2_rn(d[nt][0], d[nt][1]);
        if (r2 < NN) *(__half2*)&g_t16b[r2 * HID + c0] = __floats2half2_rn(d[nt][2], d[nt][3]);
    }
}

// ---- agg_out: segreduce(g_t16b) + b -> leaky -> @W_out + bo -> log_softmax --
__global__ void __launch_bounds__(256)
agg_out_kernel(const float* __restrict__ bc, const float* __restrict__ Wo,
               const float* __restrict__ bo, float* __restrict__ out) {
    __shared__ __half Hs[128][HS];     // 18.4 KB
    __shared__ __half Wsh[64][HS];     // 9.2 KB
    __shared__ float  bs[HID];
    __shared__ float  bos[NCLS];
    int tid = threadIdx.x, lane = tid & 31, w = tid >> 5;
    long long row0 = (long long)blockIdx.x * 128;

    if (tid < HID) bs[tid] = bc[tid];
    if (tid < NCLS) bos[tid] = bo[tid];
    for (int i = tid; i < HID * NCLS; i += 256) {
        int k = i / NCLS, n = i % NCLS;
        Wsh[k][n] = __float2half(Wo[k * NCLS + n]);
    }
    __syncthreads();

    const unsigned* t16 = (const unsigned*)g_t16b;
    float b0v = bs[2 * lane], b1v = bs[2 * lane + 1];
#pragma unroll 1
    for (int i = 0; i < 16; i++) {
        int lr = w * 16 + i;
        long long d = row0 + lr;
        if (d < NN) {
            float2 a = seg_reduce(t16, (int)d, lane);
            float x0 = a.x + b0v, x1 = a.y + b1v;
            x0 = (x0 > 0.f) ? x0 : NEG * x0;
            x1 = (x1 > 0.f) ? x1 : NEG * x1;
            *(__half2*)&Hs[lr][2 * lane] = __floats2half2_rn(x0, x1);
        } else {
            *(__half2*)&Hs[lr][2 * lane] = __floats2half2_rn(0.f, 0.f);
        }
    }
    __syncthreads();

    // logits: Hs(128x64) @ Wo(64x40) -> 5 n-tiles
    int wr = w * 16;
    float d[5][4];
#pragma unroll
    for (int nt = 0; nt < 5; nt++)
#pragma unroll
        for (int q = 0; q < 4; q++) d[nt][q] = 0.f;
#pragma unroll
    for (int ks = 0; ks < 4; ks++) {
        unsigned a0, a1, a2, a3;
        load_a_s(&Hs[0][0], HS, wr, ks * 16, lane, a0, a1, a2, a3);
#pragma unroll
        for (int nt = 0; nt < 5; nt++) {
            unsigned b0, b1r;
            load_b_s(&Wsh[0][0], HS, ks * 16, nt * 8, lane, b0, b1r);
            mma16816(d[nt], a0, a1, a2, a3, b0, b1r);
        }
    }

    // bias + row-wise log_softmax in fragment registers.
    // Row rA owns d[nt][0..1] across the quad (lanes g*4..g*4+3); row rA+8 owns d[nt][2..3].
#pragma unroll
    for (int nt = 0; nt < 5; nt++) {
        int c0 = nt * 8 + 2 * (lane & 3);
        d[nt][0] += bos[c0]; d[nt][1] += bos[c0 + 1];
        d[nt][2] += bos[c0]; d[nt][3] += bos[c0 + 1];
    }

    float m1 = -1e30f, m2 = -1e30f;
#pragma unroll
    for (int nt = 0; nt < 5; nt++) {
        m1 = fmaxf(m1, fmaxf(d[nt][0], d[nt][1]));
        m2 = fmaxf(m2, fmaxf(d[nt][2], d[nt][3]));
    }
#pragma unroll
    for (int o = 1; o <= 2; o <<= 1) {
        m1 = fmaxf(m1, __shfl_xor_sync(0xffffffffu, m1, o));
        m2 = fmaxf(m2, __shfl_xor_sync(0xffffffffu, m2, o));
    }
    float s1 = 0.f, s2 = 0.f;
#pragma unroll
    for (int nt = 0; nt < 5; nt++) {
        s1 += expf(d[nt][0] - m1) + expf(d[nt][1] - m1);
        s2 += expf(d[nt][2] - m2) + expf(d[nt][3] - m2);
    }
#pragma unroll
    for (int o = 1; o <= 2; o <<= 1) {
        s1 += __shfl_xor_sync(0xffffffffu, s1, o);
        s2 += __shfl_xor_sync(0xffffffffu, s2, o);
    }
    float lse1 = m1 + logf(s1), lse2 = m2 + logf(s2);

    int rA = wr + (lane >> 2);
    long long r1 = row0 + rA, r2 = row0 + rA + 8;
#pragma unroll
    for (int nt = 0; nt < 5; nt++) {
        int c0 = nt * 8 + 2 * (lane & 3);
        if (r1 < NN) {
            out[r1 * NCLS + c0]     = d[nt][0] - lse1;
            out[r1 * NCLS + c0 + 1] = d[nt][1] - lse1;
        }
        if (r2 < NN) {
            out[r2 * NCLS + c0]     = d[nt][2] - lse2;
            out[r2 * NCLS + c0 + 1] = d[nt][3] - lse2;
        }
    }
}

// ---------------- launch (kernel launches ONLY) ------------------------------
extern "C" void kernel_launch(void* const* d_in, const int* in_sizes, int n_in,
                              void* d_out, int out_size) {
    const float* x       = (const float*)d_in[0];
    const void*  ei      = d_in[1];
    const float* ew      = (const float*)d_in[2];
    const float* W_first = (const float*)d_in[3];
    const float* b_first = (const float*)d_in[4];
    const float* Wc1     = (const float*)d_in[5];
    const float* bc1     = (const float*)d_in[6];
    const float* Wc2     = (const float*)d_in[7];
    const float* bc2     = (const float*)d_in[8];
    const float* W_out   = (const float*)d_in[9];
    const float* b_out   = (const float*)d_in[10];
    float* out = (float*)d_out;

    const int T = 256;
    init_kernel<<<(NN + T - 1) / T, T>>>(ei);                    // 1
    deg_accum_kernel<<<(NE + T - 1) / T, T>>>(ei, ew);           // 2
    scan1_kernel<<<NPART, 256>>>();                              // 3
    fused_first<<<NB128, T>>>(x, W_first, b_first, Wc1);         // 4 <- profiled
    scan3_kernel<<<NPART, 256>>>();                              // 5
    fill_kernel<<<(NE + T - 1) / T, T>>>(ei, ew);                // 6

    agg_mm_kernel<<<NB128, T>>>(bc1, Wc2);                       // 7 : g_t16 -> g_t16b
    agg_out_kernel<<<NB128, T>>>(bc2, W_out, b_out, out);        // 8 : g_t16b -> out
}

// round 17
// speedup vs baseline: 2.0524x; 1.0172x over previous
#include <cuda_runtime.h>
#include <cuda_bf16.h>
#include <cuda_fp16.h>

#define NN 100000
#define NE 1600000
#define FEATS 128
#define HID 64
#define NCLS 40
#define NEG 0.01f
#define NPART ((NN + 1023) / 1024)
#define NB128 ((NN + 127) / 128)
#define NDEG 1184
#define HS 72     // fp16 W/H smem row stride
#define XS16 40   // fp16 X smem row stride (32 cols + pad)
#define DEG_ONE (1ull << 20)
#define CNT_ONE (1ull << 40)

typedef unsigned long long ull;

// ---------------- scratch (device globals) -----------------------------------
__device__ ull    g_dc[NN];                  // cnt in [40:64), deg*2^20 in [0:40)
__device__ float  g_dis[NN];
__device__ __half g_t16[(size_t)NN * HID];   // layer-1 messages
__device__ __half g_t16b[(size_t)NN * HID];  // layer-2 messages
__device__ int    g_rowptr[NN + 1];
__device__ int    g_part[NPART];
__device__ int2   g_csre[NE];                // .x = src, .y = norm bits
__device__ int    g_is64;

// ---------------- mma / async helpers -----------------------------------------
__device__ __forceinline__ unsigned s2u(const void* p) {
    return (unsigned)__cvta_generic_to_shared(p);
}
__device__ __forceinline__ void ldsm4(unsigned& a0, unsigned& a1,
                                      unsigned& a2, unsigned& a3, unsigned ad) {
    asm volatile("ldmatrix.sync.aligned.m8n8.x4.shared.b16 {%0,%1,%2,%3},[%4];"
                 : "=r"(a0), "=r"(a1), "=r"(a2), "=r"(a3) : "r"(ad));
}
__device__ __forceinline__ void ldsm2t(unsigned& b0, unsigned& b1, unsigned ad) {
    asm volatile("ldmatrix.sync.aligned.m8n8.x2.trans.shared.b16 {%0,%1},[%2];"
                 : "=r"(b0), "=r"(b1) : "r"(ad));
}
__device__ __forceinline__ void mma16816(float* d, unsigned a0, unsigned a1,
                                         unsigned a2, unsigned a3,
                                         unsigned b0, unsigned b1) {
    asm volatile(
        "mma.sync.aligned.m16n8k16.row.col.f32.f16.f16.f32 "
        "{%0,%1,%2,%3},{%4,%5,%6,%7},{%8,%9},{%0,%1,%2,%3};"
        : "+f"(d[0]), "+f"(d[1]), "+f"(d[2]), "+f"(d[3])
        : "r"(a0), "r"(a1), "r"(a2), "r"(a3), "r"(b0), "r"(b1));
}
__device__ __forceinline__ void cp_async16(void* smem, const void* gmem) {
    asm volatile("cp.async.cg.shared.global [%0], [%1], 16;"
                 :: "r"(s2u(smem)), "l"(gmem));
}
#define CP_COMMIT() asm volatile("cp.async.commit_group;")
#define CP_WAIT1()  asm volatile("cp.async.wait_group 1;")
#define CP_WAIT0()  asm volatile("cp.async.wait_group 0;")

__device__ __forceinline__ void load_a_s(const __half* base, int ldm, int wr,
                                         int kb, int lane, unsigned& a0,
                                         unsigned& a1, unsigned& a2, unsigned& a3) {
    int lr = lane & 7, sel = lane >> 3;
    int r = wr + lr + (sel & 1) * 8;
    int c = kb + (sel >> 1) * 8;
    ldsm4(a0, a1, a2, a3, s2u(base + r * ldm + c));
}
__device__ __forceinline__ void load_b_s(const __half* base, int ldm, int kb,
                                         int nb, int lane, unsigned& b0, unsigned& b1) {
    int kr = kb + (lane & 7) + ((lane >> 3) & 1) * 8;
    ldsm2t(b0, b1, s2u(base + kr * ldm + nb));
}

// ---------------- edge helpers ------------------------------------------------
__device__ __forceinline__ long long edge_node(const void* ei, long long idx) {
    if (g_is64) return ((const long long*)ei)[idx];
    return (long long)((const int*)ei)[idx];
}

// ---------------- init (+ dtype detection) ------------------------------------
__global__ void init_kernel(const void* ei) {
    int i = blockIdx.x * blockDim.x + threadIdx.x;
    if (i < NN) g_dc[i] = DEG_ONE;   // deg = 1.0 (self loop), cnt = 0
    if (blockIdx.x == 0 && threadIdx.x == 0) {
        const int* w = (const int*)ei;
        int zeros = 0;
        for (int j = 1; j < 64; j += 2) zeros += (w[j] == 0);
        g_is64 = (zeros == 32) ? 1 : 0;
    }
}

// ---------------- mega: deg blocks [0,NDEG) || fused_first blocks ------------
// deg path: grid-stride packed 64-bit histogram atomics.
// GEMM path: x@W1 + b1 -> leaky -> @Wc1 -> g_t16 (cp.async pipelined).
__global__ void __launch_bounds__(256)
mega_kernel(const float* __restrict__ x, const float* __restrict__ W1,
            const float* __restrict__ b1, const float* __restrict__ Wc1,
            const void* __restrict__ ei, const float* __restrict__ ew) {
    __shared__ __align__(16) char pool[2 * 128 * 32 * 4];   // 32 KB staging / H tile
    __shared__ __half Xs[128][XS16];                        // 10 KB
    __shared__ __half Wsh[32][HS];                          // 4.6 KB
    __shared__ float  bsh[HID];

    if (blockIdx.x < NDEG) {
        int t0 = blockIdx.x * 256 + threadIdx.x;
        for (int e = t0; e < NE; e += NDEG * 256) {
            int d = (int)edge_node(ei, (long long)NE + e);
            ull inc = CNT_ONE + (ull)__float2uint_rn(ew[e] * 1048576.0f);
            atomicAdd(&g_dc[d], inc);
        }
        return;
    }
    int bid = blockIdx.x - NDEG;

    float (*St)[128][32] = reinterpret_cast<float(*)[128][32]>(pool);
    __half (*Hs)[HS]     = reinterpret_cast<__half(*)[HS]>(pool);

    int tid = threadIdx.x, lane = tid & 31, w = tid >> 5;
    long long row0 = (long long)bid * 128;
    if (tid < HID) bsh[tid] = b1[tid];
    int wr = w * 16;

    float d[8][4];
#pragma unroll
    for (int nt = 0; nt < 8; nt++)
#pragma unroll
        for (int q = 0; q < 4; q++) d[nt][q] = 0.f;

    {
        for (int i = tid; i < 128 * 8; i += 256) {
            int r = i >> 3, c4 = i & 7;
            long long rr = row0 + r; if (rr >= NN) rr = NN - 1;
            cp_async16(&St[0][r][c4 * 4], &((const float4*)x)[rr * 32 + c4]);
        }
        CP_COMMIT();
    }

#pragma unroll
    for (int p = 0; p < 4; p++) {
        if (p < 3) {
            for (int i = tid; i < 128 * 8; i += 256) {
                int r = i >> 3, c4 = i & 7;
                long long rr = row0 + r; if (rr >= NN) rr = NN - 1;
                cp_async16(&St[(p + 1) & 1][r][c4 * 4],
                           &((const float4*)x)[rr * 32 + (p + 1) * 8 + c4]);
            }
            CP_COMMIT();
            CP_WAIT1();
        } else {
            CP_WAIT0();
        }
        __syncthreads();
        for (int i = tid; i < 128 * 16; i += 256) {
            int r = i >> 4, c2 = i & 15;
            float2 v = *(const float2*)&St[p & 1][r][c2 * 2];
            *(__half2*)&Xs[r][c2 * 2] = __floats2half2_rn(v.x, v.y);
        }
        for (int i = tid; i < 32 * HID; i += 256) {
            int k = i >> 6, n = i & 63;
            Wsh[k][n] = __float2half(W1[(p * 32 + k) * HID + n]);
        }
        __syncthreads();
#pragma unroll
        for (int ks = 0; ks < 2; ks++) {
            unsigned a0, a1, a2, a3;
            load_a_s(&Xs[0][0], XS16, wr, ks * 16, lane, a0, a1, a2, a3);
#pragma unroll
            for (int nt = 0; nt < 8; nt++) {
                unsigned b0, b1r;
                load_b_s(&Wsh[0][0], HS, ks * 16, nt * 8, lane, b0, b1r);
                mma16816(d[nt], a0, a1, a2, a3, b0, b1r);
            }
        }
        __syncthreads();
    }

    int rA = wr + (lane >> 2);
#pragma unroll
    for (int nt = 0; nt < 8; nt++) {
        int c0 = nt * 8 + 2 * (lane & 3);
        float bx = bsh[c0], by = bsh[c0 + 1];
        float v0 = d[nt][0] + bx, v1 = d[nt][1] + by;
        float v2 = d[nt][2] + bx, v3 = d[nt][3] + by;
        v0 = (v0 > 0.f) ? v0 : NEG * v0;
        v1 = (v1 > 0.f) ? v1 : NEG * v1;
        v2 = (v2 > 0.f) ? v2 : NEG * v2;
        v3 = (v3 > 0.f) ? v3 : NEG * v3;
        *(__half2*)&Hs[rA][c0]     = __floats2half2_rn(v0, v1);
        *(__half2*)&Hs[rA + 8][c0] = __floats2half2_rn(v2, v3);
    }

#pragma unroll
    for (int nt = 0; nt < 8; nt++)
#pragma unroll
        for (int q = 0; q < 4; q++) d[nt][q] = 0.f;
#pragma unroll
    for (int kp = 0; kp < 2; kp++) {
        __syncthreads();
        for (int i = tid; i < 32 * HID; i += 256) {
            int k = i >> 6, n = i & 63;
            Wsh[k][n] = __float2half(Wc1[(kp * 32 + k) * HID + n]);
        }
        __syncthreads();
#pragma unroll
        for (int ks = 0; ks < 2; ks++) {
            unsigned a0, a1, a2, a3;
            load_a_s(&Hs[0][0], HS, wr, kp * 32 + ks * 16, lane, a0, a1, a2, a3);
#pragma unroll
            for (int nt = 0; nt < 8; nt++) {
                unsigned b0, b1r;
                load_b_s(&Wsh[0][0], HS, ks * 16, nt * 8, lane, b0, b1r);
                mma16816(d[nt], a0, a1, a2, a3, b0, b1r);
            }
        }
    }

    long long r1 = row0 + rA, r2 = row0 + rA + 8;
#pragma unroll
    for (int nt = 0; nt < 8; nt++) {
        int c0 = nt * 8 + 2 * (lane & 3);
        if (r1 < NN) *(__half2*)&g_t16[r1 * HID + c0] = __floats2half2_rn(d[nt][0], d[nt][1]);
        if (r2 < NN) *(__half2*)&g_t16[r2 * HID + c0] = __floats2half2_rn(d[nt][2], d[nt][3]);
    }
}

// ---------------- scan: block sums (+ dis fused, packed read) -----------------
__global__ void scan1_kernel() {
    __shared__ int sh[256];
    int t = threadIdx.x;
    int nb = blockIdx.x * 1024;
    for (int i = nb + t; i < nb + 1024 && i < NN; i += 256) {
        ull v = g_dc[i];
        float deg = (float)(v & (CNT_ONE - 1)) * (1.0f / 1048576.0f);
        g_dis[i] = rsqrtf(deg);
    }
    int base = nb + t * 4;
    int s = 0;
#pragma unroll
    for (int j = 0; j < 4; j++)
        if (base + j < NN) s += (int)(g_dc[base + j] >> 40);
    sh[t] = s; __syncthreads();
#pragma unroll
    for (int o = 128; o > 0; o >>= 1) {
        if (t < o) sh[t] += sh[t + o];
        __syncthreads();
    }
    if (t == 0) g_part[blockIdx.x] = sh[0];
}

__global__ void scan3_kernel() {
    __shared__ int parts[128];
    __shared__ int sh[256];
    int t = threadIdx.x;
    int pv = (t < 128) ? ((t < NPART) ? g_part[t] : 0) : 0;
    if (t < 128) parts[t] = pv;
    __syncthreads();
    for (int o = 1; o < 128; o <<= 1) {
        int x = (t >= o && t < 128) ? parts[t - o] : 0;
        __syncthreads();
        if (t < 128) parts[t] += x;
        __syncthreads();
    }
    int blk_base = (blockIdx.x == 0) ? 0 : parts[blockIdx.x - 1];

    int base = blockIdx.x * 1024 + t * 4;
    int v[4]; int s = 0;
#pragma unroll
    for (int j = 0; j < 4; j++) {
        v[j] = (base + j < NN) ? (int)(g_dc[base + j] >> 40) : 0;
        s += v[j];
    }
    sh[t] = s; __syncthreads();
    for (int o = 1; o < 256; o <<= 1) {
        int x = (t >= o) ? sh[t - o] : 0;
        __syncthreads();
        sh[t] += x;
        __syncthreads();
    }
    int off = (t == 0) ? 0 : sh[t - 1];
    int b = blk_base + off;
    int run = 0;
#pragma unroll
    for (int j = 0; j < 4; j++) {
        if (base + j < NN) g_rowptr[base + j] = b + run;
        run += v[j];
    }
    if (blockIdx.x == 0 && t == 0) g_rowptr[NN] = NE;
}

// ---------------- CSR fill: slot via countdown on packed count ----------------
__global__ void fill_kernel(const void* __restrict__ ei,
                            const float* __restrict__ ew) {
    int e = blockIdx.x * blockDim.x + threadIdx.x;
    if (e < NE) {
        int s = (int)edge_node(ei, e);
        int d = (int)edge_node(ei, (long long)NE + e);
        float nrm = g_dis[s] * ew[e] * g_dis[d];
        ull old = atomicAdd(&g_dc[d], (ull)(0ull - CNT_ONE));
        int idx = (int)(old >> 40) - 1;
        g_csre[g_rowptr[d] + idx] = make_int2(s, __float_as_int(nrm));
    }
}

// ---------------- seg reduce for dst d: lane holds cols 2l, 2l+1 -------------
__device__ __forceinline__ float2 seg_reduce(const unsigned* __restrict__ t16,
                                             int d, int lane) {
    float dd = g_dis[d];
    float sc = dd * dd;
    unsigned su = t16[(size_t)d * 32 + lane];
    float2 sv = __half22float2(*(__half2*)&su);
    float ax = sc * sv.x, ay = sc * sv.y;

    int e = g_rowptr[d], e1 = g_rowptr[d + 1];
    for (; e + 8 <= e1; e += 8) {
        int2 a[8]; unsigned u[8];
#pragma unroll
        for (int q = 0; q < 8; q++) a[q] = g_csre[e + q];
#pragma unroll
        for (int q = 0; q < 8; q++) u[q] = t16[(size_t)a[q].x * 32 + lane];
#pragma unroll
        for (int q = 0; q < 8; q++) {
            float2 v = __half22float2(*(__half2*)&u[q]);
            float n = __int_as_float(a[q].y);
            ax += n * v.x; ay += n * v.y;
        }
    }
    for (; e < e1; e++) {
        int2 a = g_csre[e];
        unsigned u = t16[(size_t)a.x * 32 + lane];
        float2 v = __half22float2(*(__half2*)&u);
        float n = __int_as_float(a.y);
        ax += n * v.x; ay += n * v.y;
    }
    return make_float2(ax, ay);
}

// ---------------- agg_mm: segreduce(g_t16) + b -> leaky -> @Wc2 -> g_t16b ----
__global__ void __launch_bounds__(256)
agg_mm_kernel(const float* __restrict__ bc, const float* __restrict__ W2) {
    __shared__ __half Hs[128][HS];     // 18.4 KB
    __shared__ __half Wsh[64][HS];     // 9.2 KB
    __shared__ float  bs[HID];
    int tid = threadIdx.x, lane = tid & 31, w = tid >> 5;
    long long row0 = (long long)blockIdx.x * 128;

    if (tid < HID) bs[tid] = bc[tid];
    for (int i = tid; i < 64 * HID; i += 256) {
        int k = i >> 6, n = i & 63;
        Wsh[k][n] = __float2half(W2[k * HID + n]);
    }
    __syncthreads();

    const unsigned* t16 = (const unsigned*)g_t16;
    float b0v = bs[2 * lane], b1v = bs[2 * lane + 1];
#pragma unroll 1
    for (int i = 0; i < 16; i++) {
        int lr = w * 16 + i;
        long long d = row0 + lr;
        if (d < NN) {
            float2 a = seg_reduce(t16, (int)d, lane);
            float x0 = a.x + b0v, x1 = a.y + b1v;
            x0 = (x0 > 0.f) ? x0 : NEG * x0;
            x1 = (x1 > 0.f) ? x1 : NEG * x1;
            *(__half2*)&Hs[lr][2 * lane] = __floats2half2_rn(x0, x1);
        } else {
            *(__half2*)&Hs[lr][2 * lane] = __floats2half2_rn(0.f, 0.f);
        }
    }
    __syncthreads();

    int wr = w * 16;
    float d[8][4];
#pragma unroll
    for (int nt = 0; nt < 8; nt++)
#pragma unroll
        for (int q = 0; q < 4; q++) d[nt][q] = 0.f;
#pragma unroll
    for (int ks = 0; ks < 4; ks++) {
        unsigned a0, a1, a2, a3;
        load_a_s(&Hs[0][0], HS, wr, ks * 16, lane, a0, a1, a2, a3);
#pragma unroll
        for (int nt = 0; nt < 8; nt++) {
            unsigned b0, b1r;
            load_b_s(&Wsh[0][0], HS, ks * 16, nt * 8, lane, b0, b1r);
            mma16816(d[nt], a0, a1, a2, a3, b0, b1r);
        }
    }

    int rA = wr + (lane >> 2);
    long long r1 = row0 + rA, r2 = row0 + rA + 8;
#pragma unroll
    for (int nt = 0; nt < 8; nt++) {
        int c0 = nt * 8 + 2 * (lane & 3);
        if (r1 < NN) *(__half2*)&g_t16b[r1 * HID + c0] = __floats2half2_rn(d[nt][0], d[nt][1]);
        if (r2 < NN) *(__half2*)&g_t16b[r2 * HID + c0] = __floats2half2_rn(d[nt][2], d[nt][3]);
    }
}

// ---- agg_out: segreduce(g_t16b) + b -> leaky -> @W_out + bo -> log_softmax --
__global__ void __launch_bounds__(256)
agg_out_kernel(const float* __restrict__ bc, const float* __restrict__ Wo,
               const float* __restrict__ bo, float* __restrict__ out) {
    __shared__ __half Hs[128][HS];     // 18.4 KB
    __shared__ __half Wsh[64][HS];     // 9.2 KB
    __shared__ float  bs[HID];
    __shared__ float  bos[NCLS];
    int tid = threadIdx.x, lane = tid & 31, w = tid >> 5;
    long long row0 = (long long)blockIdx.x * 128;

    if (tid < HID) bs[tid] = bc[tid];
    if (tid < NCLS) bos[tid] = bo[tid];
    for (int i = tid; i < HID * NCLS; i += 256) {
        int k = i / NCLS, n = i % NCLS;
        Wsh[k][n] = __float2half(Wo[k * NCLS + n]);
    }
    __syncthreads();

    const unsigned* t16 = (const unsigned*)g_t16b;
    float b0v = bs[2 * lane], b1v = bs[2 * lane + 1];
#pragma unroll 1
    for (int i = 0; i < 16; i++) {
        int lr = w * 16 + i;
        long long d = row0 + lr;
        if (d < NN) {
            float2 a = seg_reduce(t16, (int)d, lane);
            float x0 = a.x + b0v, x1 = a.y + b1v;
            x0 = (x0 > 0.f) ? x0 : NEG * x0;
            x1 = (x1 > 0.f) ? x1 : NEG * x1;
            *(__half2*)&Hs[lr][2 * lane] = __floats2half2_rn(x0, x1);
        } else {
            *(__half2*)&Hs[lr][2 * lane] = __floats2half2_rn(0.f, 0.f);
        }
    }
    __syncthreads();

    int wr = w * 16;
    float d[5][4];
#pragma unroll
    for (int nt = 0; nt < 5; nt++)
#pragma unroll
        for (int q = 0; q < 4; q++) d[nt][q] = 0.f;
#pragma unroll
    for (int ks = 0; ks < 4; ks++) {
        unsigned a0, a1, a2, a3;
        load_a_s(&Hs[0][0], HS, wr, ks * 16, lane, a0, a1, a2, a3);
#pragma unroll
        for (int nt = 0; nt < 5; nt++) {
            unsigned b0, b1r;
            load_b_s(&Wsh[0][0], HS, ks * 16, nt * 8, lane, b0, b1r);
            mma16816(d[nt], a0, a1, a2, a3, b0, b1r);
        }
    }

#pragma unroll
    for (int nt = 0; nt < 5; nt++) {
        int c0 = nt * 8 + 2 * (lane & 3);
        d[nt][0] += bos[c0]; d[nt][1] += bos[c0 + 1];
        d[nt][2] += bos[c0]; d[nt][3] += bos[c0 + 1];
    }

    float m1 = -1e30f, m2 = -1e30f;
#pragma unroll
    for (int nt = 0; nt < 5; nt++) {
        m1 = fmaxf(m1, fmaxf(d[nt][0], d[nt][1]));
        m2 = fmaxf(m2, fmaxf(d[nt][2], d[nt][3]));
    }
#pragma unroll
    for (int o = 1; o <= 2; o <<= 1) {
        m1 = fmaxf(m1, __shfl_xor_sync(0xffffffffu, m1, o));
        m2 = fmaxf(m2, __shfl_xor_sync(0xffffffffu, m2, o));
    }
    float s1 = 0.f, s2 = 0.f;
#pragma unroll
    for (int nt = 0; nt < 5; nt++) {
        s1 += expf(d[nt][0] - m1) + expf(d[nt][1] - m1);
        s2 += expf(d[nt][2] - m2) + expf(d[nt][3] - m2);
    }
#pragma unroll
    for (int o = 1; o <= 2; o <<= 1) {
        s1 += __shfl_xor_sync(0xffffffffu, s1, o);
        s2 += __shfl_xor_sync(0xffffffffu, s2, o);
    }
    float lse1 = m1 + logf(s1), lse2 = m2 + logf(s2);

    int rA = wr + (lane >> 2);
    long long r1 = row0 + rA, r2 = row0 + rA + 8;
#pragma unroll
    for (int nt = 0; nt < 5; nt++) {
        int c0 = nt * 8 + 2 * (lane & 3);
        if (r1 < NN) {
            out[r1 * NCLS + c0]     = d[nt][0] - lse1;
            out[r1 * NCLS + c0 + 1] = d[nt][1] - lse1;
        }
        if (r2 < NN) {
            out[r2 * NCLS + c0]     = d[nt][2] - lse2;
            out[r2 * NCLS + c0 + 1] = d[nt][3] - lse2;
        }
    }
}

// ---------------- launch (kernel launches ONLY) ------------------------------
extern "C" void kernel_launch(void* const* d_in, const int* in_sizes, int n_in,
                              void* d_out, int out_size) {
    const float* x       = (const float*)d_in[0];
    const void*  ei      = d_in[1];
    const float* ew      = (const float*)d_in[2];
    const float* W_first = (const float*)d_in[3];
    const float* b_first = (const float*)d_in[4];
    const float* Wc1     = (const float*)d_in[5];
    const float* bc1     = (const float*)d_in[6];
    const float* Wc2     = (const float*)d_in[7];
    const float* bc2     = (const float*)d_in[8];
    const float* W_out   = (const float*)d_in[9];
    const float* b_out   = (const float*)d_in[10];
    float* out = (float*)d_out;

    const int T = 256;
    init_kernel<<<(NN + T - 1) / T, T>>>(ei);                          // 1
    mega_kernel<<<NDEG + NB128, T>>>(x, W_first, b_first, Wc1, ei, ew);// 2 (deg || GEMM)
    scan1_kernel<<<NPART, 256>>>();                                    // 3
    scan3_kernel<<<NPART, 256>>>();                                    // 4
    fill_kernel<<<(NE + T - 1) / T, T>>>(ei, ew);                      // 5

    agg_mm_kernel<<<NB128, T>>>(bc1, Wc2);                             // 6 : g_t16 -> g_t16b
    agg_out_kernel<<<NB128, T>>>(bc2, W_out, b_out, out);              // 7 : g_t16b -> out
}